// round 1
// baseline (speedup 1.0000x reference)
#include <cuda_runtime.h>
#include <math.h>

// ---------------- problem constants ----------------
#define NB   128      // batch
#define RNUM 300      // rooms
#define EMB  32       // embedding width
#define CH0  33       // 1 + EMB input channels
#define MAPD 72       // map side

// ---------------- scratch (static device memory; no allocation) -------------
__device__ float g_grid[NB * CH0 * MAPD * MAPD];          // encode output  [128,33,72,72]
__device__ float g_c1 [NB * 64  * 72 * 72];               // conv1 out
__device__ float g_p1 [NB * 64  * 35 * 35];               // pool1 out
__device__ float g_c2 [NB * 128 * 35 * 35];               // conv2 out
__device__ float g_p2 [NB * 128 * 17 * 17];               // pool2 out
__device__ float g_c3 [NB * 256 * 17 * 17];               // conv3 out
__device__ float g_p3 [NB * 256 * 8 * 8];                 // pool3 out
__device__ float g_gap[NB * 256];
__device__ float g_f1 [NB * 512];
__device__ float g_f2 [NB * 256];

// ---------------- zero fill ----------------
__global__ void zero_kernel(float* __restrict__ p, int n) {
    int i = blockIdx.x * blockDim.x + threadIdx.x;
    if (i < n) p[i] = 0.f;
}

// ---------------- encode: scatter rooms into grid ----------------
// grid layout: [n][c][y][x]  (matches reference transpose (0,3,2,1))
__global__ void scatter_kernel(const int* __restrict__ X,
                               const int* __restrict__ rm,
                               const float* __restrict__ emb,
                               float* __restrict__ grid) {
    int idx = blockIdx.x * blockDim.x + threadIdx.x;     // n * R * 64
    if (idx >= NB * RNUM * 64) return;
    int cell = idx & 63;
    int r    = (idx >> 6) % RNUM;
    int n    = idx / (RNUM * 64);
    int occ  = rm[r * 64 + cell];
    if (!occ) return;
    int cx = cell >> 3, cy = cell & 7;
    int px = X[(n * RNUM + r) * 2 + 0];
    int py = X[(n * RNUM + r) * 2 + 1];
    int ix = px + cx, iy = py + cy;                       // always in-bounds by construction
    float* base = grid + ((size_t)n * CH0) * MAPD * MAPD + (size_t)iy * MAPD + ix;
    atomicAdd(base, 1.0f);                                // occupancy channel
    const float* er = emb + r * EMB;
#pragma unroll
    for (int e = 0; e < EMB; ++e)
        atomicAdd(base + (size_t)(1 + e) * MAPD * MAPD, er[e]);
}

// ---------------- tiled direct conv + bias + relu ----------------
// block: 256 threads, one (n, spatial TILExTILE tile, CO_BLK-chunk of output ch)
// smem: input slice [CB][IT][IT] + weight slice [CO_BLK][CB][K*K]
template<int CIN, int COUT, int CO_BLK, int K, int HIN, int TILE, int CB, int CO_T, int PX_T>
__global__ void __launch_bounds__(256)
conv_relu_kernel(const float* __restrict__ in, const float* __restrict__ wgt,
                 const float* __restrict__ bias, float* __restrict__ out) {
    constexpr int IT   = TILE + K - 1;
    constexpr int PAD  = K / 2;
    constexpr int NPX  = TILE * TILE;
    constexpr int GRPS = CO_BLK / CO_T;
    constexpr int PXG  = 256 / GRPS;
    constexpr int KK   = K * K;
    constexpr int TD   = (HIN + TILE - 1) / TILE;

    extern __shared__ float smem[];
    float* s_in = smem;                       // CB*IT*IT
    float* s_w  = smem + CB * IT * IT;        // CO_BLK*CB*KK

    const int tile = blockIdx.x;
    const int ty0  = (tile / TD) * TILE;
    const int tx0  = (tile % TD) * TILE;
    const int cob0 = blockIdx.y * CO_BLK;
    const int n    = blockIdx.z;
    const int t    = threadIdx.x;
    const int g    = t / PXG;                 // co group
    const int p    = t % PXG;                 // pixel group

    int  pys[PX_T], pxs[PX_T];
    bool ok[PX_T];
#pragma unroll
    for (int i = 0; i < PX_T; ++i) {
        int pxidx = p + i * PXG;
        ok[i] = (pxidx < NPX);
        int v  = ok[i] ? pxidx : 0;
        pys[i] = v / TILE;
        pxs[i] = v % TILE;
    }

    float acc[CO_T][PX_T];
#pragma unroll
    for (int j = 0; j < CO_T; ++j)
#pragma unroll
        for (int i = 0; i < PX_T; ++i) acc[j][i] = 0.f;

    for (int ci0 = 0; ci0 < CIN; ci0 += CB) {
        // stage input slice (zero-padded at borders / tile overhang)
        for (int e = t; e < CB * IT * IT; e += 256) {
            int cc = e / (IT * IT);
            int rr = e % (IT * IT);
            int iy = rr / IT, ix = rr % IT;
            int y = ty0 - PAD + iy, x = tx0 - PAD + ix;
            float v = 0.f;
            if (y >= 0 && y < HIN && x >= 0 && x < HIN)
                v = in[(((size_t)n * CIN + ci0 + cc) * HIN + y) * HIN + x];
            s_in[e] = v;
        }
        // stage weight slice
        for (int e = t; e < CO_BLK * CB * KK; e += 256) {
            int col = e / (CB * KK);
            int rr  = e % (CB * KK);
            s_w[e]  = wgt[((size_t)(cob0 + col) * CIN + ci0 + rr / KK) * KK + rr % KK];
        }
        __syncthreads();

#pragma unroll 1
        for (int cc = 0; cc < CB; ++cc) {
            const float* sin_c = s_in + cc * IT * IT;
            const float* sw_c  = s_w + cc * KK;
#pragma unroll
            for (int kk = 0; kk < KK; ++kk) {
                const int ky = kk / K, kx = kk % K;
                float wr[CO_T];
#pragma unroll
                for (int j = 0; j < CO_T; ++j)
                    wr[j] = sw_c[(g * CO_T + j) * CB * KK + kk];
#pragma unroll
                for (int i = 0; i < PX_T; ++i) {
                    float v = sin_c[(pys[i] + ky) * IT + (pxs[i] + kx)];
#pragma unroll
                    for (int j = 0; j < CO_T; ++j)
                        acc[j][i] = fmaf(wr[j], v, acc[j][i]);
                }
            }
        }
        __syncthreads();
    }

#pragma unroll
    for (int j = 0; j < CO_T; ++j) {
        int co = cob0 + g * CO_T + j;
        float bb = bias[co];
#pragma unroll
        for (int i = 0; i < PX_T; ++i) {
            if (!ok[i]) continue;
            int y = ty0 + pys[i], x = tx0 + pxs[i];
            if (y < HIN && x < HIN) {
                float v = acc[j][i] + bb;
                out[(((size_t)n * COUT + co) * HIN + y) * HIN + x] = v > 0.f ? v : 0.f;
            }
        }
    }
}

// ---------------- 3x3 stride-2 VALID max pool ----------------
template<int C, int HI, int HO>
__global__ void maxpool_kernel(const float* __restrict__ in, float* __restrict__ out) {
    int idx = blockIdx.x * blockDim.x + threadIdx.x;
    if (idx >= NB * C * HO * HO) return;
    int ox = idx % HO;
    int oy = (idx / HO) % HO;
    int nc = idx / (HO * HO);
    const float* p = in + ((size_t)nc * HI + 2 * oy) * HI + 2 * ox;
    float m = p[0];
#pragma unroll
    for (int dy = 0; dy < 3; ++dy)
#pragma unroll
        for (int dx = 0; dx < 3; ++dx)
            m = fmaxf(m, p[dy * HI + dx]);
    out[idx] = m;
}

// ---------------- global average pool over 8x8 ----------------
__global__ void gap_kernel(const float* __restrict__ in, float* __restrict__ out) {
    int idx = blockIdx.x * blockDim.x + threadIdx.x;   // n*256 + c
    if (idx >= NB * 256) return;
    const float* p = in + (size_t)idx * 64;
    float s = 0.f;
#pragma unroll
    for (int i = 0; i < 64; ++i) s += p[i];
    out[idx] = s * (1.0f / 64.0f);
}

// ---------------- fully connected (y = x @ W^T + b, optional relu) ----------
__global__ void fc_kernel(const float* __restrict__ in, const float* __restrict__ w,
                          const float* __restrict__ b, float* __restrict__ out,
                          int K_, int O_, int relu) {
    int idx = blockIdx.x * blockDim.x + threadIdx.x;
    if (idx >= NB * O_) return;
    int n = idx / O_, o = idx % O_;
    const float4* ip = (const float4*)(in + (size_t)n * K_);
    const float4* wp = (const float4*)(w + (size_t)o * K_);
    float s = b[o];
    int k4 = K_ >> 2;
#pragma unroll 4
    for (int k = 0; k < k4; ++k) {
        float4 a = ip[k], ww = wp[k];
        s = fmaf(a.x, ww.x, s); s = fmaf(a.y, ww.y, s);
        s = fmaf(a.z, ww.z, s); s = fmaf(a.w, ww.w, s);
    }
    if (relu) s = fmaxf(s, 0.f);
    out[idx] = s;
}

// ---------------- launch ----------------
extern "C" void kernel_launch(void* const* d_in, const int* in_sizes, int n_in,
                              void* d_out, int out_size) {
    const int*   X    = (const int*)  d_in[0];
    const int*   rmap = (const int*)  d_in[1];
    const float* emb  = (const float*)d_in[2];
    const float* cw0  = (const float*)d_in[3];
    const float* cb0  = (const float*)d_in[4];
    const float* cw1  = (const float*)d_in[5];
    const float* cb1  = (const float*)d_in[6];
    const float* cw2  = (const float*)d_in[7];
    const float* cb2  = (const float*)d_in[8];
    const float* fw0  = (const float*)d_in[9];
    const float* fb0  = (const float*)d_in[10];
    const float* fw1  = (const float*)d_in[11];
    const float* fb1  = (const float*)d_in[12];
    const float* fw2  = (const float*)d_in[13];
    const float* fb2  = (const float*)d_in[14];
    float* out = (float*)d_out;

    float *grid, *c1, *p1, *c2, *p2, *c3, *p3, *gapb, *f1, *f2;
    cudaGetSymbolAddress((void**)&grid, g_grid);
    cudaGetSymbolAddress((void**)&c1,  g_c1);
    cudaGetSymbolAddress((void**)&p1,  g_p1);
    cudaGetSymbolAddress((void**)&c2,  g_c2);
    cudaGetSymbolAddress((void**)&p2,  g_p2);
    cudaGetSymbolAddress((void**)&c3,  g_c3);
    cudaGetSymbolAddress((void**)&p3,  g_p3);
    cudaGetSymbolAddress((void**)&gapb, g_gap);
    cudaGetSymbolAddress((void**)&f1,  g_f1);
    cudaGetSymbolAddress((void**)&f2,  g_f2);

    // conv smem sizes (dynamic, > 48KB)
    const int SM1 = (11 * 16 * 16 + 64  * 11 * 25) * 4;   // 81664
    const int SM2 = (16 * 10 * 10 + 128 * 16 * 9 ) * 4;   // 80128
    const int SM3 = (32 * 11 * 11 + 64  * 32 * 9 ) * 4;   // 89216
    cudaFuncSetAttribute((const void*)conv_relu_kernel<33, 64, 64, 5, 72, 12, 11, 4, 9>,
                         cudaFuncAttributeMaxDynamicSharedMemorySize, SM1);
    cudaFuncSetAttribute((const void*)conv_relu_kernel<64, 128, 128, 3, 35, 8, 16, 8, 4>,
                         cudaFuncAttributeMaxDynamicSharedMemorySize, SM2);
    cudaFuncSetAttribute((const void*)conv_relu_kernel<128, 256, 64, 3, 17, 9, 32, 4, 6>,
                         cudaFuncAttributeMaxDynamicSharedMemorySize, SM3);

    // 1) zero + scatter encode
    {
        int ne = NB * CH0 * MAPD * MAPD;
        zero_kernel<<<(ne + 255) / 256, 256>>>(grid, ne);
        int nt = NB * RNUM * 64;
        scatter_kernel<<<(nt + 255) / 256, 256>>>(X, rmap, emb, grid);
    }
    // 2) conv1 (33->64, k5, 72x72) + pool -> 35x35
    conv_relu_kernel<33, 64, 64, 5, 72, 12, 11, 4, 9>
        <<<dim3(36, 1, NB), 256, SM1>>>(grid, cw0, cb0, c1);
    {
        int nt = NB * 64 * 35 * 35;
        maxpool_kernel<64, 72, 35><<<(nt + 255) / 256, 256>>>(c1, p1);
    }
    // 3) conv2 (64->128, k3, 35x35) + pool -> 17x17
    conv_relu_kernel<64, 128, 128, 3, 35, 8, 16, 8, 4>
        <<<dim3(25, 1, NB), 256, SM2>>>(p1, cw1, cb1, c2);
    {
        int nt = NB * 128 * 17 * 17;
        maxpool_kernel<128, 35, 17><<<(nt + 255) / 256, 256>>>(c2, p2);
    }
    // 4) conv3 (128->256, k3, 17x17) + pool -> 8x8
    conv_relu_kernel<128, 256, 64, 3, 17, 9, 32, 4, 6>
        <<<dim3(4, 4, NB), 256, SM3>>>(p2, cw2, cb2, c3);
    {
        int nt = NB * 256 * 8 * 8;
        maxpool_kernel<256, 17, 8><<<(nt + 255) / 256, 256>>>(c3, p3);
    }
    // 5) GAP + FC stack
    gap_kernel<<<(NB * 256 + 255) / 256, 256>>>(p3, gapb);
    fc_kernel<<<(NB * 512 + 255) / 256, 256>>>(gapb, fw0, fb0, f1, 256, 512, 1);
    fc_kernel<<<(NB * 256 + 255) / 256, 256>>>(f1,   fw1, fb1, f2, 512, 256, 1);
    fc_kernel<<<(NB * 512 + 255) / 256, 256>>>(f2,   fw2, fb2, out, 256, 512, 0);
}

// round 2
// speedup vs baseline: 2.6736x; 2.6736x over previous
#include <cuda_runtime.h>
#include <math.h>
#include <stdint.h>

// ---------------- problem constants ----------------
#define NB   128
#define RNUM 300
#define EMB  32

// padded NHWC activation buffers
__device__ float g_grid[NB * 76 * 76 * 40];     // conv1 input  (pad2, ch 33->40)
__device__ float g_c1 [NB * 72 * 72 * 64];      // conv1 out (valid, NHWC)
__device__ float g_p1 [NB * 37 * 37 * 64];      // pool1 out (pad1)
__device__ float g_c2 [NB * 35 * 35 * 128];     // conv2 out
__device__ float g_p2 [NB * 19 * 19 * 128];     // pool2 out (pad1)
__device__ float g_c3 [NB * 17 * 17 * 256];     // conv3 out
__device__ float g_p3 [NB * 8 * 8 * 256];       // pool3 out (no pad)
__device__ float g_gap[NB * 256];
__device__ float g_f1 [NB * 512];
__device__ float g_f2 [NB * 256];
// transformed weights: [kk][ci_padded][co], tf32
__device__ float g_wt1[25 * 40 * 64];
__device__ float g_wt2[9 * 64 * 128];
__device__ float g_wt3[9 * 128 * 256];

// ---------------- helpers ----------------
__device__ __forceinline__ float to_tf32(float x) {
    float r; asm("cvt.rna.tf32.f32 %0, %1;" : "=f"(r) : "f"(x)); return r;
}
__device__ __forceinline__ void mma_tf32(float* d, const uint32_t* a, const uint32_t* b) {
    asm volatile(
        "mma.sync.aligned.m16n8k8.row.col.f32.tf32.tf32.f32 "
        "{%0,%1,%2,%3}, {%4,%5,%6,%7}, {%8,%9}, {%0,%1,%2,%3};"
        : "+f"(d[0]), "+f"(d[1]), "+f"(d[2]), "+f"(d[3])
        : "r"(a[0]), "r"(a[1]), "r"(a[2]), "r"(a[3]), "r"(b[0]), "r"(b[1]));
}

// ---------------- zero fill (vectorized) ----------------
__global__ void zero_kernel(float4* __restrict__ p, int n4) {
    int i = blockIdx.x * blockDim.x + threadIdx.x;
    if (i < n4) p[i] = make_float4(0.f, 0.f, 0.f, 0.f);
}

// ---------------- scatter rooms into padded NHWC grid ----------------
__global__ void scatter_kernel(const int* __restrict__ X,
                               const int* __restrict__ rm,
                               const float* __restrict__ emb,
                               float* __restrict__ grid) {
    int idx = blockIdx.x * blockDim.x + threadIdx.x;     // n * R * 64
    if (idx >= NB * RNUM * 64) return;
    int cell = idx & 63;
    int r    = (idx >> 6) % RNUM;
    int n    = idx / (RNUM * 64);
    if (!rm[r * 64 + cell]) return;
    int cx = cell >> 3, cy = cell & 7;
    int px = X[(n * RNUM + r) * 2 + 0];
    int py = X[(n * RNUM + r) * 2 + 1];
    int Y = py + cy + 2, Xc = px + cx + 2;               // padded coords, layout [n][Y][X][40]
    float* base = grid + (((size_t)n * 76 + Y) * 76 + Xc) * 40;
    atomicAdd(base, 1.0f);
    const float* er = emb + r * EMB;
#pragma unroll
    for (int e = 0; e < EMB; ++e)
        atomicAdd(base + 1 + e, er[e]);
}

// ---------------- weight transform: OIHW -> [kk][ci_pad][co] tf32 -----------
template<int CI, int CIP, int CO, int KK>
__global__ void wtrans_kernel(const float* __restrict__ w, float* __restrict__ wt) {
    int i = blockIdx.x * blockDim.x + threadIdx.x;
    if (i >= KK * CIP * CO) return;
    int co = i % CO;
    int ci = (i / CO) % CIP;
    int kk = i / (CO * CIP);
    float v = (ci < CI) ? w[((size_t)co * CI + ci) * KK + kk] : 0.f;
    wt[i] = to_tf32(v);
}

// ---------------- tf32 tensor-core conv (shifted-window implicit GEMM) ------
// input: padded NHWC [NB][Hp][Wp][CINP]; out: valid NHWC [NB][H][W][CO]
// block: 256 threads = 8 warps, all tiled along M (pixels). N tile = 64 co.
template<int CINP, int CO, int K, int H, int W, int PAD, int MPIX, int MT>
__global__ void __launch_bounds__(256, 1)
mma_conv_kernel(const float* __restrict__ in, const float* __restrict__ wt,
                const float* __restrict__ bias, float* __restrict__ out) {
    constexpr int Wp = W + 2 * PAD;
    constexpr int Hp = H + 2 * PAD;
    constexpr int HALO = PAD * Wp + PAD;
    constexpr int AWIN = MPIX + 2 * HALO;
    constexpr int NPIX = Hp * Wp;
    constexpr int KK = K * K;
    constexpr int NT = 8;                         // 64 output channels per block
    constexpr int AST = CINP + 4;                 // bank-conflict-free stride
    constexpr int NC8 = CINP / 8;

    extern __shared__ float smem[];
    float* sA = smem;                             // [AWIN][AST]
    float* sB = smem + AWIN * AST;                // [NC8*NT] 8x8 tiles (64 floats each)

    const int n    = blockIdx.z;
    const int co0  = blockIdx.y * 64;
    const int p0   = HALO + blockIdx.x * MPIX;
    const int s0   = p0 - HALO;
    const int t    = threadIdx.x;
    const int warp = t >> 5, lane = t & 31;
    const int ar   = lane >> 2;                   // 0..7
    const int ac   = lane & 3;                    // 0..3
    const int wrow = warp * (16 * MT);

    const float* inb = in + (size_t)n * NPIX * CINP;

    // stage A window once (tf32-rounded, bounds-checked)
    for (int e = t; e < AWIN * CINP; e += 256) {
        int pw = e / CINP, ch = e - pw * CINP;
        int pix = s0 + pw;
        float v = (pix < NPIX) ? inb[(size_t)pix * CINP + ch] : 0.f;
        sA[pw * AST + ch] = to_tf32(v);
    }

    float d[MT][NT][4];
#pragma unroll
    for (int mt = 0; mt < MT; ++mt)
#pragma unroll
        for (int nt = 0; nt < NT; ++nt)
#pragma unroll
            for (int q = 0; q < 4; ++q) d[mt][nt][q] = 0.f;

    for (int kk = 0; kk < KK; ++kk) {
        __syncthreads();
        // stage B[kk]: [CINP][64] -> 8x8 tiles, tile (c8,nt), elem k*8+nl
        const float* wsrc = wt + (size_t)kk * CINP * CO + co0;
        for (int e = t; e < CINP * 64; e += 256) {
            int col = e & 63, ci = e >> 6;
            float v = wsrc[(size_t)ci * CO + col];
            sB[(((ci >> 3) * NT) + (col >> 3)) * 64 + (ci & 7) * 8 + (col & 7)] = v;
        }
        __syncthreads();
        const int shift = (kk / K - PAD) * Wp + (kk % K - PAD);
        const int abase = HALO + shift;           // >= 0
#pragma unroll
        for (int c8 = 0; c8 < NC8; ++c8) {
            uint32_t bf[NT][2];
#pragma unroll
            for (int nt = 0; nt < NT; ++nt) {
                const float* bt = sB + (c8 * NT + nt) * 64;
                bf[nt][0] = __float_as_uint(bt[ac * 8 + ar]);
                bf[nt][1] = __float_as_uint(bt[(ac + 4) * 8 + ar]);
            }
#pragma unroll
            for (int mt = 0; mt < MT; ++mt) {
                const float* ap = sA + (abase + wrow + mt * 16 + ar) * AST + c8 * 8 + ac;
                uint32_t af[4];
                af[0] = __float_as_uint(ap[0]);
                af[1] = __float_as_uint(ap[8 * AST]);
                af[2] = __float_as_uint(ap[4]);
                af[3] = __float_as_uint(ap[8 * AST + 4]);
#pragma unroll
                for (int nt = 0; nt < NT; ++nt)
                    mma_tf32(d[mt][nt], af, bf[nt]);
            }
        }
    }

    // epilogue: bias + relu, store valid pixels (NHWC)
    float2 bv[NT];
#pragma unroll
    for (int nt = 0; nt < NT; ++nt)
        bv[nt] = *(const float2*)(bias + co0 + nt * 8 + 2 * ac);

#pragma unroll
    for (int mt = 0; mt < MT; ++mt) {
#pragma unroll
        for (int half = 0; half < 2; ++half) {
            int p = p0 + wrow + mt * 16 + half * 8 + ar;
            int y = p / Wp - PAD, x = p % Wp - PAD;
            if (x >= 0 && x < W && y < H) {
                float* ob = out + (((size_t)n * H + y) * W + x) * CO + co0;
#pragma unroll
                for (int nt = 0; nt < NT; ++nt) {
                    float2 v;
                    v.x = fmaxf(d[mt][nt][half * 2 + 0] + bv[nt].x, 0.f);
                    v.y = fmaxf(d[mt][nt][half * 2 + 1] + bv[nt].y, 0.f);
                    *(float2*)(ob + nt * 8 + 2 * ac) = v;
                }
            }
        }
    }
}

// ---------------- 3x3 s2 max pool, NHWC in -> padded NHWC out ---------------
template<int C, int HI, int HO, int P>
__global__ void pool_kernel(const float* __restrict__ in, float* __restrict__ out) {
    constexpr int HOP = HO + 2 * P;
    int idx = blockIdx.x * blockDim.x + threadIdx.x;    // n*HO*HO*C
    if (idx >= NB * HO * HO * C) return;
    int c  = idx % C;
    int ox = (idx / C) % HO;
    int oy = (idx / (C * HO)) % HO;
    int n  = idx / (C * HO * HO);
    const float* p = in + (((size_t)n * HI + 2 * oy) * HI + 2 * ox) * C + c;
    float m = p[0];
#pragma unroll
    for (int dy = 0; dy < 3; ++dy)
#pragma unroll
        for (int dx = 0; dx < 3; ++dx)
            m = fmaxf(m, p[((size_t)dy * HI + dx) * C]);
    out[(((size_t)n * HOP + oy + P) * HOP + ox + P) * C + c] = m;
}

// ---------------- global average pool over 8x8 (NHWC) ----------------
__global__ void gap_kernel(const float* __restrict__ in, float* __restrict__ out) {
    int idx = blockIdx.x * blockDim.x + threadIdx.x;   // n*256 + c
    if (idx >= NB * 256) return;
    int n = idx >> 8, c = idx & 255;
    const float* p = in + (size_t)n * 64 * 256 + c;
    float s = 0.f;
#pragma unroll
    for (int i = 0; i < 64; ++i) s += p[i * 256];
    out[idx] = s * (1.0f / 64.0f);
}

// ---------------- fully connected ----------------
__global__ void fc_kernel(const float* __restrict__ in, const float* __restrict__ w,
                          const float* __restrict__ b, float* __restrict__ out,
                          int K_, int O_, int relu) {
    int idx = blockIdx.x * blockDim.x + threadIdx.x;
    if (idx >= NB * O_) return;
    int n = idx / O_, o = idx % O_;
    const float4* ip = (const float4*)(in + (size_t)n * K_);
    const float4* wp = (const float4*)(w + (size_t)o * K_);
    float s = b[o];
    int k4 = K_ >> 2;
#pragma unroll 4
    for (int k = 0; k < k4; ++k) {
        float4 a = ip[k], ww = wp[k];
        s = fmaf(a.x, ww.x, s); s = fmaf(a.y, ww.y, s);
        s = fmaf(a.z, ww.z, s); s = fmaf(a.w, ww.w, s);
    }
    if (relu) s = fmaxf(s, 0.f);
    out[idx] = s;
}

// ---------------- launch ----------------
extern "C" void kernel_launch(void* const* d_in, const int* in_sizes, int n_in,
                              void* d_out, int out_size) {
    const int*   X    = (const int*)  d_in[0];
    const int*   rmap = (const int*)  d_in[1];
    const float* emb  = (const float*)d_in[2];
    const float* cw0  = (const float*)d_in[3];
    const float* cb0  = (const float*)d_in[4];
    const float* cw1  = (const float*)d_in[5];
    const float* cb1  = (const float*)d_in[6];
    const float* cw2  = (const float*)d_in[7];
    const float* cb2  = (const float*)d_in[8];
    const float* fw0  = (const float*)d_in[9];
    const float* fb0  = (const float*)d_in[10];
    const float* fw1  = (const float*)d_in[11];
    const float* fb1  = (const float*)d_in[12];
    const float* fw2  = (const float*)d_in[13];
    const float* fb2  = (const float*)d_in[14];
    float* out = (float*)d_out;

    float *grid, *c1, *p1, *c2, *p2, *c3, *p3, *gapb, *f1, *f2, *wt1, *wt2, *wt3;
    cudaGetSymbolAddress((void**)&grid, g_grid);
    cudaGetSymbolAddress((void**)&c1,  g_c1);
    cudaGetSymbolAddress((void**)&p1,  g_p1);
    cudaGetSymbolAddress((void**)&c2,  g_c2);
    cudaGetSymbolAddress((void**)&p2,  g_p2);
    cudaGetSymbolAddress((void**)&c3,  g_c3);
    cudaGetSymbolAddress((void**)&p3,  g_p3);
    cudaGetSymbolAddress((void**)&gapb, g_gap);
    cudaGetSymbolAddress((void**)&f1,  g_f1);
    cudaGetSymbolAddress((void**)&f2,  g_f2);
    cudaGetSymbolAddress((void**)&wt1, g_wt1);
    cudaGetSymbolAddress((void**)&wt2, g_wt2);
    cudaGetSymbolAddress((void**)&wt3, g_wt3);

    // conv configs:
    // conv1: CINP=40 CO=64  K=5 H=W=72 PAD=2 MPIX=512 MT=4 : smem 154,560
    // conv2: CINP=64 CO=128 K=3 H=W=35 PAD=1 MPIX=256 MT=2 : smem 106,688
    // conv3: CINP=128 CO=256 K=3 H=W=17 PAD=1 MPIX=256 MT=2: smem 189,056
    const int SM1 = (820 * 44 + 40 * 64) * 4;
    const int SM2 = (332 * 68 + 64 * 64) * 4;
    const int SM3 = (296 * 132 + 128 * 64) * 4;
    cudaFuncSetAttribute((const void*)mma_conv_kernel<40, 64, 5, 72, 72, 2, 512, 4>,
                         cudaFuncAttributeMaxDynamicSharedMemorySize, SM1);
    cudaFuncSetAttribute((const void*)mma_conv_kernel<64, 128, 3, 35, 35, 1, 256, 2>,
                         cudaFuncAttributeMaxDynamicSharedMemorySize, SM2);
    cudaFuncSetAttribute((const void*)mma_conv_kernel<128, 256, 3, 17, 17, 1, 256, 2>,
                         cudaFuncAttributeMaxDynamicSharedMemorySize, SM3);

    // zero padded buffers (grid fully; p1/p2 for pad frames)
    {
        int n4;
        n4 = NB * 76 * 76 * 40 / 4; zero_kernel<<<(n4 + 255) / 256, 256>>>((float4*)grid, n4);
        n4 = NB * 37 * 37 * 64 / 4; zero_kernel<<<(n4 + 255) / 256, 256>>>((float4*)p1, n4);
        n4 = NB * 19 * 19 * 128 / 4; zero_kernel<<<(n4 + 255) / 256, 256>>>((float4*)p2, n4);
    }
    // weight transforms
    {
        int n1 = 25 * 40 * 64;  wtrans_kernel<33, 40, 64, 25><<<(n1 + 255) / 256, 256>>>(cw0, wt1);
        int n2 = 9 * 64 * 128;  wtrans_kernel<64, 64, 128, 9><<<(n2 + 255) / 256, 256>>>(cw1, wt2);
        int n3 = 9 * 128 * 256; wtrans_kernel<128, 128, 256, 9><<<(n3 + 255) / 256, 256>>>(cw2, wt3);
    }
    // scatter encode
    {
        int nt = NB * RNUM * 64;
        scatter_kernel<<<(nt + 255) / 256, 256>>>(X, rmap, emb, grid);
    }
    // conv1 + pool1
    mma_conv_kernel<40, 64, 5, 72, 72, 2, 512, 4>
        <<<dim3(11, 1, NB), 256, SM1>>>(grid, wt1, cb0, c1);
    {
        int nt = NB * 35 * 35 * 64;
        pool_kernel<64, 72, 35, 1><<<(nt + 255) / 256, 256>>>(c1, p1);
    }
    // conv2 + pool2
    mma_conv_kernel<64, 128, 3, 35, 35, 1, 256, 2>
        <<<dim3(6, 2, NB), 256, SM2>>>(p1, wt2, cb1, c2);
    {
        int nt = NB * 17 * 17 * 128;
        pool_kernel<128, 35, 17, 1><<<(nt + 255) / 256, 256>>>(c2, p2);
    }
    // conv3 + pool3
    mma_conv_kernel<128, 256, 3, 17, 17, 1, 256, 2>
        <<<dim3(2, 4, NB), 256, SM3>>>(p2, wt3, cb2, c3);
    {
        int nt = NB * 8 * 8 * 256;
        pool_kernel<256, 17, 8, 0><<<(nt + 255) / 256, 256>>>(c3, p3);
    }
    // GAP + FC stack
    gap_kernel<<<(NB * 256 + 255) / 256, 256>>>(p3, gapb);
    fc_kernel<<<(NB * 512 + 255) / 256, 256>>>(gapb, fw0, fb0, f1, 256, 512, 1);
    fc_kernel<<<(NB * 256 + 255) / 256, 256>>>(f1,   fw1, fb1, f2, 512, 256, 1);
    fc_kernel<<<(NB * 512 + 255) / 256, 256>>>(f2,   fw2, fb2, out, 256, 512, 0);
}

// round 3
// speedup vs baseline: 3.3750x; 1.2623x over previous
#include <cuda_runtime.h>
#include <math.h>
#include <stdint.h>

// ---------------- problem constants ----------------
#define NB   128
#define RNUM 300
#define EMB  32

// padded NHWC activation buffers
__device__ float g_grid[NB * 76 * 76 * 40];     // conv1 input  (pad2, ch 33->40)
__device__ float g_c1 [NB * 72 * 72 * 64];      // conv1 out (valid, NHWC)
__device__ float g_p1 [NB * 37 * 37 * 64];      // pool1 out (pad1)
__device__ float g_c2 [NB * 35 * 35 * 128];     // conv2 out
__device__ float g_p2 [NB * 19 * 19 * 128];     // pool2 out (pad1)
__device__ float g_c3 [NB * 17 * 17 * 256];     // conv3 out
__device__ float g_p3 [NB * 8 * 8 * 256];       // pool3 out (no pad)
__device__ float g_gap[NB * 256];
__device__ float g_f1 [NB * 512];
__device__ float g_f2 [NB * 256];
// transformed weights: per-tap smem fragment images
// layout: [kk][cob][c8][nt][64]   (64-elem 8x8 k-pair-packed tile)
__device__ float g_wt1[25 * 40 * 64];
__device__ float g_wt2[9 * 64 * 128];
__device__ float g_wt3[9 * 128 * 256];

// ---------------- helpers ----------------
__device__ __forceinline__ float to_tf32(float x) {
    float r; asm("cvt.rna.tf32.f32 %0, %1;" : "=f"(r) : "f"(x)); return r;
}
__device__ __forceinline__ void mma_tf32(float* d, const uint32_t* a, const uint32_t* b) {
    asm volatile(
        "mma.sync.aligned.m16n8k8.row.col.f32.tf32.tf32.f32 "
        "{%0,%1,%2,%3}, {%4,%5,%6,%7}, {%8,%9}, {%0,%1,%2,%3};"
        : "+f"(d[0]), "+f"(d[1]), "+f"(d[2]), "+f"(d[3])
        : "r"(a[0]), "r"(a[1]), "r"(a[2]), "r"(a[3]), "r"(b[0]), "r"(b[1]));
}
__device__ __forceinline__ void cp_async16(float* smem_dst, const float* gsrc) {
    uint32_t s = (uint32_t)__cvta_generic_to_shared(smem_dst);
    asm volatile("cp.async.cg.shared.global [%0], [%1], 16;" :: "r"(s), "l"(gsrc));
}

// ---------------- zero fill (vectorized) ----------------
__global__ void zero_kernel(float4* __restrict__ p, int n4) {
    int i = blockIdx.x * blockDim.x + threadIdx.x;
    if (i < n4) p[i] = make_float4(0.f, 0.f, 0.f, 0.f);
}

// ---------------- scatter rooms into padded NHWC grid ----------------
__global__ void scatter_kernel(const int* __restrict__ X,
                               const int* __restrict__ rm,
                               const float* __restrict__ emb,
                               float* __restrict__ grid) {
    int idx = blockIdx.x * blockDim.x + threadIdx.x;     // n * R * 64
    if (idx >= NB * RNUM * 64) return;
    int cell = idx & 63;
    int r    = (idx >> 6) % RNUM;
    int n    = idx / (RNUM * 64);
    if (!rm[r * 64 + cell]) return;
    int cx = cell >> 3, cy = cell & 7;
    int px = X[(n * RNUM + r) * 2 + 0];
    int py = X[(n * RNUM + r) * 2 + 1];
    int Y = py + cy + 2, Xc = px + cx + 2;               // padded coords, layout [n][Y][X][40]
    float* base = grid + (((size_t)n * 76 + Y) * 76 + Xc) * 40;
    atomicAdd(base, 1.0f);
    const float* er = emb + r * EMB;
#pragma unroll
    for (int e = 0; e < EMB; ++e)
        atomicAdd(base + 1 + e, er[e]);
}

// ------- weight transform: OIHW -> per-tap fragment image, tf32 -------------
// out layout: [kk][cob][c8][nt][e64], e64 = kmod*16 + nloc*2 + khalf
//   ci = c8*8 + khalf*4 + kmod ; co = cob*64 + nt*8 + nloc
template<int CI, int CIP, int CO, int KK>
__global__ void wtrans_kernel(const float* __restrict__ w, float* __restrict__ wt) {
    constexpr int NC8 = CIP / 8, COB = CO / 64;
    int i = blockIdx.x * blockDim.x + threadIdx.x;
    if (i >= KK * COB * NC8 * 8 * 64) return;
    int e   = i & 63;
    int tt  = i >> 6;
    int nt  = tt & 7;
    int tt2 = tt >> 3;
    int c8  = tt2 % NC8;
    int tt3 = tt2 / NC8;
    int cob = tt3 % COB;
    int kk  = tt3 / COB;
    int kmod = e >> 4, nloc = (e >> 1) & 7, kh = e & 1;
    int ci = c8 * 8 + kh * 4 + kmod;
    int co = cob * 64 + nt * 8 + nloc;
    float v = (ci < CI) ? w[((size_t)co * CI + ci) * KK + kk] : 0.f;
    wt[i] = to_tf32(v);
}

// ---------------- tf32 tensor-core conv (shifted-window implicit GEMM) ------
// input: padded NHWC [NB][Hp][Wp][CINP*HALVES]; out: valid NHWC [NB][H][W][CO]
// MT = 2 fixed. MPIX = NWARP*32. B double-buffered via cp.async.
template<int CINP, int HALVES, int CO, int K, int H, int W, int PAD, int NTHREADS>
__global__ void __launch_bounds__(NTHREADS, (NTHREADS == 256) ? 2 : 1)
mma_conv_kernel(const float* __restrict__ in, const float* __restrict__ wt,
                const float* __restrict__ bias, float* __restrict__ out) {
    constexpr int MT   = 2;
    constexpr int NT   = 8;
    constexpr int NWARP = NTHREADS / 32;
    constexpr int MPIX = NWARP * 16 * MT;
    constexpr int Wp = W + 2 * PAD;
    constexpr int Hp = H + 2 * PAD;
    constexpr int HALO = PAD * Wp + PAD;
    constexpr int AWIN = MPIX + 2 * HALO;
    constexpr int NPIX = Hp * Wp;
    constexpr int KK   = K * K;
    constexpr int AST  = CINP + 4;
    constexpr int NC8  = CINP / 8;
    constexpr int NC8F = NC8 * HALVES;
    constexpr int CINF = CINP * HALVES;
    constexpr int COB  = CO / 64;
    constexpr int BSZ  = CINP * 64;          // floats per B buffer
    constexpr int NCHUNK = BSZ / 4;
    constexpr int C4   = CINP / 4;

    extern __shared__ float smem[];
    float* sA = smem;                         // [AWIN][AST]
    float* sB = smem + AWIN * AST;            // [2][BSZ]

    const int n    = blockIdx.z;
    const int cob  = blockIdx.y;
    const int co0  = cob * 64;
    const int p0   = HALO + blockIdx.x * MPIX;
    const int s0   = p0 - HALO;
    const int t    = threadIdx.x;
    const int warp = t >> 5, lane = t & 31;
    const int ar   = lane >> 2;               // 0..7
    const int ac   = lane & 3;                // 0..3
    const int wrow = warp * (16 * MT);

    const float* inb = in + (size_t)n * NPIX * CINF;

    float d[MT][NT][4];
#pragma unroll
    for (int mt = 0; mt < MT; ++mt)
#pragma unroll
        for (int nt = 0; nt < NT; ++nt)
#pragma unroll
            for (int q = 0; q < 4; ++q) d[mt][nt][q] = 0.f;

#pragma unroll 1
    for (int h = 0; h < HALVES; ++h) {
        // stage A window for this channel half (tf32-rounded)
#pragma unroll 2
        for (int e = t; e < AWIN * C4; e += NTHREADS) {
            int pw = e / C4, c4 = e - pw * C4;
            int pix = s0 + pw;
            float4 v = make_float4(0.f, 0.f, 0.f, 0.f);
            if (pix < NPIX)
                v = *(const float4*)(inb + (size_t)pix * CINF + h * CINP + c4 * 4);
            v.x = to_tf32(v.x); v.y = to_tf32(v.y);
            v.z = to_tf32(v.z); v.w = to_tf32(v.w);
            *(float4*)(sA + pw * AST + c4 * 4) = v;
        }
        // prefetch B for taps 0 and 1
#pragma unroll 1
        for (int pf = 0; pf < 2; ++pf) {
            const float* src = wt + ((size_t)(pf * COB + cob) * NC8F + h * NC8) * 512;
            float* dst = sB + pf * BSZ;
            for (int c = t; c < NCHUNK; c += NTHREADS)
                cp_async16(dst + c * 4, src + c * 4);
            asm volatile("cp.async.commit_group;" ::: "memory");
        }

#pragma unroll 1
        for (int kk = 0; kk < KK; ++kk) {
            if (kk + 1 < KK) asm volatile("cp.async.wait_group 1;" ::: "memory");
            else             asm volatile("cp.async.wait_group 0;" ::: "memory");
            __syncthreads();

            const float* sBb = sB + (kk & 1) * BSZ;
            const int abase = HALO + (kk / K - PAD) * Wp + (kk % K - PAD) + wrow;
#pragma unroll
            for (int c8 = 0; c8 < NC8; ++c8) {
                float2 bf[NT];
                const float2* bt = (const float2*)(sBb + c8 * 512);
#pragma unroll
                for (int nt = 0; nt < NT; ++nt)
                    bf[nt] = bt[nt * 32 + ac * 8 + ar];
#pragma unroll
                for (int mt = 0; mt < MT; ++mt) {
                    const float* ap = sA + (abase + mt * 16 + ar) * AST + c8 * 8 + ac;
                    uint32_t af[4];
                    af[0] = __float_as_uint(ap[0]);
                    af[1] = __float_as_uint(ap[8 * AST]);
                    af[2] = __float_as_uint(ap[4]);
                    af[3] = __float_as_uint(ap[8 * AST + 4]);
#pragma unroll
                    for (int nt = 0; nt < NT; ++nt)
                        mma_tf32(d[mt][nt], af, (const uint32_t*)&bf[nt]);
                }
            }
            __syncthreads();
            if (kk + 2 < KK) {
                const float* src = wt + ((size_t)((kk + 2) * COB + cob) * NC8F + h * NC8) * 512;
                float* dst = sB + (kk & 1) * BSZ;
                for (int c = t; c < NCHUNK; c += NTHREADS)
                    cp_async16(dst + c * 4, src + c * 4);
                asm volatile("cp.async.commit_group;" ::: "memory");
            }
        }
    }

    // epilogue: bias + relu, store valid pixels (NHWC)
    float2 bv[NT];
#pragma unroll
    for (int nt = 0; nt < NT; ++nt)
        bv[nt] = *(const float2*)(bias + co0 + nt * 8 + 2 * ac);

#pragma unroll
    for (int mt = 0; mt < MT; ++mt) {
#pragma unroll
        for (int half = 0; half < 2; ++half) {
            int p = p0 + wrow + mt * 16 + half * 8 + ar;
            int y = p / Wp - PAD, x = p % Wp - PAD;
            if (x >= 0 && x < W && y < H) {
                float* ob = out + (((size_t)n * H + y) * W + x) * CO + co0;
#pragma unroll
                for (int nt = 0; nt < NT; ++nt) {
                    float2 v;
                    v.x = fmaxf(d[mt][nt][half * 2 + 0] + bv[nt].x, 0.f);
                    v.y = fmaxf(d[mt][nt][half * 2 + 1] + bv[nt].y, 0.f);
                    *(float2*)(ob + nt * 8 + 2 * ac) = v;
                }
            }
        }
    }
}

// ---------------- 3x3 s2 max pool, NHWC in -> padded NHWC out (float4) ------
template<int C, int HI, int HO, int P>
__global__ void pool_kernel(const float4* __restrict__ in, float4* __restrict__ out) {
    constexpr int C4 = C / 4, HOP = HO + 2 * P;
    int idx = blockIdx.x * blockDim.x + threadIdx.x;
    if (idx >= NB * HO * HO * C4) return;
    int c  = idx % C4;
    int ox = (idx / C4) % HO;
    int oy = (idx / (C4 * HO)) % HO;
    int n  = idx / (C4 * HO * HO);
    const float4* p = in + (((size_t)n * HI + 2 * oy) * HI + 2 * ox) * C4 + c;
    float4 m = p[0];
#pragma unroll
    for (int dy = 0; dy < 3; ++dy)
#pragma unroll
        for (int dx = 0; dx < 3; ++dx) {
            float4 q = p[((size_t)dy * HI + dx) * C4];
            m.x = fmaxf(m.x, q.x); m.y = fmaxf(m.y, q.y);
            m.z = fmaxf(m.z, q.z); m.w = fmaxf(m.w, q.w);
        }
    out[(((size_t)n * HOP + oy + P) * HOP + ox + P) * C4 + c] = m;
}

// ---------------- global average pool over 8x8 (NHWC, float4) ----------------
__global__ void gap_kernel(const float4* __restrict__ in, float4* __restrict__ out) {
    int idx = blockIdx.x * blockDim.x + threadIdx.x;   // n*64 + c4
    if (idx >= NB * 64) return;
    int n = idx >> 6, c = idx & 63;
    const float4* p = in + (size_t)n * 64 * 64 + c;
    float4 s = make_float4(0.f, 0.f, 0.f, 0.f);
#pragma unroll
    for (int i = 0; i < 64; ++i) {
        float4 q = p[i * 64];
        s.x += q.x; s.y += q.y; s.z += q.z; s.w += q.w;
    }
    s.x *= (1.f/64.f); s.y *= (1.f/64.f); s.z *= (1.f/64.f); s.w *= (1.f/64.f);
    out[idx] = s;
}

// ---------------- fully connected ----------------
__global__ void fc_kernel(const float* __restrict__ in, const float* __restrict__ w,
                          const float* __restrict__ b, float* __restrict__ out,
                          int K_, int O_, int relu) {
    int idx = blockIdx.x * blockDim.x + threadIdx.x;
    if (idx >= NB * O_) return;
    int n = idx / O_, o = idx % O_;
    const float4* ip = (const float4*)(in + (size_t)n * K_);
    const float4* wp = (const float4*)(w + (size_t)o * K_);
    float s = b[o];
    int k4 = K_ >> 2;
#pragma unroll 4
    for (int k = 0; k < k4; ++k) {
        float4 a = ip[k], ww = wp[k];
        s = fmaf(a.x, ww.x, s); s = fmaf(a.y, ww.y, s);
        s = fmaf(a.z, ww.z, s); s = fmaf(a.w, ww.w, s);
    }
    if (relu) s = fmaxf(s, 0.f);
    out[idx] = s;
}

// ---------------- launch ----------------
extern "C" void kernel_launch(void* const* d_in, const int* in_sizes, int n_in,
                              void* d_out, int out_size) {
    const int*   X    = (const int*)  d_in[0];
    const int*   rmap = (const int*)  d_in[1];
    const float* emb  = (const float*)d_in[2];
    const float* cw0  = (const float*)d_in[3];
    const float* cb0  = (const float*)d_in[4];
    const float* cw1  = (const float*)d_in[5];
    const float* cb1  = (const float*)d_in[6];
    const float* cw2  = (const float*)d_in[7];
    const float* cb2  = (const float*)d_in[8];
    const float* fw0  = (const float*)d_in[9];
    const float* fb0  = (const float*)d_in[10];
    const float* fw1  = (const float*)d_in[11];
    const float* fb1  = (const float*)d_in[12];
    const float* fw2  = (const float*)d_in[13];
    const float* fb2  = (const float*)d_in[14];
    float* out = (float*)d_out;

    float *grid, *c1, *p1, *c2, *p2, *c3, *p3, *gapb, *f1, *f2, *wt1, *wt2, *wt3;
    cudaGetSymbolAddress((void**)&grid, g_grid);
    cudaGetSymbolAddress((void**)&c1,  g_c1);
    cudaGetSymbolAddress((void**)&p1,  g_p1);
    cudaGetSymbolAddress((void**)&c2,  g_c2);
    cudaGetSymbolAddress((void**)&p2,  g_p2);
    cudaGetSymbolAddress((void**)&c3,  g_c3);
    cudaGetSymbolAddress((void**)&p3,  g_p3);
    cudaGetSymbolAddress((void**)&gapb, g_gap);
    cudaGetSymbolAddress((void**)&f1,  g_f1);
    cudaGetSymbolAddress((void**)&f2,  g_f2);
    cudaGetSymbolAddress((void**)&wt1, g_wt1);
    cudaGetSymbolAddress((void**)&wt2, g_wt2);
    cudaGetSymbolAddress((void**)&wt3, g_wt3);

    // conv smem sizes
    // conv1: A=(512+308)*44, B=2*40*64 -> 164800 B ; 512 thr, 1 blk/SM
    // conv2: A=(512+76)*68,  B=2*64*64 -> 192704 B ; 512 thr, 1 blk/SM
    // conv3: A=(256+40)*68,  B=2*64*64 -> 113280 B ; 256 thr, 2 blk/SM
    const int SM1 = (820 * 44 + 2 * 40 * 64) * 4;
    const int SM2 = (588 * 68 + 2 * 64 * 64) * 4;
    const int SM3 = (296 * 68 + 2 * 64 * 64) * 4;
    cudaFuncSetAttribute((const void*)mma_conv_kernel<40, 1, 64, 5, 72, 72, 2, 512>,
                         cudaFuncAttributeMaxDynamicSharedMemorySize, SM1);
    cudaFuncSetAttribute((const void*)mma_conv_kernel<64, 1, 128, 3, 35, 35, 1, 512>,
                         cudaFuncAttributeMaxDynamicSharedMemorySize, SM2);
    cudaFuncSetAttribute((const void*)mma_conv_kernel<64, 2, 256, 3, 17, 17, 1, 256>,
                         cudaFuncAttributeMaxDynamicSharedMemorySize, SM3);

    // zero padded buffers
    {
        int n4;
        n4 = NB * 76 * 76 * 40 / 4;  zero_kernel<<<(n4 + 255) / 256, 256>>>((float4*)grid, n4);
        n4 = NB * 37 * 37 * 64 / 4;  zero_kernel<<<(n4 + 255) / 256, 256>>>((float4*)p1, n4);
        n4 = NB * 19 * 19 * 128 / 4; zero_kernel<<<(n4 + 255) / 256, 256>>>((float4*)p2, n4);
    }
    // weight transforms (fragment-image layout)
    {
        int n1 = 25 * 40 * 64;  wtrans_kernel<33, 40, 64, 25><<<(n1 + 255) / 256, 256>>>(cw0, wt1);
        int n2 = 9 * 64 * 128;  wtrans_kernel<64, 64, 128, 9><<<(n2 + 255) / 256, 256>>>(cw1, wt2);
        int n3 = 9 * 128 * 256; wtrans_kernel<128, 128, 256, 9><<<(n3 + 255) / 256, 256>>>(cw2, wt3);
    }
    // scatter encode
    {
        int nt = NB * RNUM * 64;
        scatter_kernel<<<(nt + 255) / 256, 256>>>(X, rmap, emb, grid);
    }
    // conv1 + pool1
    mma_conv_kernel<40, 1, 64, 5, 72, 72, 2, 512>
        <<<dim3(12, 1, NB), 512, SM1>>>(grid, wt1, cb0, c1);
    {
        int nt = NB * 35 * 35 * 16;
        pool_kernel<64, 72, 35, 1><<<(nt + 255) / 256, 256>>>((const float4*)c1, (float4*)p1);
    }
    // conv2 + pool2
    mma_conv_kernel<64, 1, 128, 3, 35, 35, 1, 512>
        <<<dim3(3, 2, NB), 512, SM2>>>(p1, wt2, cb1, c2);
    {
        int nt = NB * 17 * 17 * 32;
        pool_kernel<128, 35, 17, 1><<<(nt + 255) / 256, 256>>>((const float4*)c2, (float4*)p2);
    }
    // conv3 + pool3
    mma_conv_kernel<64, 2, 256, 3, 17, 17, 1, 256>
        <<<dim3(2, 4, NB), 256, SM3>>>(p2, wt3, cb2, c3);
    {
        int nt = NB * 8 * 8 * 64;
        pool_kernel<256, 17, 8, 0><<<(nt + 255) / 256, 256>>>((const float4*)c3, (float4*)p3);
    }
    // GAP + FC stack
    gap_kernel<<<(NB * 64 + 255) / 256, 256>>>((const float4*)p3, (float4*)gapb);
    fc_kernel<<<(NB * 512 + 255) / 256, 256>>>(gapb, fw0, fb0, f1, 256, 512, 1);
    fc_kernel<<<(NB * 256 + 255) / 256, 256>>>(f1,   fw1, fb1, f2, 512, 256, 1);
    fc_kernel<<<(NB * 512 + 255) / 256, 256>>>(f2,   fw2, fb2, out, 256, 512, 0);
}

// round 4
// speedup vs baseline: 4.6972x; 1.3918x over previous
#include <cuda_runtime.h>
#include <cuda_fp16.h>
#include <math.h>
#include <stdint.h>

// ---------------- problem constants ----------------
#define NB   128
#define RNUM 300
#define EMB  32

// padded NHWC activation buffers (fp32)
__device__ float g_grid[NB * 76 * 76 * 40];     // conv1 input  (pad2, ch 33->40)
__device__ float g_c1 [NB * 72 * 72 * 64];      // conv1 out
__device__ float g_p1 [NB * 37 * 37 * 64];      // pool1 out (pad1)
__device__ float g_c2 [NB * 35 * 35 * 128];     // conv2 out
__device__ float g_p2 [NB * 19 * 19 * 128];     // pool2 out (pad1)
__device__ float g_c3 [NB * 17 * 17 * 256];     // conv3 out
__device__ float g_p3 [NB * 8 * 8 * 256];       // pool3 out
__device__ float g_gap[NB * 256];
__device__ float g_f1 [NB * 512];
__device__ float g_f2 [NB * 256];
// transformed weights: per-tap half2 fragment images (uint32 = half2)
// layout: [kk][cob][h][c16][nt][64]
__device__ unsigned g_wt1[25 * 1 * 1 * 3 * 512];
__device__ unsigned g_wt2[ 9 * 2 * 1 * 4 * 512];
__device__ unsigned g_wt3[ 9 * 4 * 2 * 4 * 512];

// ---------------- helpers ----------------
__device__ __forceinline__ void mma_f16(float* d, const uint32_t* a, const uint32_t* b) {
    asm volatile(
        "mma.sync.aligned.m16n8k16.row.col.f32.f16.f16.f32 "
        "{%0,%1,%2,%3}, {%4,%5,%6,%7}, {%8,%9}, {%0,%1,%2,%3};"
        : "+f"(d[0]), "+f"(d[1]), "+f"(d[2]), "+f"(d[3])
        : "r"(a[0]), "r"(a[1]), "r"(a[2]), "r"(a[3]), "r"(b[0]), "r"(b[1]));
}
__device__ __forceinline__ void cp_async16(void* smem_dst, const void* gsrc) {
    uint32_t s = (uint32_t)__cvta_generic_to_shared(smem_dst);
    asm volatile("cp.async.cg.shared.global [%0], [%1], 16;" :: "r"(s), "l"(gsrc));
}
__device__ __forceinline__ uint32_t f2h2(float a, float b) {
    __half2 h = __float22half2_rn(make_float2(a, b));
    return *(uint32_t*)&h;
}

// ---------------- zero fill ----------------
__global__ void zero_kernel(float4* __restrict__ p, int n4) {
    int i = blockIdx.x * blockDim.x + threadIdx.x;
    if (i < n4) p[i] = make_float4(0.f, 0.f, 0.f, 0.f);
}

// ---------------- scatter rooms into padded NHWC grid ----------------
__global__ void scatter_kernel(const int* __restrict__ X,
                               const int* __restrict__ rm,
                               const float* __restrict__ emb,
                               float* __restrict__ grid) {
    int idx = blockIdx.x * blockDim.x + threadIdx.x;     // n * R * 64
    if (idx >= NB * RNUM * 64) return;
    int cell = idx & 63;
    int r    = (idx >> 6) % RNUM;
    int n    = idx / (RNUM * 64);
    if (!rm[r * 64 + cell]) return;
    int cx = cell >> 3, cy = cell & 7;
    int px = X[(n * RNUM + r) * 2 + 0];
    int py = X[(n * RNUM + r) * 2 + 1];
    int Y = py + cy + 2, Xc = px + cx + 2;               // padded coords [n][Y][X][40]
    float* base = grid + (((size_t)n * 76 + Y) * 76 + Xc) * 40;
    atomicAdd(base, 1.0f);
    const float* er = emb + r * EMB;
#pragma unroll
    for (int e = 0; e < EMB; ++e)
        atomicAdd(base + 1 + e, er[e]);
}

// ------- weight transform: OIHW -> per-tap half2 fragment image -------------
// uint32 index i decodes as [kk][cob][h][c16][nt][u64]
//   u = pair*2 + which ; pair = ac*8 + ar ; k0 = c16*16 + ac*2 + which*8
//   ci = h*CIPH + k0 ; co = cob*64 + nt*8 + ar ; half2 = (w[ci], w[ci+1])
template<int CI, int CIPH, int HALVES, int CO, int KK>
__global__ void wtrans_kernel(const float* __restrict__ w, unsigned* __restrict__ wt) {
    constexpr int NC16 = CIPH / 16, COB = CO / 64;
    int i = blockIdx.x * blockDim.x + threadIdx.x;
    if (i >= KK * COB * HALVES * NC16 * 512) return;
    int u  = i & 63;  int t1 = i >> 6;
    int nt = t1 & 7;  int t2 = t1 >> 3;
    int c16 = t2 % NC16; int t3 = t2 / NC16;
    int h  = t3 % HALVES; int t4 = t3 / HALVES;
    int cob = t4 % COB;  int kk = t4 / COB;
    int pair = u >> 1, which = u & 1;
    int ac = pair >> 3, ar = pair & 7;
    int k0 = c16 * 16 + ac * 2 + which * 8;
    int ci0 = h * CIPH + k0;
    int co  = cob * 64 + nt * 8 + ar;
    float v0 = (ci0     < CI) ? w[((size_t)co * CI + ci0)     * KK + kk] : 0.f;
    float v1 = (ci0 + 1 < CI) ? w[((size_t)co * CI + ci0 + 1) * KK + kk] : 0.f;
    wt[i] = f2h2(v0, v1);
}

// ---------------- fp16 tensor-core conv (shifted-window implicit GEMM) ------
// input: padded NHWC fp32 [NB][Hp][Wp][CING*HALVES]; out: valid NHWC [NB][H][W][CO]
// A staged as half2 in smem; B double-buffered fragment images via cp.async.
template<int CINP, int CING, int HALVES, int CO, int K, int H, int W, int PAD, int NTHREADS>
__global__ void __launch_bounds__(NTHREADS, (NTHREADS == 256) ? 2 : 1)
mma_conv_kernel(const float* __restrict__ in, const unsigned* __restrict__ wt,
                const float* __restrict__ bias, float* __restrict__ out) {
    constexpr int MT   = 2;
    constexpr int NT   = 8;
    constexpr int NWARP = NTHREADS / 32;
    constexpr int MPIX = NWARP * 16 * MT;
    constexpr int Wp   = W + 2 * PAD;
    constexpr int Hp   = H + 2 * PAD;
    constexpr int HALO = PAD * Wp + PAD;
    constexpr int AWIN = MPIX + 2 * HALO;
    constexpr int NPIX = Hp * Wp;
    constexpr int KK   = K * K;
    constexpr int AST2 = CINP / 2 + 4;          // half2 stride, conflict-free frags
    constexpr int NC16 = CINP / 16;
    constexpr int CINF = CING * HALVES;
    constexpr int COB  = CO / 64;
    constexpr int BSZ  = NC16 * 512;            // uint32 per B buffer
    constexpr int CP4  = CINP / 4;
    constexpr int CG4  = CING / 4;

    extern __shared__ uint32_t smem[];
    uint32_t* sA = smem;                        // [AWIN][AST2] half2
    uint32_t* sB = smem + AWIN * AST2;          // [2][BSZ]

    const int n    = blockIdx.z;
    const int cob  = blockIdx.y;
    const int co0  = cob * 64;
    const int p0   = HALO + blockIdx.x * MPIX;
    const int s0   = p0 - HALO;
    const int t    = threadIdx.x;
    const int warp = t >> 5, lane = t & 31;
    const int ar   = lane >> 2;                 // 0..7 (row / col group)
    const int ac   = lane & 3;                  // 0..3 (k-pair group)
    const int wrow = warp * (16 * MT);

    const float* inb = in + (size_t)n * NPIX * CINF;

    float d[MT][NT][4];
#pragma unroll
    for (int mt = 0; mt < MT; ++mt)
#pragma unroll
        for (int nt = 0; nt < NT; ++nt)
#pragma unroll
            for (int q = 0; q < 4; ++q) d[mt][nt][q] = 0.f;

#pragma unroll 1
    for (int h = 0; h < HALVES; ++h) {
        // stage A window for this half: fp32 -> half2
#pragma unroll 2
        for (int e = t; e < AWIN * CP4; e += NTHREADS) {
            int pw = e / CP4, c4 = e - pw * CP4;
            int pix = s0 + pw;
            float4 v = make_float4(0.f, 0.f, 0.f, 0.f);
            if (pix < NPIX && c4 < CG4)
                v = *(const float4*)(inb + (size_t)pix * CINF + h * CING + c4 * 4);
            sA[pw * AST2 + c4 * 2 + 0] = f2h2(v.x, v.y);
            sA[pw * AST2 + c4 * 2 + 1] = f2h2(v.z, v.w);
        }
        // prefetch B for taps 0 and 1
#pragma unroll 1
        for (int pf = 0; pf < 2; ++pf) {
            const unsigned* src = wt + ((size_t)(pf * COB + cob) * HALVES + h) * BSZ;
            uint32_t* dst = sB + pf * BSZ;
            for (int c = t; c < BSZ / 4; c += NTHREADS)
                cp_async16(dst + c * 4, src + c * 4);
            asm volatile("cp.async.commit_group;" ::: "memory");
        }

#pragma unroll 1
        for (int kk = 0; kk < KK; ++kk) {
            if (kk + 1 < KK) asm volatile("cp.async.wait_group 1;" ::: "memory");
            else             asm volatile("cp.async.wait_group 0;" ::: "memory");
            __syncthreads();

            const uint32_t* sBb = sB + (kk & 1) * BSZ;
            const int abase = HALO + (kk / K - PAD) * Wp + (kk % K - PAD) + wrow;
#pragma unroll
            for (int c16 = 0; c16 < NC16; ++c16) {
                uint2 bf[NT];
                const uint2* bt = (const uint2*)(sBb + c16 * 512);
#pragma unroll
                for (int nt = 0; nt < NT; ++nt)
                    bf[nt] = bt[nt * 32 + ac * 8 + ar];
#pragma unroll
                for (int mt = 0; mt < MT; ++mt) {
                    const uint32_t* ap = sA + (abase + mt * 16 + ar) * AST2 + c16 * 8 + ac;
                    uint32_t af[4];
                    af[0] = ap[0];
                    af[1] = ap[8 * AST2];
                    af[2] = ap[4];
                    af[3] = ap[8 * AST2 + 4];
#pragma unroll
                    for (int nt = 0; nt < NT; ++nt)
                        mma_f16(d[mt][nt], af, (const uint32_t*)&bf[nt]);
                }
            }
            __syncthreads();
            if (kk + 2 < KK) {
                const unsigned* src = wt + ((size_t)((kk + 2) * COB + cob) * HALVES + h) * BSZ;
                uint32_t* dst = sB + (kk & 1) * BSZ;
                for (int c = t; c < BSZ / 4; c += NTHREADS)
                    cp_async16(dst + c * 4, src + c * 4);
                asm volatile("cp.async.commit_group;" ::: "memory");
            }
        }
    }

    // epilogue: bias + relu, store valid pixels (NHWC)
    float2 bv[NT];
#pragma unroll
    for (int nt = 0; nt < NT; ++nt)
        bv[nt] = *(const float2*)(bias + co0 + nt * 8 + 2 * ac);

#pragma unroll
    for (int mt = 0; mt < MT; ++mt) {
#pragma unroll
        for (int half = 0; half < 2; ++half) {
            int p = p0 + wrow + mt * 16 + half * 8 + ar;
            int y = p / Wp - PAD, x = p % Wp - PAD;
            if (x >= 0 && x < W && y < H) {
                float* ob = out + (((size_t)n * H + y) * W + x) * CO + co0;
#pragma unroll
                for (int nt = 0; nt < NT; ++nt) {
                    float2 v;
                    v.x = fmaxf(d[mt][nt][half * 2 + 0] + bv[nt].x, 0.f);
                    v.y = fmaxf(d[mt][nt][half * 2 + 1] + bv[nt].y, 0.f);
                    *(float2*)(ob + nt * 8 + 2 * ac) = v;
                }
            }
        }
    }
}

// ---------------- 3x3 s2 max pool, NHWC in -> padded NHWC out (float4) ------
template<int C, int HI, int HO, int P>
__global__ void pool_kernel(const float4* __restrict__ in, float4* __restrict__ out) {
    constexpr int C4 = C / 4, HOP = HO + 2 * P;
    int idx = blockIdx.x * blockDim.x + threadIdx.x;
    if (idx >= NB * HO * HO * C4) return;
    int c  = idx % C4;
    int ox = (idx / C4) % HO;
    int oy = (idx / (C4 * HO)) % HO;
    int n  = idx / (C4 * HO * HO);
    const float4* p = in + (((size_t)n * HI + 2 * oy) * HI + 2 * ox) * C4 + c;
    float4 m = p[0];
#pragma unroll
    for (int dy = 0; dy < 3; ++dy)
#pragma unroll
        for (int dx = 0; dx < 3; ++dx) {
            float4 q = p[((size_t)dy * HI + dx) * C4];
            m.x = fmaxf(m.x, q.x); m.y = fmaxf(m.y, q.y);
            m.z = fmaxf(m.z, q.z); m.w = fmaxf(m.w, q.w);
        }
    out[(((size_t)n * HOP + oy + P) * HOP + ox + P) * C4 + c] = m;
}

// ---------------- global average pool over 8x8 (NHWC, float4) ----------------
__global__ void gap_kernel(const float4* __restrict__ in, float4* __restrict__ out) {
    int idx = blockIdx.x * blockDim.x + threadIdx.x;   // n*64 + c4
    if (idx >= NB * 64) return;
    int n = idx >> 6, c = idx & 63;
    const float4* p = in + (size_t)n * 64 * 64 + c;
    float4 s = make_float4(0.f, 0.f, 0.f, 0.f);
#pragma unroll
    for (int i = 0; i < 64; ++i) {
        float4 q = p[i * 64];
        s.x += q.x; s.y += q.y; s.z += q.z; s.w += q.w;
    }
    s.x *= (1.f/64.f); s.y *= (1.f/64.f); s.z *= (1.f/64.f); s.w *= (1.f/64.f);
    out[idx] = s;
}

// ---------------- fully connected ----------------
__global__ void fc_kernel(const float* __restrict__ in, const float* __restrict__ w,
                          const float* __restrict__ b, float* __restrict__ out,
                          int K_, int O_, int relu) {
    int idx = blockIdx.x * blockDim.x + threadIdx.x;
    if (idx >= NB * O_) return;
    int n = idx / O_, o = idx % O_;
    const float4* ip = (const float4*)(in + (size_t)n * K_);
    const float4* wp = (const float4*)(w + (size_t)o * K_);
    float s = b[o];
    int k4 = K_ >> 2;
#pragma unroll 4
    for (int k = 0; k < k4; ++k) {
        float4 a = ip[k], ww = wp[k];
        s = fmaf(a.x, ww.x, s); s = fmaf(a.y, ww.y, s);
        s = fmaf(a.z, ww.z, s); s = fmaf(a.w, ww.w, s);
    }
    if (relu) s = fmaxf(s, 0.f);
    out[idx] = s;
}

// ---------------- launch ----------------
extern "C" void kernel_launch(void* const* d_in, const int* in_sizes, int n_in,
                              void* d_out, int out_size) {
    const int*   X    = (const int*)  d_in[0];
    const int*   rmap = (const int*)  d_in[1];
    const float* emb  = (const float*)d_in[2];
    const float* cw0  = (const float*)d_in[3];
    const float* cb0  = (const float*)d_in[4];
    const float* cw1  = (const float*)d_in[5];
    const float* cb1  = (const float*)d_in[6];
    const float* cw2  = (const float*)d_in[7];
    const float* cb2  = (const float*)d_in[8];
    const float* fw0  = (const float*)d_in[9];
    const float* fb0  = (const float*)d_in[10];
    const float* fw1  = (const float*)d_in[11];
    const float* fb1  = (const float*)d_in[12];
    const float* fw2  = (const float*)d_in[13];
    const float* fb2  = (const float*)d_in[14];
    float* out = (float*)d_out;

    float *grid, *c1, *p1, *c2, *p2, *c3, *p3, *gapb, *f1, *f2;
    unsigned *wt1, *wt2, *wt3;
    cudaGetSymbolAddress((void**)&grid, g_grid);
    cudaGetSymbolAddress((void**)&c1,  g_c1);
    cudaGetSymbolAddress((void**)&p1,  g_p1);
    cudaGetSymbolAddress((void**)&c2,  g_c2);
    cudaGetSymbolAddress((void**)&p2,  g_p2);
    cudaGetSymbolAddress((void**)&c3,  g_c3);
    cudaGetSymbolAddress((void**)&p3,  g_p3);
    cudaGetSymbolAddress((void**)&gapb, g_gap);
    cudaGetSymbolAddress((void**)&f1,  g_f1);
    cudaGetSymbolAddress((void**)&f2,  g_f2);
    cudaGetSymbolAddress((void**)&wt1, g_wt1);
    cudaGetSymbolAddress((void**)&wt2, g_wt2);
    cudaGetSymbolAddress((void**)&wt3, g_wt3);

    // smem sizes
    // conv1: A=(512+308)*28, B=2*3*512 -> 104,128 B ; 512 thr
    // conv2: A=(512+76)*36,  B=2*4*512 -> 101,056 B ; 512 thr
    // conv3: A=(256+40)*36,  B=2*4*512 ->  59,008 B ; 256 thr, 2 blk/SM
    const int SM1 = (820 * 28 + 2 * 3 * 512) * 4;
    const int SM2 = (588 * 36 + 2 * 4 * 512) * 4;
    const int SM3 = (296 * 36 + 2 * 4 * 512) * 4;
    cudaFuncSetAttribute((const void*)mma_conv_kernel<48, 40, 1, 64, 5, 72, 72, 2, 512>,
                         cudaFuncAttributeMaxDynamicSharedMemorySize, SM1);
    cudaFuncSetAttribute((const void*)mma_conv_kernel<64, 64, 1, 128, 3, 35, 35, 1, 512>,
                         cudaFuncAttributeMaxDynamicSharedMemorySize, SM2);
    cudaFuncSetAttribute((const void*)mma_conv_kernel<64, 64, 2, 256, 3, 17, 17, 1, 256>,
                         cudaFuncAttributeMaxDynamicSharedMemorySize, SM3);

    // zero padded buffers
    {
        int n4;
        n4 = NB * 76 * 76 * 40 / 4;  zero_kernel<<<(n4 + 255) / 256, 256>>>((float4*)grid, n4);
        n4 = NB * 37 * 37 * 64 / 4;  zero_kernel<<<(n4 + 255) / 256, 256>>>((float4*)p1, n4);
        n4 = NB * 19 * 19 * 128 / 4; zero_kernel<<<(n4 + 255) / 256, 256>>>((float4*)p2, n4);
    }
    // weight transforms (half2 fragment images)
    {
        int n1 = 25 * 1 * 1 * 3 * 512; wtrans_kernel<33, 48, 1, 64, 25><<<(n1 + 255) / 256, 256>>>(cw0, wt1);
        int n2 =  9 * 2 * 1 * 4 * 512; wtrans_kernel<64, 64, 1, 128, 9><<<(n2 + 255) / 256, 256>>>(cw1, wt2);
        int n3 =  9 * 4 * 2 * 4 * 512; wtrans_kernel<128, 64, 2, 256, 9><<<(n3 + 255) / 256, 256>>>(cw2, wt3);
    }
    // scatter encode
    {
        int nt = NB * RNUM * 64;
        scatter_kernel<<<(nt + 255) / 256, 256>>>(X, rmap, emb, grid);
    }
    // conv1 + pool1
    mma_conv_kernel<48, 40, 1, 64, 5, 72, 72, 2, 512>
        <<<dim3(11, 1, NB), 512, SM1>>>(grid, wt1, cb0, c1);
    {
        int nt = NB * 35 * 35 * 16;
        pool_kernel<64, 72, 35, 1><<<(nt + 255) / 256, 256>>>((const float4*)c1, (float4*)p1);
    }
    // conv2 + pool2
    mma_conv_kernel<64, 64, 1, 128, 3, 35, 35, 1, 512>
        <<<dim3(3, 2, NB), 512, SM2>>>(p1, wt2, cb1, c2);
    {
        int nt = NB * 17 * 17 * 32;
        pool_kernel<128, 35, 17, 1><<<(nt + 255) / 256, 256>>>((const float4*)c2, (float4*)p2);
    }
    // conv3 + pool3
    mma_conv_kernel<64, 64, 2, 256, 3, 17, 17, 1, 256>
        <<<dim3(2, 4, NB), 256, SM3>>>(p2, wt3, cb2, c3);
    {
        int nt = NB * 8 * 8 * 64;
        pool_kernel<256, 17, 8, 0><<<(nt + 255) / 256, 256>>>((const float4*)c3, (float4*)p3);
    }
    // GAP + FC stack
    gap_kernel<<<(NB * 64 + 255) / 256, 256>>>((const float4*)p3, (float4*)gapb);
    fc_kernel<<<(NB * 512 + 255) / 256, 256>>>(gapb, fw0, fb0, f1, 256, 512, 1);
    fc_kernel<<<(NB * 256 + 255) / 256, 256>>>(f1,   fw1, fb1, f2, 512, 256, 1);
    fc_kernel<<<(NB * 512 + 255) / 256, 256>>>(f2,   fw2, fb2, out, 256, 512, 0);
}

// round 5
// speedup vs baseline: 5.1098x; 1.0878x over previous
#include <cuda_runtime.h>
#include <cuda_fp16.h>
#include <math.h>
#include <stdint.h>

// ---------------- problem constants ----------------
#define NB   128
#define RNUM 300
#define EMB  32

// activation buffers
__device__ float    g_grid[NB * 76 * 76 * 40];       // conv1 input (fp32, pad2)
__device__ unsigned g_c1 [NB * 72 * 72 * 32];        // conv1 out (half2 words)
__device__ unsigned g_p1 [NB * 37 * 37 * 32];        // pool1 out (half2, pad1)
__device__ unsigned g_c2 [NB * 35 * 35 * 64];        // conv2 out (half2)
__device__ unsigned g_p2 [NB * 19 * 19 * 64];        // pool2 out (half2, pad1)
__device__ float    g_c3 [NB * 17 * 17 * 256];       // conv3 out (fp32)
__device__ float    g_p3 [NB * 8 * 8 * 256];         // pool3 out
__device__ float    g_gap[NB * 256];
__device__ float    g_f1 [NB * 512];
__device__ float    g_f2 [NB * 256];
// weights: per-tap half2 fragment images [kk][cob][h][c16][nt][64]
__device__ unsigned g_wt1[25 * 1 * 1 * 3 * 512];
__device__ unsigned g_wt2[ 9 * 2 * 1 * 4 * 512];
__device__ unsigned g_wt3[ 9 * 4 * 2 * 4 * 512];

// ---------------- helpers ----------------
__device__ __forceinline__ void mma_f16(float* d, const uint32_t* a, const uint32_t* b) {
    asm volatile(
        "mma.sync.aligned.m16n8k16.row.col.f32.f16.f16.f32 "
        "{%0,%1,%2,%3}, {%4,%5,%6,%7}, {%8,%9}, {%0,%1,%2,%3};"
        : "+f"(d[0]), "+f"(d[1]), "+f"(d[2]), "+f"(d[3])
        : "r"(a[0]), "r"(a[1]), "r"(a[2]), "r"(a[3]), "r"(b[0]), "r"(b[1]));
}
__device__ __forceinline__ void cp_async16(void* smem_dst, const void* gsrc) {
    uint32_t s = (uint32_t)__cvta_generic_to_shared(smem_dst);
    asm volatile("cp.async.cg.shared.global [%0], [%1], 16;" :: "r"(s), "l"(gsrc));
}
__device__ __forceinline__ uint32_t f2h2(float a, float b) {
    __half2 h = __float22half2_rn(make_float2(a, b));
    return *(uint32_t*)&h;
}

// ---------------- zero fill ----------------
__global__ void zero_kernel(float4* __restrict__ p, int n4) {
    int i = blockIdx.x * blockDim.x + threadIdx.x;
    if (i < n4) p[i] = make_float4(0.f, 0.f, 0.f, 0.f);
}

// ---------------- scatter rooms into padded NHWC grid ----------------
__global__ void scatter_kernel(const int* __restrict__ X,
                               const int* __restrict__ rm,
                               const float* __restrict__ emb,
                               float* __restrict__ grid) {
    int idx = blockIdx.x * blockDim.x + threadIdx.x;     // n * R * 64
    if (idx >= NB * RNUM * 64) return;
    int cell = idx & 63;
    int r    = (idx >> 6) % RNUM;
    int n    = idx / (RNUM * 64);
    if (!rm[r * 64 + cell]) return;
    int cx = cell >> 3, cy = cell & 7;
    int px = X[(n * RNUM + r) * 2 + 0];
    int py = X[(n * RNUM + r) * 2 + 1];
    int Y = py + cy + 2, Xc = px + cx + 2;
    float* base = grid + (((size_t)n * 76 + Y) * 76 + Xc) * 40;
    atomicAdd(base, 1.0f);
    const float* er = emb + r * EMB;
#pragma unroll
    for (int e = 0; e < EMB; ++e)
        atomicAdd(base + 1 + e, er[e]);
}

// ------- weight transform: OIHW -> per-tap half2 fragment image -------------
template<int CI, int CIPH, int HALVES, int CO, int KK>
__global__ void wtrans_kernel(const float* __restrict__ w, unsigned* __restrict__ wt) {
    constexpr int NC16 = CIPH / 16, COB = CO / 64;
    int i = blockIdx.x * blockDim.x + threadIdx.x;
    if (i >= KK * COB * HALVES * NC16 * 512) return;
    int u  = i & 63;  int t1 = i >> 6;
    int nt = t1 & 7;  int t2 = t1 >> 3;
    int c16 = t2 % NC16; int t3 = t2 / NC16;
    int h  = t3 % HALVES; int t4 = t3 / HALVES;
    int cob = t4 % COB;  int kk = t4 / COB;
    int pair = u >> 1, which = u & 1;
    int ac = pair >> 3, ar = pair & 7;
    int k0 = c16 * 16 + ac * 2 + which * 8;
    int ci0 = h * CIPH + k0;
    int co  = cob * 64 + nt * 8 + ar;
    float v0 = (ci0     < CI) ? w[((size_t)co * CI + ci0)     * KK + kk] : 0.f;
    float v1 = (ci0 + 1 < CI) ? w[((size_t)co * CI + ci0 + 1) * KK + kk] : 0.f;
    wt[i] = f2h2(v0, v1);
}

// ---------------- fp16 tensor-core conv (shifted-window implicit GEMM) ------
// IN_HALF: input is half2 words [NB][Hp][Wp][CINF/2]; else fp32 [..][CINF]
// OUT_HALF: output half2 words [NB][H][W][CO/2]; else fp32
template<int CINP, int CING, int HALVES, int CO, int K, int H, int W, int PAD,
         int IN_HALF, int OUT_HALF>
__global__ void __launch_bounds__(256, 1)
mma_conv_kernel(const void* __restrict__ in_, const unsigned* __restrict__ wt,
                const float* __restrict__ bias, void* __restrict__ out_) {
    constexpr int MT   = 4;
    constexpr int NT   = 8;
    constexpr int NTHREADS = 256;
    constexpr int NWARP = 8;
    constexpr int MPIX = NWARP * 16 * MT;      // 512
    constexpr int Wp   = W + 2 * PAD;
    constexpr int Hp   = H + 2 * PAD;
    constexpr int HALO = PAD * Wp + PAD;
    constexpr int AWIN = MPIX + 2 * HALO;
    constexpr int NPIX = Hp * Wp;
    constexpr int KK   = K * K;
    constexpr int AST2 = CINP / 2 + 4;
    constexpr int NC16 = CINP / 16;
    constexpr int CINF = CING * HALVES;
    constexpr int COB  = CO / 64;
    constexpr int BSZ  = NC16 * 512;
    constexpr int CP4  = CINP / 4;
    constexpr int CG4  = CING / 4;
    constexpr int CGW8 = CING / 8;             // uint4 chunks per pixel (half path)

    extern __shared__ uint32_t smem[];
    uint32_t* sA = smem;                       // [AWIN][AST2] half2
    uint32_t* sB = smem + AWIN * AST2;         // [2][BSZ]

    const int n    = blockIdx.z;
    const int cob  = blockIdx.y;
    const int co0  = cob * 64;
    const int p0   = HALO + blockIdx.x * MPIX;
    const int s0   = p0 - HALO;
    const int t    = threadIdx.x;
    const int warp = t >> 5, lane = t & 31;
    const int ar   = lane >> 2;
    const int ac   = lane & 3;
    const int wrow = warp * (16 * MT);

    float d[MT][NT][4];
#pragma unroll
    for (int mt = 0; mt < MT; ++mt)
#pragma unroll
        for (int nt = 0; nt < NT; ++nt)
#pragma unroll
            for (int q = 0; q < 4; ++q) d[mt][nt][q] = 0.f;

#pragma unroll 1
    for (int h = 0; h < HALVES; ++h) {
        // ---- stage A window for this half ----
        if (IN_HALF) {
            const uint4* inb = (const uint4*)((const uint32_t*)in_ +
                               (size_t)n * NPIX * (CINF / 2) + h * (CING / 2));
#pragma unroll 2
            for (int e = t; e < AWIN * CGW8; e += NTHREADS) {
                int pw = e / CGW8, c = e - pw * CGW8;
                int pix = s0 + pw;
                uint4 v = make_uint4(0u, 0u, 0u, 0u);
                if (pix < NPIX)
                    v = inb[(size_t)pix * (CINF / 8) + c];
                uint32_t* dst = sA + pw * AST2 + c * 4;
                dst[0] = v.x; dst[1] = v.y; dst[2] = v.z; dst[3] = v.w;
            }
        } else {
            const float* inb = (const float*)in_ + (size_t)n * NPIX * CINF + h * CING;
#pragma unroll 2
            for (int e = t; e < AWIN * CP4; e += NTHREADS) {
                int pw = e / CP4, c4 = e - pw * CP4;
                int pix = s0 + pw;
                float4 v = make_float4(0.f, 0.f, 0.f, 0.f);
                if (pix < NPIX && c4 < CG4)
                    v = *(const float4*)(inb + (size_t)pix * CINF + c4 * 4);
                sA[pw * AST2 + c4 * 2 + 0] = f2h2(v.x, v.y);
                sA[pw * AST2 + c4 * 2 + 1] = f2h2(v.z, v.w);
            }
        }
        // prefetch B for taps 0 and 1
#pragma unroll 1
        for (int pf = 0; pf < 2; ++pf) {
            const unsigned* src = wt + ((size_t)(pf * COB + cob) * HALVES + h) * BSZ;
            uint32_t* dst = sB + pf * BSZ;
            for (int c = t; c < BSZ / 4; c += NTHREADS)
                cp_async16(dst + c * 4, src + c * 4);
            asm volatile("cp.async.commit_group;" ::: "memory");
        }

#pragma unroll 1
        for (int kk = 0; kk < KK; ++kk) {
            if (kk + 1 < KK) asm volatile("cp.async.wait_group 1;" ::: "memory");
            else             asm volatile("cp.async.wait_group 0;" ::: "memory");
            __syncthreads();

            const uint32_t* sBb = sB + (kk & 1) * BSZ;
            const int abase = HALO + (kk / K - PAD) * Wp + (kk % K - PAD) + wrow;
#pragma unroll
            for (int c16 = 0; c16 < NC16; ++c16) {
                uint2 bf[NT];
                const uint2* bt = (const uint2*)(sBb + c16 * 512);
#pragma unroll
                for (int nt = 0; nt < NT; ++nt)
                    bf[nt] = bt[nt * 32 + ac * 8 + ar];
#pragma unroll
                for (int mt = 0; mt < MT; ++mt) {
                    const uint32_t* ap = sA + (abase + mt * 16 + ar) * AST2 + c16 * 8 + ac;
                    uint32_t af[4];
                    af[0] = ap[0];
                    af[1] = ap[8 * AST2];
                    af[2] = ap[4];
                    af[3] = ap[8 * AST2 + 4];
#pragma unroll
                    for (int nt = 0; nt < NT; ++nt)
                        mma_f16(d[mt][nt], af, (const uint32_t*)&bf[nt]);
                }
            }
            __syncthreads();
            if (kk + 2 < KK) {
                const unsigned* src = wt + ((size_t)((kk + 2) * COB + cob) * HALVES + h) * BSZ;
                uint32_t* dst = sB + (kk & 1) * BSZ;
                for (int c = t; c < BSZ / 4; c += NTHREADS)
                    cp_async16(dst + c * 4, src + c * 4);
                asm volatile("cp.async.commit_group;" ::: "memory");
            }
        }
    }

    // ---- epilogue: bias + relu, store valid pixels ----
    float2 bv[NT];
#pragma unroll
    for (int nt = 0; nt < NT; ++nt)
        bv[nt] = *(const float2*)(bias + co0 + nt * 8 + 2 * ac);

#pragma unroll
    for (int mt = 0; mt < MT; ++mt) {
#pragma unroll
        for (int half = 0; half < 2; ++half) {
            int p = p0 + wrow + mt * 16 + half * 8 + ar;
            int y = p / Wp - PAD, x = p % Wp - PAD;
            if (x >= 0 && x < W && y < H) {
                size_t pixo = ((size_t)n * H + y) * W + x;
                if (OUT_HALF) {
                    uint32_t* ob = (uint32_t*)out_ + pixo * (CO / 2) + co0 / 2 + ac;
#pragma unroll
                    for (int nt = 0; nt < NT; ++nt) {
                        float vx = fmaxf(d[mt][nt][half * 2 + 0] + bv[nt].x, 0.f);
                        float vy = fmaxf(d[mt][nt][half * 2 + 1] + bv[nt].y, 0.f);
                        ob[nt * 4] = f2h2(vx, vy);
                    }
                } else {
                    float* ob = (float*)out_ + pixo * CO + co0 + 2 * ac;
#pragma unroll
                    for (int nt = 0; nt < NT; ++nt) {
                        float2 v;
                        v.x = fmaxf(d[mt][nt][half * 2 + 0] + bv[nt].x, 0.f);
                        v.y = fmaxf(d[mt][nt][half * 2 + 1] + bv[nt].y, 0.f);
                        *(float2*)(ob + nt * 8) = v;
                    }
                }
            }
        }
    }
}

// ---------------- 3x3 s2 max pool, half2 NHWC -> padded half2 NHWC ----------
template<int C, int HI, int HO, int P>
__global__ void pool_half_kernel(const uint2* __restrict__ in, uint2* __restrict__ out) {
    constexpr int C4 = C / 4, HOP = HO + 2 * P;
    int idx = blockIdx.x * blockDim.x + threadIdx.x;
    if (idx >= NB * HO * HO * C4) return;
    int c  = idx % C4;
    int ox = (idx / C4) % HO;
    int oy = (idx / (C4 * HO)) % HO;
    int n  = idx / (C4 * HO * HO);
    const uint2* p = in + (((size_t)n * HI + 2 * oy) * HI + 2 * ox) * C4 + c;
    uint2 m0 = p[0];
    __half2 ma = *(__half2*)&m0.x, mb = *(__half2*)&m0.y;
#pragma unroll
    for (int dy = 0; dy < 3; ++dy)
#pragma unroll
        for (int dx = 0; dx < 3; ++dx) {
            uint2 q = p[((size_t)dy * HI + dx) * C4];
            ma = __hmax2(ma, *(__half2*)&q.x);
            mb = __hmax2(mb, *(__half2*)&q.y);
        }
    uint2 r; r.x = *(uint32_t*)&ma; r.y = *(uint32_t*)&mb;
    out[(((size_t)n * HOP + oy + P) * HOP + ox + P) * C4 + c] = r;
}

// ---------------- 3x3 s2 max pool fp32 (pool3) ----------------
template<int C, int HI, int HO>
__global__ void pool_f32_kernel(const float4* __restrict__ in, float4* __restrict__ out) {
    constexpr int C4 = C / 4;
    int idx = blockIdx.x * blockDim.x + threadIdx.x;
    if (idx >= NB * HO * HO * C4) return;
    int c  = idx % C4;
    int ox = (idx / C4) % HO;
    int oy = (idx / (C4 * HO)) % HO;
    int n  = idx / (C4 * HO * HO);
    const float4* p = in + (((size_t)n * HI + 2 * oy) * HI + 2 * ox) * C4 + c;
    float4 m = p[0];
#pragma unroll
    for (int dy = 0; dy < 3; ++dy)
#pragma unroll
        for (int dx = 0; dx < 3; ++dx) {
            float4 q = p[((size_t)dy * HI + dx) * C4];
            m.x = fmaxf(m.x, q.x); m.y = fmaxf(m.y, q.y);
            m.z = fmaxf(m.z, q.z); m.w = fmaxf(m.w, q.w);
        }
    out[(((size_t)n * HO + oy) * HO + ox) * C4 + c] = m;
}

// ---------------- global average pool over 8x8 (NHWC, float4) ----------------
__global__ void gap_kernel(const float4* __restrict__ in, float4* __restrict__ out) {
    int idx = blockIdx.x * blockDim.x + threadIdx.x;
    if (idx >= NB * 64) return;
    int n = idx >> 6, c = idx & 63;
    const float4* p = in + (size_t)n * 64 * 64 + c;
    float4 s = make_float4(0.f, 0.f, 0.f, 0.f);
#pragma unroll
    for (int i = 0; i < 64; ++i) {
        float4 q = p[i * 64];
        s.x += q.x; s.y += q.y; s.z += q.z; s.w += q.w;
    }
    s.x *= (1.f/64.f); s.y *= (1.f/64.f); s.z *= (1.f/64.f); s.w *= (1.f/64.f);
    out[idx] = s;
}

// ---------------- fully connected ----------------
__global__ void fc_kernel(const float* __restrict__ in, const float* __restrict__ w,
                          const float* __restrict__ b, float* __restrict__ out,
                          int K_, int O_, int relu) {
    int idx = blockIdx.x * blockDim.x + threadIdx.x;
    if (idx >= NB * O_) return;
    int n = idx / O_, o = idx % O_;
    const float4* ip = (const float4*)(in + (size_t)n * K_);
    const float4* wp = (const float4*)(w + (size_t)o * K_);
    float s = b[o];
    int k4 = K_ >> 2;
#pragma unroll 4
    for (int k = 0; k < k4; ++k) {
        float4 a = ip[k], ww = wp[k];
        s = fmaf(a.x, ww.x, s); s = fmaf(a.y, ww.y, s);
        s = fmaf(a.z, ww.z, s); s = fmaf(a.w, ww.w, s);
    }
    if (relu) s = fmaxf(s, 0.f);
    out[idx] = s;
}

// ---------------- launch ----------------
extern "C" void kernel_launch(void* const* d_in, const int* in_sizes, int n_in,
                              void* d_out, int out_size) {
    const int*   X    = (const int*)  d_in[0];
    const int*   rmap = (const int*)  d_in[1];
    const float* emb  = (const float*)d_in[2];
    const float* cw0  = (const float*)d_in[3];
    const float* cb0  = (const float*)d_in[4];
    const float* cw1  = (const float*)d_in[5];
    const float* cb1  = (const float*)d_in[6];
    const float* cw2  = (const float*)d_in[7];
    const float* cb2  = (const float*)d_in[8];
    const float* fw0  = (const float*)d_in[9];
    const float* fb0  = (const float*)d_in[10];
    const float* fw1  = (const float*)d_in[11];
    const float* fb1  = (const float*)d_in[12];
    const float* fw2  = (const float*)d_in[13];
    const float* fb2  = (const float*)d_in[14];
    float* out = (float*)d_out;

    float *grid, *c3, *p3, *gapb, *f1, *f2;
    unsigned *c1, *p1, *c2, *p2, *wt1, *wt2, *wt3;
    cudaGetSymbolAddress((void**)&grid, g_grid);
    cudaGetSymbolAddress((void**)&c1,  g_c1);
    cudaGetSymbolAddress((void**)&p1,  g_p1);
    cudaGetSymbolAddress((void**)&c2,  g_c2);
    cudaGetSymbolAddress((void**)&p2,  g_p2);
    cudaGetSymbolAddress((void**)&c3,  g_c3);
    cudaGetSymbolAddress((void**)&p3,  g_p3);
    cudaGetSymbolAddress((void**)&gapb, g_gap);
    cudaGetSymbolAddress((void**)&f1,  g_f1);
    cudaGetSymbolAddress((void**)&f2,  g_f2);
    cudaGetSymbolAddress((void**)&wt1, g_wt1);
    cudaGetSymbolAddress((void**)&wt2, g_wt2);
    cudaGetSymbolAddress((void**)&wt3, g_wt3);

    // smem sizes (words*4)
    const int SM1 = (820 * 28 + 2 * 3 * 512) * 4;   // 104,128
    const int SM2 = (588 * 36 + 2 * 4 * 512) * 4;   // 101,056
    const int SM3 = (552 * 36 + 2 * 4 * 512) * 4;   //  95,872
    cudaFuncSetAttribute((const void*)mma_conv_kernel<48, 40, 1, 64, 5, 72, 72, 2, 0, 1>,
                         cudaFuncAttributeMaxDynamicSharedMemorySize, SM1);
    cudaFuncSetAttribute((const void*)mma_conv_kernel<64, 64, 1, 128, 3, 35, 35, 1, 1, 1>,
                         cudaFuncAttributeMaxDynamicSharedMemorySize, SM2);
    cudaFuncSetAttribute((const void*)mma_conv_kernel<64, 64, 2, 256, 3, 17, 17, 1, 1, 0>,
                         cudaFuncAttributeMaxDynamicSharedMemorySize, SM3);

    // zero padded buffers (grid fp32; p1/p2 half)
    {
        int n4;
        n4 = NB * 76 * 76 * 40 / 4;      zero_kernel<<<(n4 + 255) / 256, 256>>>((float4*)grid, n4);
        n4 = NB * 37 * 37 * 32 / 4;      zero_kernel<<<(n4 + 255) / 256, 256>>>((float4*)p1, n4);
        n4 = NB * 19 * 19 * 64 / 4;      zero_kernel<<<(n4 + 255) / 256, 256>>>((float4*)p2, n4);
    }
    // weight transforms
    {
        int n1 = 25 * 1 * 1 * 3 * 512; wtrans_kernel<33, 48, 1, 64, 25><<<(n1 + 255) / 256, 256>>>(cw0, wt1);
        int n2 =  9 * 2 * 1 * 4 * 512; wtrans_kernel<64, 64, 1, 128, 9><<<(n2 + 255) / 256, 256>>>(cw1, wt2);
        int n3 =  9 * 4 * 2 * 4 * 512; wtrans_kernel<128, 64, 2, 256, 9><<<(n3 + 255) / 256, 256>>>(cw2, wt3);
    }
    // scatter encode
    {
        int nt = NB * RNUM * 64;
        scatter_kernel<<<(nt + 255) / 256, 256>>>(X, rmap, emb, grid);
    }
    // conv1 + pool1
    mma_conv_kernel<48, 40, 1, 64, 5, 72, 72, 2, 0, 1>
        <<<dim3(11, 1, NB), 256, SM1>>>(grid, wt1, cb0, c1);
    {
        int nt = NB * 35 * 35 * 16;
        pool_half_kernel<64, 72, 35, 1><<<(nt + 255) / 256, 256>>>((const uint2*)c1, (uint2*)p1);
    }
    // conv2 + pool2
    mma_conv_kernel<64, 64, 1, 128, 3, 35, 35, 1, 1, 1>
        <<<dim3(3, 2, NB), 256, SM2>>>(p1, wt2, cb1, c2);
    {
        int nt = NB * 17 * 17 * 32;
        pool_half_kernel<128, 35, 17, 1><<<(nt + 255) / 256, 256>>>((const uint2*)c2, (uint2*)p2);
    }
    // conv3 + pool3
    mma_conv_kernel<64, 64, 2, 256, 3, 17, 17, 1, 1, 0>
        <<<dim3(1, 4, NB), 256, SM3>>>(p2, wt3, cb2, c3);
    {
        int nt = NB * 8 * 8 * 64;
        pool_f32_kernel<256, 17, 8><<<(nt + 255) / 256, 256>>>((const float4*)c3, (float4*)p3);
    }
    // GAP + FC stack
    gap_kernel<<<(NB * 64 + 255) / 256, 256>>>((const float4*)p3, (float4*)gapb);
    fc_kernel<<<(NB * 512 + 255) / 256, 256>>>(gapb, fw0, fb0, f1, 256, 512, 1);
    fc_kernel<<<(NB * 256 + 255) / 256, 256>>>(f1,   fw1, fb1, f2, 512, 256, 1);
    fc_kernel<<<(NB * 512 + 255) / 256, 256>>>(f2,   fw2, fb2, out, 256, 512, 0);
}

// round 7
// speedup vs baseline: 5.8760x; 1.1499x over previous
#include <cuda_runtime.h>
#include <cuda_fp16.h>
#include <stdint.h>

// ---------------- problem constants ----------------
#define NB   128
#define RNUM 300
#define EMB  32

// ---------------- buffers ----------------
__device__ float    g_grid[NB * 76 * 76 * 40];   // conv1 input fp32 (pad2, 40ch: 33 real)
__device__ unsigned g_c1 [NB * 72 * 72 * 32];    // conv1 out half2 (64ch)
__device__ unsigned g_p1 [NB * 37 * 37 * 32];    // pool1 half2 (pad1)
__device__ unsigned g_c2 [NB * 35 * 35 * 64];    // conv2 out half2 (128ch)
__device__ unsigned g_p2 [NB * 19 * 19 * 64];    // pool2 half2 (pad1)
__device__ float    g_c3 [NB * 17 * 17 * 256];   // conv3 out fp32
__device__ float    g_p3 [NB * 8 * 8 * 256];
__device__ float    g_gap[NB * 256];
__device__ float    g_f1 [NB * 512];
__device__ float    g_f2 [NB * 256];
// B fragment images: [cob][tap][c16][nt][lane][2]  (uint32 = half2)
__device__ unsigned g_wt1[ 38400];               // 1 * 25 * 3 * 8  * 64
__device__ unsigned g_wt2[ 36864];               // 4 *  9 * 4 * 4  * 64
__device__ unsigned g_wt3[147456];               // 8 * 18 * 4 * 4  * 64

// ---------------- helpers ----------------
__device__ __forceinline__ void mma_f16(float* d, const uint32_t* a, const uint32_t* b) {
    asm volatile(
        "mma.sync.aligned.m16n8k16.row.col.f32.f16.f16.f32 "
        "{%0,%1,%2,%3}, {%4,%5,%6,%7}, {%8,%9}, {%0,%1,%2,%3};"
        : "+f"(d[0]), "+f"(d[1]), "+f"(d[2]), "+f"(d[3])
        : "r"(a[0]), "r"(a[1]), "r"(a[2]), "r"(a[3]), "r"(b[0]), "r"(b[1]));
}
__device__ __forceinline__ void ldsm_x4(uint32_t* a, uint32_t addr) {
    asm volatile("ldmatrix.sync.aligned.m8n8.x4.shared.b16 {%0,%1,%2,%3}, [%4];"
        : "=r"(a[0]), "=r"(a[1]), "=r"(a[2]), "=r"(a[3]) : "r"(addr));
}
__device__ __forceinline__ uint32_t smem_u32(const void* p) {
    uint32_t a;
    asm("{ .reg .u64 t; cvta.to.shared.u64 t, %1; cvt.u32.u64 %0, t; }" : "=r"(a) : "l"(p));
    return a;
}
__device__ __forceinline__ void cp_async16_s(uint32_t saddr, const void* g) {
    asm volatile("cp.async.cg.shared.global [%0], [%1], 16;" :: "r"(saddr), "l"(g));
}
__device__ __forceinline__ uint32_t f2h2(float a, float b) {
    __half2 h = __float22half2_rn(make_float2(a, b));
    return *(uint32_t*)&h;
}

// ---------------- zero fill ----------------
__global__ void zero_kernel(float4* __restrict__ p, int n4) {
    int i = blockIdx.x * blockDim.x + threadIdx.x;
    if (i < n4) p[i] = make_float4(0.f, 0.f, 0.f, 0.f);
}

// ---------------- scatter rooms into padded NHWC grid ----------------
__global__ void scatter_kernel(const int* __restrict__ X,
                               const int* __restrict__ rm,
                               const float* __restrict__ emb,
                               float* __restrict__ grid) {
    int idx = blockIdx.x * blockDim.x + threadIdx.x;
    if (idx >= NB * RNUM * 64) return;
    int cell = idx & 63;
    int r    = (idx >> 6) % RNUM;
    int n    = idx / (RNUM * 64);
    if (!rm[r * 64 + cell]) return;
    int cx = cell >> 3, cy = cell & 7;
    int px = X[(n * RNUM + r) * 2 + 0];
    int py = X[(n * RNUM + r) * 2 + 1];
    int Y = py + cy + 2, Xc = px + cx + 2;
    float* base = grid + (((size_t)n * 76 + Y) * 76 + Xc) * 40;
    atomicAdd(base, 1.0f);
    const float* er = emb + r * EMB;
#pragma unroll
    for (int e = 0; e < EMB; ++e)
        atomicAdd(base + 1 + e, er[e]);
}

// ------- weight transform: OIHW -> resident B fragment images ---------------
// word w: [cob][tap][c16][nt][lane][which]; ac=lane&3, ar=lane>>2
//   k_local = c16*16 + ac*2 + which*8 ; ci = (tap/KK)*CINH + k_local
//   co = cob*NCO + nt*8 + ar ; word = half2(w[ci], w[ci+1])
template<int CI, int CINH, int HALVES, int NCO, int COB, int KK>
__global__ void wtrans_kernel(const float* __restrict__ w, unsigned* __restrict__ wt) {
    constexpr int NT = NCO / 8, NC16 = CINH / 16, TAPS = KK * HALVES;
    int i = blockIdx.x * blockDim.x + threadIdx.x;
    if (i >= COB * TAPS * NC16 * NT * 64) return;
    int which = i & 1;
    int lane  = (i >> 1) & 31;
    int r1    = i >> 6;
    int nt    = r1 % NT;  r1 /= NT;
    int c16   = r1 % NC16; r1 /= NC16;
    int tap   = r1 % TAPS;
    int cob   = r1 / TAPS;
    int ac = lane & 3, ar = lane >> 2;
    int k_local = c16 * 16 + ac * 2 + which * 8;
    int h  = tap / KK, kk = tap % KK;
    int ci0 = h * CINH + k_local;
    int co  = cob * NCO + nt * 8 + ar;
    float v0 = (ci0     < CI) ? w[((size_t)co * CI + ci0)     * KK + kk] : 0.f;
    float v1 = (ci0 + 1 < CI) ? w[((size_t)co * CI + ci0 + 1) * KK + kk] : 0.f;
    wt[i] = f2h2(v0, v1);
}

// ---------------- fp16 mma.sync conv: B resident, zero-sync main loop -------
// A: [HALVES][AWIN rows][AST2 half2 words]; per-tap shift = row offset.
template<int CINH, int HALVES, int NCO, int MT, int K, int H, int W, int PAD,
         int IN_MODE, int OUT_HALF, int CO_TOTAL>
__global__ void __launch_bounds__(256, 2)
hmma_conv_kernel(const void* __restrict__ in_, const unsigned* __restrict__ wt,
                 const float* __restrict__ bias, void* __restrict__ out_) {
    constexpr int NT    = NCO / 8;
    constexpr int NC16  = CINH / 16;
    constexpr int KK    = K * K;
    constexpr int TAPS  = KK * HALVES;
    constexpr int MPIX  = 8 * 16 * MT;
    constexpr int Wp    = W + 2 * PAD, Hp = H + 2 * PAD;
    constexpr int NPIX  = Wp * Hp;
    constexpr int HALO  = PAD * Wp + PAD;
    constexpr int AWIN  = MPIX + 2 * HALO;
    constexpr int AST2  = CINH / 2 + 4;          // words; LDSM conflict-free
    constexpr int AWORDS = HALVES * AWIN * AST2;
    constexpr int BWORDS = TAPS * NC16 * NT * 64;
    constexpr int CINF   = 64 * HALVES;          // half input channel count

    extern __shared__ uint32_t sm[];
    uint32_t* sA = sm;
    uint32_t* sB = sm + AWORDS;

    const int tid  = threadIdx.x;
    const int warp = tid >> 5, lane = tid & 31;
    const int ar   = lane >> 2, ac = lane & 3;
    const int n    = blockIdx.z;
    const int cob  = blockIdx.y;
    const int co0  = cob * NCO;
    const int p0   = HALO + blockIdx.x * MPIX;
    const int s0   = p0 - HALO;
    const int wrow = warp * (16 * MT);

    // ---- stage B (all taps) via cp.async ----
    {
        const unsigned* wsrc = wt + (size_t)cob * BWORDS;
        uint32_t sBu = smem_u32(sB);
        for (int c = tid; c < BWORDS / 4; c += 256)
            cp_async16_s(sBu + c * 16, wsrc + c * 4);
        asm volatile("cp.async.commit_group;" ::: "memory");
    }
    // ---- stage A window(s) ----
    if (IN_MODE == 0) {
        const float* inb = (const float*)in_ + (size_t)n * NPIX * 40;
        for (int e = tid; e < AWIN * 6; e += 256) {
            int row = e / 6, c = e % 6;
            int pix = s0 + row;
            uint4 v = make_uint4(0u, 0u, 0u, 0u);
            if (pix < NPIX && c < 5) {
                const float4* g = (const float4*)(inb + (size_t)pix * 40 + c * 8);
                float4 a = g[0], b = g[1];
                v.x = f2h2(a.x, a.y); v.y = f2h2(a.z, a.w);
                v.z = f2h2(b.x, b.y); v.w = f2h2(b.z, b.w);
            }
            *(uint4*)(sA + row * AST2 + c * 4) = v;
        }
    } else {
        const uint4* inb = (const uint4*)in_ + (size_t)n * NPIX * (CINF / 8);
        for (int e = tid; e < HALVES * AWIN * 8; e += 256) {
            int h = e / (AWIN * 8);
            int r2 = e % (AWIN * 8);
            int row = r2 >> 3, c = r2 & 7;
            int pix = s0 + row;
            uint4 v = make_uint4(0u, 0u, 0u, 0u);
            if (pix < NPIX)
                v = inb[(size_t)pix * (CINF / 8) + h * 8 + c];
            *(uint4*)(sA + (h * AWIN + row) * AST2 + c * 4) = v;
        }
    }
    asm volatile("cp.async.wait_group 0;" ::: "memory");
    __syncthreads();

    // ---- accumulators ----
    float d[MT][NT][4];
#pragma unroll
    for (int mt = 0; mt < MT; ++mt)
#pragma unroll
        for (int nt = 0; nt < NT; ++nt)
#pragma unroll
            for (int q = 0; q < 4; ++q) d[mt][nt][q] = 0.f;

    // per-thread LDSM base: row = lane&15, khalf = (lane>>4)*8 halves (=4 words)
    const uint32_t sAu = smem_u32(sA);
    const uint32_t a_off0 = sAu +
        (uint32_t)(((HALO + wrow + (lane & 15)) * AST2 + ((lane >> 4) << 2)) * 4);

    // ---- main loop: NO barriers ----
    for (int tap = 0; tap < TAPS; ++tap) {
        int h  = (HALVES == 2) ? (tap / KK) : 0;
        int kt = (HALVES == 2) ? (tap % KK) : tap;
        int shift = (kt / K - PAD) * Wp + (kt % K) - PAD;
        uint32_t abase = a_off0 + (uint32_t)((h * AWIN + shift) * (AST2 * 4));
        const uint2* btap = (const uint2*)sB + (size_t)tap * (NC16 * NT * 32) + lane;
#pragma unroll
        for (int c16 = 0; c16 < NC16; ++c16) {
            uint2 bf[NT];
#pragma unroll
            for (int nt = 0; nt < NT; ++nt)
                bf[nt] = btap[(c16 * NT + nt) * 32];
#pragma unroll
            for (int mt = 0; mt < MT; ++mt) {
                uint32_t af[4];
                ldsm_x4(af, abase + (uint32_t)((mt * 16 * AST2 + c16 * 8) * 4));
#pragma unroll
                for (int nt = 0; nt < NT; ++nt)
                    mma_f16(d[mt][nt], af, (const uint32_t*)&bf[nt]);
            }
        }
    }

    // ---- epilogue: bias + relu ----
    float2 bv[NT];
#pragma unroll
    for (int nt = 0; nt < NT; ++nt)
        bv[nt] = *(const float2*)(bias + co0 + nt * 8 + 2 * ac);

#pragma unroll
    for (int mt = 0; mt < MT; ++mt) {
#pragma unroll
        for (int half = 0; half < 2; ++half) {
            int p = p0 + wrow + mt * 16 + half * 8 + ar;
            int y = p / Wp - PAD, x = p % Wp - PAD;
            if (x >= 0 && x < W && y < H) {
                size_t pix = ((size_t)n * H + y) * W + x;
                if (OUT_HALF) {
                    uint32_t* ob = (uint32_t*)out_ + pix * (CO_TOTAL / 2) + co0 / 2 + ac;
#pragma unroll
                    for (int nt = 0; nt < NT; ++nt) {
                        float vx = fmaxf(d[mt][nt][half * 2 + 0] + bv[nt].x, 0.f);
                        float vy = fmaxf(d[mt][nt][half * 2 + 1] + bv[nt].y, 0.f);
                        ob[nt * 4] = f2h2(vx, vy);
                    }
                } else {
                    float* ob = (float*)out_ + pix * CO_TOTAL + co0 + 2 * ac;
#pragma unroll
                    for (int nt = 0; nt < NT; ++nt) {
                        float2 v;
                        v.x = fmaxf(d[mt][nt][half * 2 + 0] + bv[nt].x, 0.f);
                        v.y = fmaxf(d[mt][nt][half * 2 + 1] + bv[nt].y, 0.f);
                        *(float2*)(ob + nt * 8) = v;
                    }
                }
            }
        }
    }
}

// ---------------- pools / gap / fc ----------------
template<int C, int HI, int HO, int P>
__global__ void pool_half_kernel(const uint2* __restrict__ in, uint2* __restrict__ out) {
    constexpr int C4 = C / 4, HOP = HO + 2 * P;
    int idx = blockIdx.x * blockDim.x + threadIdx.x;
    if (idx >= NB * HO * HO * C4) return;
    int c  = idx % C4;
    int ox = (idx / C4) % HO;
    int oy = (idx / (C4 * HO)) % HO;
    int n  = idx / (C4 * HO * HO);
    const uint2* p = in + (((size_t)n * HI + 2 * oy) * HI + 2 * ox) * C4 + c;
    uint2 m0 = p[0];
    __half2 ma = *(__half2*)&m0.x, mb = *(__half2*)&m0.y;
#pragma unroll
    for (int dy = 0; dy < 3; ++dy)
#pragma unroll
        for (int dx = 0; dx < 3; ++dx) {
            uint2 q = p[((size_t)dy * HI + dx) * C4];
            ma = __hmax2(ma, *(__half2*)&q.x);
            mb = __hmax2(mb, *(__half2*)&q.y);
        }
    uint2 r; r.x = *(uint32_t*)&ma; r.y = *(uint32_t*)&mb;
    out[(((size_t)n * HOP + oy + P) * HOP + ox + P) * C4 + c] = r;
}

template<int C, int HI, int HO>
__global__ void pool_f32_kernel(const float4* __restrict__ in, float4* __restrict__ out) {
    constexpr int C4 = C / 4;
    int idx = blockIdx.x * blockDim.x + threadIdx.x;
    if (idx >= NB * HO * HO * C4) return;
    int c  = idx % C4;
    int ox = (idx / C4) % HO;
    int oy = (idx / (C4 * HO)) % HO;
    int n  = idx / (C4 * HO * HO);
    const float4* p = in + (((size_t)n * HI + 2 * oy) * HI + 2 * ox) * C4 + c;
    float4 m = p[0];
#pragma unroll
    for (int dy = 0; dy < 3; ++dy)
#pragma unroll
        for (int dx = 0; dx < 3; ++dx) {
            float4 q = p[((size_t)dy * HI + dx) * C4];
            m.x = fmaxf(m.x, q.x); m.y = fmaxf(m.y, q.y);
            m.z = fmaxf(m.z, q.z); m.w = fmaxf(m.w, q.w);
        }
    out[(((size_t)n * HO + oy) * HO + ox) * C4 + c] = m;
}

__global__ void gap_kernel(const float4* __restrict__ in, float4* __restrict__ out) {
    int idx = blockIdx.x * blockDim.x + threadIdx.x;
    if (idx >= NB * 64) return;
    int n = idx >> 6, c = idx & 63;
    const float4* p = in + (size_t)n * 64 * 64 + c;
    float4 s = make_float4(0.f, 0.f, 0.f, 0.f);
#pragma unroll
    for (int i = 0; i < 64; ++i) {
        float4 q = p[i * 64];
        s.x += q.x; s.y += q.y; s.z += q.z; s.w += q.w;
    }
    s.x *= (1.f/64.f); s.y *= (1.f/64.f); s.z *= (1.f/64.f); s.w *= (1.f/64.f);
    out[idx] = s;
}

__global__ void fc_kernel(const float* __restrict__ in, const float* __restrict__ w,
                          const float* __restrict__ b, float* __restrict__ out,
                          int K_, int O_, int relu) {
    int idx = blockIdx.x * blockDim.x + threadIdx.x;
    if (idx >= NB * O_) return;
    int n = idx / O_, o = idx % O_;
    const float4* ip = (const float4*)(in + (size_t)n * K_);
    const float4* wp = (const float4*)(w + (size_t)o * K_);
    float s = b[o];
    int k4 = K_ >> 2;
#pragma unroll 4
    for (int k = 0; k < k4; ++k) {
        float4 a = ip[k], ww = wp[k];
        s = fmaf(a.x, ww.x, s); s = fmaf(a.y, ww.y, s);
        s = fmaf(a.z, ww.z, s); s = fmaf(a.w, ww.w, s);
    }
    if (relu) s = fmaxf(s, 0.f);
    out[idx] = s;
}

// ---------------- launch ----------------
extern "C" void kernel_launch(void* const* d_in, const int* in_sizes, int n_in,
                              void* d_out, int out_size) {
    const int*   X    = (const int*)  d_in[0];
    const int*   rmap = (const int*)  d_in[1];
    const float* emb  = (const float*)d_in[2];
    const float* cw0  = (const float*)d_in[3];
    const float* cb0  = (const float*)d_in[4];
    const float* cw1  = (const float*)d_in[5];
    const float* cb1  = (const float*)d_in[6];
    const float* cw2  = (const float*)d_in[7];
    const float* cb2  = (const float*)d_in[8];
    const float* fw0  = (const float*)d_in[9];
    const float* fb0  = (const float*)d_in[10];
    const float* fw1  = (const float*)d_in[11];
    const float* fb1  = (const float*)d_in[12];
    const float* fw2  = (const float*)d_in[13];
    const float* fb2  = (const float*)d_in[14];
    float* out = (float*)d_out;

    float *grid, *c3, *p3, *gapb, *f1, *f2;
    unsigned *c1, *p1, *c2, *p2, *wt1, *wt2, *wt3;
    cudaGetSymbolAddress((void**)&grid, g_grid);
    cudaGetSymbolAddress((void**)&c1,  g_c1);
    cudaGetSymbolAddress((void**)&p1,  g_p1);
    cudaGetSymbolAddress((void**)&c2,  g_c2);
    cudaGetSymbolAddress((void**)&p2,  g_p2);
    cudaGetSymbolAddress((void**)&c3,  g_c3);
    cudaGetSymbolAddress((void**)&p3,  g_p3);
    cudaGetSymbolAddress((void**)&gapb, g_gap);
    cudaGetSymbolAddress((void**)&f1,  g_f1);
    cudaGetSymbolAddress((void**)&f2,  g_f2);
    cudaGetSymbolAddress((void**)&wt1, g_wt1);
    cudaGetSymbolAddress((void**)&wt2, g_wt2);
    cudaGetSymbolAddress((void**)&wt3, g_wt3);

    // smem: A words + B words, *4 bytes
    // conv1: (564*28 + 38400)*4            = 216,768
    // conv2: (460*36 + 9216)*4             = 103,104  (2 blocks/SM)
    // conv3: (2*424*36 + 18432)*4          = 195,840
    const int SM1 = (564 * 28 + 38400) * 4;
    const int SM2 = (460 * 36 +  9216) * 4;
    const int SM3 = (2 * 424 * 36 + 18432) * 4;
    cudaFuncSetAttribute((const void*)hmma_conv_kernel<48, 1, 64, 2, 5, 72, 72, 2, 0, 1, 64>,
                         cudaFuncAttributeMaxDynamicSharedMemorySize, SM1);
    cudaFuncSetAttribute((const void*)hmma_conv_kernel<64, 1, 32, 3, 3, 35, 35, 1, 1, 1, 128>,
                         cudaFuncAttributeMaxDynamicSharedMemorySize, SM2);
    cudaFuncSetAttribute((const void*)hmma_conv_kernel<64, 2, 32, 3, 3, 17, 17, 1, 1, 0, 256>,
                         cudaFuncAttributeMaxDynamicSharedMemorySize, SM3);

    // zero padded buffers
    {
        int n4;
        n4 = NB * 76 * 76 * 40 / 4; zero_kernel<<<(n4 + 255) / 256, 256>>>((float4*)grid, n4);
        n4 = NB * 37 * 37 * 32 / 4; zero_kernel<<<(n4 + 255) / 256, 256>>>((float4*)p1, n4);
        n4 = NB * 19 * 19 * 64 / 4; zero_kernel<<<(n4 + 255) / 256, 256>>>((float4*)p2, n4);
    }
    // weight transforms
    {
        int n1 = 38400;  wtrans_kernel<33, 48, 1, 64, 1, 25><<<(n1 + 255) / 256, 256>>>(cw0, wt1);
        int n2 = 36864;  wtrans_kernel<64, 64, 1, 32, 4, 9><<<(n2 + 255) / 256, 256>>>(cw1, wt2);
        int n3 = 147456; wtrans_kernel<128, 64, 2, 32, 8, 9><<<(n3 + 255) / 256, 256>>>(cw2, wt3);
    }
    // scatter encode
    {
        int nt = NB * RNUM * 64;
        scatter_kernel<<<(nt + 255) / 256, 256>>>(X, rmap, emb, grid);
    }
    // conv1 + pool1
    hmma_conv_kernel<48, 1, 64, 2, 5, 72, 72, 2, 0, 1, 64>
        <<<dim3(22, 1, NB), 256, SM1>>>(grid, wt1, cb0, c1);
    {
        int nt = NB * 35 * 35 * 16;
        pool_half_kernel<64, 72, 35, 1><<<(nt + 255) / 256, 256>>>((const uint2*)c1, (uint2*)p1);
    }
    // conv2 + pool2
    hmma_conv_kernel<64, 1, 32, 3, 3, 35, 35, 1, 1, 1, 128>
        <<<dim3(4, 4, NB), 256, SM2>>>(p1, wt2, cb1, c2);
    {
        int nt = NB * 17 * 17 * 32;
        pool_half_kernel<128, 35, 17, 1><<<(nt + 255) / 256, 256>>>((const uint2*)c2, (uint2*)p2);
    }
    // conv3 + pool3
    hmma_conv_kernel<64, 2, 32, 3, 3, 17, 17, 1, 1, 0, 256>
        <<<dim3(1, 8, NB), 256, SM3>>>(p2, wt3, cb2, c3);
    {
        int nt = NB * 8 * 8 * 64;
        pool_f32_kernel<256, 17, 8><<<(nt + 255) / 256, 256>>>((const float4*)c3, (float4*)p3);
    }
    // GAP + FC stack
    gap_kernel<<<(NB * 64 + 255) / 256, 256>>>((const float4*)p3, (float4*)gapb);
    fc_kernel<<<(NB * 512 + 255) / 256, 256>>>(gapb, fw0, fb0, f1, 256, 512, 1);
    fc_kernel<<<(NB * 256 + 255) / 256, 256>>>(f1,   fw1, fb1, f2, 512, 256, 1);
    fc_kernel<<<(NB * 512 + 255) / 256, 256>>>(f2,   fw2, fb2, out, 256, 512, 0);
}

// round 8
// speedup vs baseline: 6.9251x; 1.1785x over previous
#include <cuda_runtime.h>
#include <cuda_fp16.h>
#include <stdint.h>

// ---------------- problem constants ----------------
#define NB   128
#define RNUM 300
#define EMB  32

// ---------------- buffers ----------------
// grid: half NHWC [n][76][76][40]: ch0-31 = emb, ch32 = occupancy, 33-39 pad
__device__ unsigned g_grid[NB * 76 * 76 * 20];   // half2 words
__device__ unsigned g_c1 [NB * 72 * 72 * 32];    // conv1 out half2 (64ch)
__device__ unsigned g_p1 [NB * 37 * 37 * 32];    // pool1 half2 (pad1)
__device__ unsigned g_c2 [NB * 35 * 35 * 64];    // conv2 out half2 (128ch)
__device__ unsigned g_p2 [NB * 19 * 19 * 64];    // pool2 half2 (pad1)
__device__ float    g_c3 [NB * 17 * 17 * 256];   // conv3 out fp32
__device__ float    g_p3 [NB * 8 * 8 * 256];
__device__ float    g_gap[NB * 256];
__device__ float    g_f1 [NB * 512];
__device__ float    g_f2 [NB * 256];
// conv1 B: emb region 25*2*8*64 + occ region 2*8*64
__device__ unsigned g_wt1[ 26624];
__device__ unsigned g_wt2[ 36864];               // 4 * 9 * 4 * 4 * 64
__device__ unsigned g_wt3[147456];               // 8 * 18 * 4 * 4 * 64

// ---------------- helpers ----------------
__device__ __forceinline__ void mma_f16(float* d, const uint32_t* a, const uint32_t* b) {
    asm volatile(
        "mma.sync.aligned.m16n8k16.row.col.f32.f16.f16.f32 "
        "{%0,%1,%2,%3}, {%4,%5,%6,%7}, {%8,%9}, {%0,%1,%2,%3};"
        : "+f"(d[0]), "+f"(d[1]), "+f"(d[2]), "+f"(d[3])
        : "r"(a[0]), "r"(a[1]), "r"(a[2]), "r"(a[3]), "r"(b[0]), "r"(b[1]));
}
__device__ __forceinline__ void ldsm_x4(uint32_t* a, uint32_t addr) {
    asm volatile("ldmatrix.sync.aligned.m8n8.x4.shared.b16 {%0,%1,%2,%3}, [%4];"
        : "=r"(a[0]), "=r"(a[1]), "=r"(a[2]), "=r"(a[3]) : "r"(addr));
}
__device__ __forceinline__ uint32_t smem_u32(const void* p) {
    uint32_t a;
    asm("{ .reg .u64 t; cvta.to.shared.u64 t, %1; cvt.u32.u64 %0, t; }" : "=r"(a) : "l"(p));
    return a;
}
__device__ __forceinline__ void cp_async16_s(uint32_t saddr, const void* g) {
    asm volatile("cp.async.cg.shared.global [%0], [%1], 16;" :: "r"(saddr), "l"(g));
}
__device__ __forceinline__ uint32_t f2h2(float a, float b) {
    __half2 h = __float22half2_rn(make_float2(a, b));
    return *(uint32_t*)&h;
}

// ---------------- zero fill ----------------
__global__ void zero_kernel(float4* __restrict__ p, int n4) {
    int i = blockIdx.x * blockDim.x + threadIdx.x;
    if (i < n4) p[i] = make_float4(0.f, 0.f, 0.f, 0.f);
}

// ---------------- scatter rooms into half grid (half2 atomics) --------------
__global__ void scatter_kernel(const int* __restrict__ X,
                               const int* __restrict__ rm,
                               const float* __restrict__ emb,
                               __half2* __restrict__ grid) {
    int idx = blockIdx.x * blockDim.x + threadIdx.x;
    if (idx >= NB * RNUM * 64) return;
    int cell = idx & 63;
    int r    = (idx >> 6) % RNUM;
    int n    = idx / (RNUM * 64);
    if (!rm[r * 64 + cell]) return;
    int cx = cell >> 3, cy = cell & 7;
    int px = X[(n * RNUM + r) * 2 + 0];
    int py = X[(n * RNUM + r) * 2 + 1];
    int Y = py + cy + 2, Xc = px + cx + 2;
    __half2* base = grid + (((size_t)n * 76 + Y) * 76 + Xc) * 20;
    const float* er = emb + r * EMB;
#pragma unroll
    for (int w = 0; w < 16; ++w)
        atomicAdd(base + w, __float22half2_rn(make_float2(er[2 * w], er[2 * w + 1])));
    atomicAdd(base + 16, __float22half2_rn(make_float2(1.f, 0.f)));   // occupancy ch32
}

// ------- conv1 weight transform: emb (ci 1..32) + occ (ci 0) im2col regions -
__global__ void wtrans1_kernel(const float* __restrict__ w, unsigned* __restrict__ wt) {
    // emb region: [tap(25)][c16(2)][nt(8)][lane][2] -> 25600 words
    // occ region: [g(2)][nt(8)][lane][2]            ->  1024 words
    int i = blockIdx.x * blockDim.x + threadIdx.x;
    if (i >= 26624) return;
    int which = i & 1;
    int lane  = (i >> 1) & 31;
    int r1    = i >> 6;
    int ac = lane & 3, ar = lane >> 2;
    if (i < 25600) {
        int nt  = r1 % 8;  r1 /= 8;
        int c16 = r1 % 2;
        int tap = r1 / 2;
        int kl  = c16 * 16 + ac * 2 + which * 8;       // 0..31
        int co  = nt * 8 + ar;
        float v0 = w[((size_t)co * 33 + 1 + kl) * 25 + tap];
        float v1 = w[((size_t)co * 33 + 2 + kl) * 25 + tap];
        wt[i] = f2h2(v0, v1);
    } else {
        int j  = i - 25600;
        int r2 = j >> 6;
        int nt = r2 % 8;
        int g  = r2 / 8;
        int kl = g * 16 + ac * 2 + which * 8;          // tap index
        int co = nt * 8 + ar;
        float v0 = (kl     < 25) ? w[((size_t)co * 33 + 0) * 25 + kl]     : 0.f;
        float v1 = (kl + 1 < 25) ? w[((size_t)co * 33 + 0) * 25 + kl + 1] : 0.f;
        wt[i] = f2h2(v0, v1);
    }
}

// ------- generic weight transform (conv2/conv3) ------------------------------
template<int CI, int CINH, int HALVES, int NCO, int COB, int KK>
__global__ void wtrans_kernel(const float* __restrict__ w, unsigned* __restrict__ wt) {
    constexpr int NT = NCO / 8, NC16 = CINH / 16, TAPS = KK * HALVES;
    int i = blockIdx.x * blockDim.x + threadIdx.x;
    if (i >= COB * TAPS * NC16 * NT * 64) return;
    int which = i & 1;
    int lane  = (i >> 1) & 31;
    int r1    = i >> 6;
    int nt    = r1 % NT;  r1 /= NT;
    int c16   = r1 % NC16; r1 /= NC16;
    int tap   = r1 % TAPS;
    int cob   = r1 / TAPS;
    int ac = lane & 3, ar = lane >> 2;
    int k_local = c16 * 16 + ac * 2 + which * 8;
    int h  = tap / KK, kk = tap % KK;
    int ci0 = h * CINH + k_local;
    int co  = cob * NCO + nt * 8 + ar;
    float v0 = (ci0     < CI) ? w[((size_t)co * CI + ci0)     * KK + kk] : 0.f;
    float v1 = (ci0 + 1 < CI) ? w[((size_t)co * CI + ci0 + 1) * KK + kk] : 0.f;
    wt[i] = f2h2(v0, v1);
}

// ---------------- conv1: emb k16x2 per tap + occ im2col (2 groups total) ----
// grid: half [pix][20 words]; out: half2 NHWC 64ch
__global__ void __launch_bounds__(256, 1)
conv1_kernel(const unsigned* __restrict__ in, const unsigned* __restrict__ wt,
             const float* __restrict__ bias, unsigned* __restrict__ out) {
    constexpr int MT = 2, NT = 8;
    constexpr int MPIX = 256;
    constexpr int W = 72, PAD = 2, Wp = 76, NPIX = 76 * 76;
    constexpr int HALO = PAD * Wp + PAD;              // 154
    constexpr int AWIN = MPIX + 2 * HALO;             // 564
    constexpr int ASTE = 20;                          // emb row: 16 words + 4 pad
    constexpr int ASTI = 20;                          // im2col row: 16 words + 4 pad
    constexpr int AEW  = AWIN * ASTE;                 // 11280
    constexpr int IMW  = MPIX * ASTI;                 // 5120
    constexpr int OCW  = 288;                         // occ_raw: 564 halves, padded
    constexpr int BW   = 26624;

    extern __shared__ uint32_t sm[];
    uint32_t* sAe = sm;                               // emb window
    uint32_t* sIm = sm + AEW;                         // occ im2col
    __half*   sOc = (__half*)(sm + AEW + IMW);        // occ raw
    uint32_t* sB  = sm + AEW + IMW + OCW;

    const int tid  = threadIdx.x;
    const int warp = tid >> 5, lane = tid & 31;
    const int ar   = lane >> 2, ac = lane & 3;
    const int n    = blockIdx.z;
    const int p0   = HALO + blockIdx.x * MPIX;
    const int s0   = p0 - HALO;
    const int wrow = warp * (16 * MT);

    // ---- B via cp.async ----
    {
        uint32_t sBu = smem_u32(sB);
        for (int c = tid; c < BW / 4; c += 256)
            cp_async16_s(sBu + c * 16, wt + c * 4);
        asm volatile("cp.async.commit_group;" ::: "memory");
    }
    // ---- stage emb window (16 words/row) + occ raw ----
    {
        const uint4* inb = (const uint4*)(in + (size_t)n * NPIX * 20);
        for (int e = tid; e < AWIN * 4; e += 256) {
            int row = e >> 2, c = e & 3;
            int pix = s0 + row;
            uint4 v = make_uint4(0u, 0u, 0u, 0u);
            if (pix < NPIX) v = inb[(size_t)pix * 5 + c];
            *(uint4*)(sAe + row * ASTE + c * 4) = v;
        }
        const __half* inh = (const __half*)in + (size_t)n * NPIX * 40;
        for (int row = tid; row < AWIN; row += 256) {
            int pix = s0 + row;
            sOc[row] = (pix < NPIX) ? inh[(size_t)pix * 40 + 32] : __float2half(0.f);
        }
    }
    __syncthreads();
    // ---- build occ im2col: row rr (pixel p0+rr), cols k=0..24 = occ(window) ----
    {
        __half* imh = (__half*)sIm;
        for (int e = tid; e < MPIX * 16; e += 256) {
            int rr = e >> 4, w2 = e & 15;
            int k0 = 2 * w2, k1 = 2 * w2 + 1;
            __half h0 = __float2half(0.f), h1 = h0;
            if (k0 < 25) {
                int sh = (k0 / 5 - 2) * Wp + (k0 % 5) - 2;
                h0 = sOc[rr + HALO + sh];
            }
            if (k1 < 25) {
                int sh = (k1 / 5 - 2) * Wp + (k1 % 5) - 2;
                h1 = sOc[rr + HALO + sh];
            }
            imh[(rr * ASTI) * 2 + 2 * w2]     = h0;
            imh[(rr * ASTI) * 2 + 2 * w2 + 1] = h1;
        }
    }
    asm volatile("cp.async.wait_group 0;" ::: "memory");
    __syncthreads();

    float d[MT][NT][4];
#pragma unroll
    for (int mt = 0; mt < MT; ++mt)
#pragma unroll
        for (int nt = 0; nt < NT; ++nt)
#pragma unroll
            for (int q = 0; q < 4; ++q) d[mt][nt][q] = 0.f;

    const uint32_t a_off0 = smem_u32(sAe) +
        (uint32_t)(((HALO + wrow + (lane & 15)) * ASTE + ((lane >> 4) << 2)) * 4);
    const uint32_t i_off0 = smem_u32(sIm) +
        (uint32_t)(((wrow + (lane & 15)) * ASTI + ((lane >> 4) << 2)) * 4);

    // ---- emb taps: 25 x 2 groups ----
    for (int tap = 0; tap < 25; ++tap) {
        int shift = (tap / 5 - PAD) * Wp + (tap % 5) - PAD;
        uint32_t abase = a_off0 + (uint32_t)(shift * (ASTE * 4));
        const uint2* btap = (const uint2*)sB + (size_t)tap * (2 * NT * 32) + lane;
#pragma unroll
        for (int c16 = 0; c16 < 2; ++c16) {
            uint2 bf[NT];
#pragma unroll
            for (int nt = 0; nt < NT; ++nt)
                bf[nt] = btap[(c16 * NT + nt) * 32];
#pragma unroll
            for (int mt = 0; mt < MT; ++mt) {
                uint32_t af[4];
                ldsm_x4(af, abase + (uint32_t)((mt * 16 * ASTE + c16 * 8) * 4));
#pragma unroll
                for (int nt = 0; nt < NT; ++nt)
                    mma_f16(d[mt][nt], af, (const uint32_t*)&bf[nt]);
            }
        }
    }
    // ---- occ im2col: 2 groups ----
    {
        const uint2* btap = (const uint2*)(sB + 25600) + lane;
#pragma unroll
        for (int g = 0; g < 2; ++g) {
            uint2 bf[NT];
#pragma unroll
            for (int nt = 0; nt < NT; ++nt)
                bf[nt] = btap[(g * NT + nt) * 32];
#pragma unroll
            for (int mt = 0; mt < MT; ++mt) {
                uint32_t af[4];
                ldsm_x4(af, i_off0 + (uint32_t)((mt * 16 * ASTI + g * 8) * 4));
#pragma unroll
                for (int nt = 0; nt < NT; ++nt)
                    mma_f16(d[mt][nt], af, (const uint32_t*)&bf[nt]);
            }
        }
    }

    // ---- epilogue ----
    float2 bv[NT];
#pragma unroll
    for (int nt = 0; nt < NT; ++nt)
        bv[nt] = *(const float2*)(bias + nt * 8 + 2 * ac);
#pragma unroll
    for (int mt = 0; mt < MT; ++mt) {
#pragma unroll
        for (int half = 0; half < 2; ++half) {
            int p = p0 + wrow + mt * 16 + half * 8 + ar;
            int y = p / Wp - PAD, x = p % Wp - PAD;
            if (x >= 0 && x < W && y < W) {
                uint32_t* ob = out + (((size_t)n * W + y) * W + x) * 32 + ac;
#pragma unroll
                for (int nt = 0; nt < NT; ++nt) {
                    float vx = fmaxf(d[mt][nt][half * 2 + 0] + bv[nt].x, 0.f);
                    float vy = fmaxf(d[mt][nt][half * 2 + 1] + bv[nt].y, 0.f);
                    ob[nt * 4] = f2h2(vx, vy);
                }
            }
        }
    }
}

// ---------------- generic fp16 mma conv (conv2/conv3) -----------------------
template<int CINH, int HALVES, int NCO, int MT, int K, int H, int W, int PAD,
         int OUT_HALF, int CO_TOTAL>
__global__ void __launch_bounds__(256, 2)
hmma_conv_kernel(const void* __restrict__ in_, const unsigned* __restrict__ wt,
                 const float* __restrict__ bias, void* __restrict__ out_) {
    constexpr int NT    = NCO / 8;
    constexpr int NC16  = CINH / 16;
    constexpr int KK    = K * K;
    constexpr int TAPS  = KK * HALVES;
    constexpr int MPIX  = 8 * 16 * MT;
    constexpr int Wp    = W + 2 * PAD, Hp = H + 2 * PAD;
    constexpr int NPIX  = Wp * Hp;
    constexpr int HALO  = PAD * Wp + PAD;
    constexpr int AWIN  = MPIX + 2 * HALO;
    constexpr int AST2  = CINH / 2 + 4;
    constexpr int AWORDS = HALVES * AWIN * AST2;
    constexpr int BWORDS = TAPS * NC16 * NT * 64;
    constexpr int CINF   = 64 * HALVES;

    extern __shared__ uint32_t sm[];
    uint32_t* sA = sm;
    uint32_t* sB = sm + AWORDS;

    const int tid  = threadIdx.x;
    const int warp = tid >> 5, lane = tid & 31;
    const int ar   = lane >> 2, ac = lane & 3;
    const int n    = blockIdx.z;
    const int cob  = blockIdx.y;
    const int co0  = cob * NCO;
    const int p0   = HALO + blockIdx.x * MPIX;
    const int s0   = p0 - HALO;
    const int wrow = warp * (16 * MT);

    {
        const unsigned* wsrc = wt + (size_t)cob * BWORDS;
        uint32_t sBu = smem_u32(sB);
        for (int c = tid; c < BWORDS / 4; c += 256)
            cp_async16_s(sBu + c * 16, wsrc + c * 4);
        asm volatile("cp.async.commit_group;" ::: "memory");
    }
    {
        const uint4* inb = (const uint4*)in_ + (size_t)n * NPIX * (CINF / 8);
        for (int e = tid; e < HALVES * AWIN * 8; e += 256) {
            int h = e / (AWIN * 8);
            int r2 = e % (AWIN * 8);
            int row = r2 >> 3, c = r2 & 7;
            int pix = s0 + row;
            uint4 v = make_uint4(0u, 0u, 0u, 0u);
            if (pix < NPIX)
                v = inb[(size_t)pix * (CINF / 8) + h * 8 + c];
            *(uint4*)(sA + (h * AWIN + row) * AST2 + c * 4) = v;
        }
    }
    asm volatile("cp.async.wait_group 0;" ::: "memory");
    __syncthreads();

    float d[MT][NT][4];
#pragma unroll
    for (int mt = 0; mt < MT; ++mt)
#pragma unroll
        for (int nt = 0; nt < NT; ++nt)
#pragma unroll
            for (int q = 0; q < 4; ++q) d[mt][nt][q] = 0.f;

    const uint32_t a_off0 = smem_u32(sA) +
        (uint32_t)(((HALO + wrow + (lane & 15)) * AST2 + ((lane >> 4) << 2)) * 4);

    for (int tap = 0; tap < TAPS; ++tap) {
        int h  = (HALVES == 2) ? (tap / KK) : 0;
        int kt = (HALVES == 2) ? (tap % KK) : tap;
        int shift = (kt / K - PAD) * Wp + (kt % K) - PAD;
        uint32_t abase = a_off0 + (uint32_t)((h * AWIN + shift) * (AST2 * 4));
        const uint2* btap = (const uint2*)sB + (size_t)tap * (NC16 * NT * 32) + lane;
#pragma unroll
        for (int c16 = 0; c16 < NC16; ++c16) {
            uint2 bf[NT];
#pragma unroll
            for (int nt = 0; nt < NT; ++nt)
                bf[nt] = btap[(c16 * NT + nt) * 32];
#pragma unroll
            for (int mt = 0; mt < MT; ++mt) {
                uint32_t af[4];
                ldsm_x4(af, abase + (uint32_t)((mt * 16 * AST2 + c16 * 8) * 4));
#pragma unroll
                for (int nt = 0; nt < NT; ++nt)
                    mma_f16(d[mt][nt], af, (const uint32_t*)&bf[nt]);
            }
        }
    }

    float2 bv[NT];
#pragma unroll
    for (int nt = 0; nt < NT; ++nt)
        bv[nt] = *(const float2*)(bias + co0 + nt * 8 + 2 * ac);

#pragma unroll
    for (int mt = 0; mt < MT; ++mt) {
#pragma unroll
        for (int half = 0; half < 2; ++half) {
            int p = p0 + wrow + mt * 16 + half * 8 + ar;
            int y = p / Wp - PAD, x = p % Wp - PAD;
            if (x >= 0 && x < W && y < H) {
                size_t pix = ((size_t)n * H + y) * W + x;
                if (OUT_HALF) {
                    uint32_t* ob = (uint32_t*)out_ + pix * (CO_TOTAL / 2) + co0 / 2 + ac;
#pragma unroll
                    for (int nt = 0; nt < NT; ++nt) {
                        float vx = fmaxf(d[mt][nt][half * 2 + 0] + bv[nt].x, 0.f);
                        float vy = fmaxf(d[mt][nt][half * 2 + 1] + bv[nt].y, 0.f);
                        ob[nt * 4] = f2h2(vx, vy);
                    }
                } else {
                    float* ob = (float*)out_ + pix * CO_TOTAL + co0 + 2 * ac;
#pragma unroll
                    for (int nt = 0; nt < NT; ++nt) {
                        float2 v;
                        v.x = fmaxf(d[mt][nt][half * 2 + 0] + bv[nt].x, 0.f);
                        v.y = fmaxf(d[mt][nt][half * 2 + 1] + bv[nt].y, 0.f);
                        *(float2*)(ob + nt * 8) = v;
                    }
                }
            }
        }
    }
}

// ---------------- pools / gap / fc ----------------
template<int C, int HI, int HO, int P>
__global__ void pool_half_kernel(const uint2* __restrict__ in, uint2* __restrict__ out) {
    constexpr int C4 = C / 4, HOP = HO + 2 * P;
    int idx = blockIdx.x * blockDim.x + threadIdx.x;
    if (idx >= NB * HO * HO * C4) return;
    int c  = idx % C4;
    int ox = (idx / C4) % HO;
    int oy = (idx / (C4 * HO)) % HO;
    int n  = idx / (C4 * HO * HO);
    const uint2* p = in + (((size_t)n * HI + 2 * oy) * HI + 2 * ox) * C4 + c;
    uint2 m0 = p[0];
    __half2 ma = *(__half2*)&m0.x, mb = *(__half2*)&m0.y;
#pragma unroll
    for (int dy = 0; dy < 3; ++dy)
#pragma unroll
        for (int dx = 0; dx < 3; ++dx) {
            uint2 q = p[((size_t)dy * HI + dx) * C4];
            ma = __hmax2(ma, *(__half2*)&q.x);
            mb = __hmax2(mb, *(__half2*)&q.y);
        }
    uint2 r; r.x = *(uint32_t*)&ma; r.y = *(uint32_t*)&mb;
    out[(((size_t)n * HOP + oy + P) * HOP + ox + P) * C4 + c] = r;
}

template<int C, int HI, int HO>
__global__ void pool_f32_kernel(const float4* __restrict__ in, float4* __restrict__ out) {
    constexpr int C4 = C / 4;
    int idx = blockIdx.x * blockDim.x + threadIdx.x;
    if (idx >= NB * HO * HO * C4) return;
    int c  = idx % C4;
    int ox = (idx / C4) % HO;
    int oy = (idx / (C4 * HO)) % HO;
    int n  = idx / (C4 * HO * HO);
    const float4* p = in + (((size_t)n * HI + 2 * oy) * HI + 2 * ox) * C4 + c;
    float4 m = p[0];
#pragma unroll
    for (int dy = 0; dy < 3; ++dy)
#pragma unroll
        for (int dx = 0; dx < 3; ++dx) {
            float4 q = p[((size_t)dy * HI + dx) * C4];
            m.x = fmaxf(m.x, q.x); m.y = fmaxf(m.y, q.y);
            m.z = fmaxf(m.z, q.z); m.w = fmaxf(m.w, q.w);
        }
    out[(((size_t)n * HO + oy) * HO + ox) * C4 + c] = m;
}

__global__ void gap_kernel(const float4* __restrict__ in, float4* __restrict__ out) {
    int idx = blockIdx.x * blockDim.x + threadIdx.x;
    if (idx >= NB * 64) return;
    int n = idx >> 6, c = idx & 63;
    const float4* p = in + (size_t)n * 64 * 64 + c;
    float4 s = make_float4(0.f, 0.f, 0.f, 0.f);
#pragma unroll
    for (int i = 0; i < 64; ++i) {
        float4 q = p[i * 64];
        s.x += q.x; s.y += q.y; s.z += q.z; s.w += q.w;
    }
    s.x *= (1.f/64.f); s.y *= (1.f/64.f); s.z *= (1.f/64.f); s.w *= (1.f/64.f);
    out[idx] = s;
}

__global__ void fc_kernel(const float* __restrict__ in, const float* __restrict__ w,
                          const float* __restrict__ b, float* __restrict__ out,
                          int K_, int O_, int relu) {
    int idx = blockIdx.x * blockDim.x + threadIdx.x;
    if (idx >= NB * O_) return;
    int n = idx / O_, o = idx % O_;
    const float4* ip = (const float4*)(in + (size_t)n * K_);
    const float4* wp = (const float4*)(w + (size_t)o * K_);
    float s = b[o];
    int k4 = K_ >> 2;
#pragma unroll 4
    for (int k = 0; k < k4; ++k) {
        float4 a = ip[k], ww = wp[k];
        s = fmaf(a.x, ww.x, s); s = fmaf(a.y, ww.y, s);
        s = fmaf(a.z, ww.z, s); s = fmaf(a.w, ww.w, s);
    }
    if (relu) s = fmaxf(s, 0.f);
    out[idx] = s;
}

// ---------------- launch ----------------
extern "C" void kernel_launch(void* const* d_in, const int* in_sizes, int n_in,
                              void* d_out, int out_size) {
    const int*   X    = (const int*)  d_in[0];
    const int*   rmap = (const int*)  d_in[1];
    const float* emb  = (const float*)d_in[2];
    const float* cw0  = (const float*)d_in[3];
    const float* cb0  = (const float*)d_in[4];
    const float* cw1  = (const float*)d_in[5];
    const float* cb1  = (const float*)d_in[6];
    const float* cw2  = (const float*)d_in[7];
    const float* cb2  = (const float*)d_in[8];
    const float* fw0  = (const float*)d_in[9];
    const float* fb0  = (const float*)d_in[10];
    const float* fw1  = (const float*)d_in[11];
    const float* fb1  = (const float*)d_in[12];
    const float* fw2  = (const float*)d_in[13];
    const float* fb2  = (const float*)d_in[14];
    float* out = (float*)d_out;

    float *c3, *p3, *gapb, *f1, *f2;
    unsigned *grid, *c1, *p1, *c2, *p2, *wt1, *wt2, *wt3;
    cudaGetSymbolAddress((void**)&grid, g_grid);
    cudaGetSymbolAddress((void**)&c1,  g_c1);
    cudaGetSymbolAddress((void**)&p1,  g_p1);
    cudaGetSymbolAddress((void**)&c2,  g_c2);
    cudaGetSymbolAddress((void**)&p2,  g_p2);
    cudaGetSymbolAddress((void**)&c3,  g_c3);
    cudaGetSymbolAddress((void**)&p3,  g_p3);
    cudaGetSymbolAddress((void**)&gapb, g_gap);
    cudaGetSymbolAddress((void**)&f1,  g_f1);
    cudaGetSymbolAddress((void**)&f2,  g_f2);
    cudaGetSymbolAddress((void**)&wt1, g_wt1);
    cudaGetSymbolAddress((void**)&wt2, g_wt2);
    cudaGetSymbolAddress((void**)&wt3, g_wt3);

    // smem (words * 4B):
    // conv1: 11280 + 5120 + 288 + 26624 = 43312 -> 173,248 B
    // conv2: 460*36 + 9216 = 25776 -> 103,104 B (2 blocks/SM)
    // conv3: 2*424*36 + 18432 = 48960 -> 195,840 B
    const int SM1 = 43312 * 4;
    const int SM2 = (460 * 36 +  9216) * 4;
    const int SM3 = (2 * 424 * 36 + 18432) * 4;
    cudaFuncSetAttribute((const void*)conv1_kernel,
                         cudaFuncAttributeMaxDynamicSharedMemorySize, SM1);
    cudaFuncSetAttribute((const void*)hmma_conv_kernel<64, 1, 32, 3, 3, 35, 35, 1, 1, 128>,
                         cudaFuncAttributeMaxDynamicSharedMemorySize, SM2);
    cudaFuncSetAttribute((const void*)hmma_conv_kernel<64, 2, 32, 3, 3, 17, 17, 1, 0, 256>,
                         cudaFuncAttributeMaxDynamicSharedMemorySize, SM3);

    // zero padded buffers
    {
        int n4;
        n4 = NB * 76 * 76 * 20 / 4; zero_kernel<<<(n4 + 255) / 256, 256>>>((float4*)grid, n4);
        n4 = NB * 37 * 37 * 32 / 4; zero_kernel<<<(n4 + 255) / 256, 256>>>((float4*)p1, n4);
        n4 = NB * 19 * 19 * 64 / 4; zero_kernel<<<(n4 + 255) / 256, 256>>>((float4*)p2, n4);
    }
    // weight transforms
    {
        wtrans1_kernel<<<(26624 + 255) / 256, 256>>>(cw0, wt1);
        int n2 = 36864;  wtrans_kernel<64, 64, 1, 32, 4, 9><<<(n2 + 255) / 256, 256>>>(cw1, wt2);
        int n3 = 147456; wtrans_kernel<128, 64, 2, 32, 8, 9><<<(n3 + 255) / 256, 256>>>(cw2, wt3);
    }
    // scatter encode (half2 atomics)
    {
        int nt = NB * RNUM * 64;
        scatter_kernel<<<(nt + 255) / 256, 256>>>(X, rmap, emb, (__half2*)grid);
    }
    // conv1 + pool1
    conv1_kernel<<<dim3(22, 1, NB), 256, SM1>>>(grid, wt1, cb0, c1);
    {
        int nt = NB * 35 * 35 * 16;
        pool_half_kernel<64, 72, 35, 1><<<(nt + 255) / 256, 256>>>((const uint2*)c1, (uint2*)p1);
    }
    // conv2 + pool2
    hmma_conv_kernel<64, 1, 32, 3, 3, 35, 35, 1, 1, 128>
        <<<dim3(4, 4, NB), 256, SM2>>>(p1, wt2, cb1, c2);
    {
        int nt = NB * 17 * 17 * 32;
        pool_half_kernel<128, 35, 17, 1><<<(nt + 255) / 256, 256>>>((const uint2*)c2, (uint2*)p2);
    }
    // conv3 + pool3
    hmma_conv_kernel<64, 2, 32, 3, 3, 17, 17, 1, 0, 256>
        <<<dim3(1, 8, NB), 256, SM3>>>(p2, wt3, cb2, c3);
    {
        int nt = NB * 8 * 8 * 64;
        pool_f32_kernel<256, 17, 8><<<(nt + 255) / 256, 256>>>((const float4*)c3, (float4*)p3);
    }
    // GAP + FC stack
    gap_kernel<<<(NB * 64 + 255) / 256, 256>>>((const float4*)p3, (float4*)gapb);
    fc_kernel<<<(NB * 512 + 255) / 256, 256>>>(gapb, fw0, fb0, f1, 256, 512, 1);
    fc_kernel<<<(NB * 256 + 255) / 256, 256>>>(f1,   fw1, fb1, f2, 512, 256, 1);
    fc_kernel<<<(NB * 512 + 255) / 256, 256>>>(f2,   fw2, fb2, out, 256, 512, 0);
}

// round 9
// speedup vs baseline: 8.0486x; 1.1622x over previous
#include <cuda_runtime.h>
#include <cuda_fp16.h>
#include <stdint.h>

// ---------------- problem constants ----------------
#define NB   128
#define RNUM 300
#define EMB  32

// ---------------- buffers ----------------
// grid: half NHWC [n][76][76][40]: ch0-31 = emb, ch32 = occupancy, 33-39 pad
__device__ unsigned g_grid[NB * 76 * 76 * 20];   // half2 words
__device__ unsigned g_c1 [NB * 72 * 72 * 32];    // conv1 out half2 (64ch)
__device__ unsigned g_p1 [NB * 37 * 37 * 32];    // pool1 half2 (pad1)
__device__ unsigned g_c2 [NB * 35 * 35 * 64];    // conv2 out half2 (128ch)
__device__ unsigned g_p2 [NB * 19 * 19 * 64];    // pool2 half2 (pad1)
__device__ float    g_c3 [NB * 17 * 17 * 256];   // conv3 out fp32
__device__ float    g_p3 [NB * 8 * 8 * 256];
__device__ float    g_gap[NB * 256];
__device__ float    g_f1 [NB * 512];
__device__ float    g_f2 [NB * 256];
// conv1 B: emb region 25*2*8*64 + occ region 2*8*64
__device__ unsigned g_wt1[ 26624];
__device__ unsigned g_wt2[ 36864];               // 4 * 9 * 4 * 4 * 64
__device__ unsigned g_wt3[147456];               // 8 * 18 * 4 * 4 * 64

// ---------------- helpers ----------------
__device__ __forceinline__ void mma_f16(float* d, const uint32_t* a, const uint32_t* b) {
    asm volatile(
        "mma.sync.aligned.m16n8k16.row.col.f32.f16.f16.f32 "
        "{%0,%1,%2,%3}, {%4,%5,%6,%7}, {%8,%9}, {%0,%1,%2,%3};"
        : "+f"(d[0]), "+f"(d[1]), "+f"(d[2]), "+f"(d[3])
        : "r"(a[0]), "r"(a[1]), "r"(a[2]), "r"(a[3]), "r"(b[0]), "r"(b[1]));
}
__device__ __forceinline__ void ldsm_x4(uint32_t* a, uint32_t addr) {
    asm volatile("ldmatrix.sync.aligned.m8n8.x4.shared.b16 {%0,%1,%2,%3}, [%4];"
        : "=r"(a[0]), "=r"(a[1]), "=r"(a[2]), "=r"(a[3]) : "r"(addr));
}
__device__ __forceinline__ uint32_t smem_u32(const void* p) {
    uint32_t a;
    asm("{ .reg .u64 t; cvta.to.shared.u64 t, %1; cvt.u32.u64 %0, t; }" : "=r"(a) : "l"(p));
    return a;
}
__device__ __forceinline__ void cp_async16_s(uint32_t saddr, const void* g) {
    asm volatile("cp.async.cg.shared.global [%0], [%1], 16;" :: "r"(saddr), "l"(g));
}
// cp.async with zero-fill when src out of range (src-size = 0)
__device__ __forceinline__ void cp_async16_z(uint32_t saddr, const void* g, uint32_t srcsz) {
    asm volatile("cp.async.cg.shared.global [%0], [%1], 16, %2;"
                 :: "r"(saddr), "l"(g), "r"(srcsz));
}
__device__ __forceinline__ uint32_t f2h2(float a, float b) {
    __half2 h = __float22half2_rn(make_float2(a, b));
    return *(uint32_t*)&h;
}

// ---------------- zero fill ----------------
__global__ void zero_kernel(float4* __restrict__ p, int n4) {
    int i = blockIdx.x * blockDim.x + threadIdx.x;
    if (i < n4) p[i] = make_float4(0.f, 0.f, 0.f, 0.f);
}

// ---------------- scatter rooms into half grid (half2 atomics) --------------
__global__ void scatter_kernel(const int* __restrict__ X,
                               const int* __restrict__ rm,
                               const float* __restrict__ emb,
                               __half2* __restrict__ grid) {
    int idx = blockIdx.x * blockDim.x + threadIdx.x;
    if (idx >= NB * RNUM * 64) return;
    int cell = idx & 63;
    int r    = (idx >> 6) % RNUM;
    int n    = idx / (RNUM * 64);
    if (!rm[r * 64 + cell]) return;
    int cx = cell >> 3, cy = cell & 7;
    int px = X[(n * RNUM + r) * 2 + 0];
    int py = X[(n * RNUM + r) * 2 + 1];
    int Y = py + cy + 2, Xc = px + cx + 2;
    __half2* base = grid + (((size_t)n * 76 + Y) * 76 + Xc) * 20;
    const float* er = emb + r * EMB;
#pragma unroll
    for (int w = 0; w < 16; ++w)
        atomicAdd(base + w, __float22half2_rn(make_float2(er[2 * w], er[2 * w + 1])));
    atomicAdd(base + 16, __float22half2_rn(make_float2(1.f, 0.f)));   // occupancy ch32
}

// ------- conv1 weight transform: emb (ci 1..32) + occ (ci 0) im2col regions -
__global__ void wtrans1_kernel(const float* __restrict__ w, unsigned* __restrict__ wt) {
    int i = blockIdx.x * blockDim.x + threadIdx.x;
    if (i >= 26624) return;
    int which = i & 1;
    int lane  = (i >> 1) & 31;
    int r1    = i >> 6;
    int ac = lane & 3, ar = lane >> 2;
    if (i < 25600) {
        int nt  = r1 % 8;  r1 /= 8;
        int c16 = r1 % 2;
        int tap = r1 / 2;
        int kl  = c16 * 16 + ac * 2 + which * 8;
        int co  = nt * 8 + ar;
        float v0 = w[((size_t)co * 33 + 1 + kl) * 25 + tap];
        float v1 = w[((size_t)co * 33 + 2 + kl) * 25 + tap];
        wt[i] = f2h2(v0, v1);
    } else {
        int j  = i - 25600;
        int r2 = j >> 6;
        int nt = r2 % 8;
        int g  = r2 / 8;
        int kl = g * 16 + ac * 2 + which * 8;
        int co = nt * 8 + ar;
        float v0 = (kl     < 25) ? w[((size_t)co * 33 + 0) * 25 + kl]     : 0.f;
        float v1 = (kl + 1 < 25) ? w[((size_t)co * 33 + 0) * 25 + kl + 1] : 0.f;
        wt[i] = f2h2(v0, v1);
    }
}

// ------- generic weight transform (conv2/conv3) ------------------------------
template<int CI, int CINH, int HALVES, int NCO, int COB, int KK>
__global__ void wtrans_kernel(const float* __restrict__ w, unsigned* __restrict__ wt) {
    constexpr int NT = NCO / 8, NC16 = CINH / 16, TAPS = KK * HALVES;
    int i = blockIdx.x * blockDim.x + threadIdx.x;
    if (i >= COB * TAPS * NC16 * NT * 64) return;
    int which = i & 1;
    int lane  = (i >> 1) & 31;
    int r1    = i >> 6;
    int nt    = r1 % NT;  r1 /= NT;
    int c16   = r1 % NC16; r1 /= NC16;
    int tap   = r1 % TAPS;
    int cob   = r1 / TAPS;
    int ac = lane & 3, ar = lane >> 2;
    int k_local = c16 * 16 + ac * 2 + which * 8;
    int h  = tap / KK, kk = tap % KK;
    int ci0 = h * CINH + k_local;
    int co  = cob * NCO + nt * 8 + ar;
    float v0 = (ci0     < CI) ? w[((size_t)co * CI + ci0)     * KK + kk] : 0.f;
    float v1 = (ci0 + 1 < CI) ? w[((size_t)co * CI + ci0 + 1) * KK + kk] : 0.f;
    wt[i] = f2h2(v0, v1);
}

// ---------------- conv1: emb k16x2 per tap + occ im2col (2 groups total) ----
__global__ void __launch_bounds__(256, 1)
conv1_kernel(const unsigned* __restrict__ in, const unsigned* __restrict__ wt,
             const float* __restrict__ bias, unsigned* __restrict__ out) {
    constexpr int MT = 2, NT = 8;
    constexpr int MPIX = 256;
    constexpr int W = 72, PAD = 2, Wp = 76, NPIX = 76 * 76;
    constexpr int HALO = PAD * Wp + PAD;              // 154
    constexpr int AWIN = MPIX + 2 * HALO;             // 564
    constexpr int ASTE = 20;
    constexpr int ASTI = 20;
    constexpr int AEW  = AWIN * ASTE;                 // 11280
    constexpr int IMW  = MPIX * ASTI;                 // 5120
    constexpr int OCW  = 288;
    constexpr int BW   = 26624;

    extern __shared__ uint32_t sm[];
    uint32_t* sAe = sm;
    uint32_t* sIm = sm + AEW;
    __half*   sOc = (__half*)(sm + AEW + IMW);
    uint32_t* sB  = sm + AEW + IMW + OCW;

    const int tid  = threadIdx.x;
    const int warp = tid >> 5, lane = tid & 31;
    const int ar   = lane >> 2, ac = lane & 3;
    const int n    = blockIdx.z;
    const int p0   = HALO + blockIdx.x * MPIX;
    const int s0   = p0 - HALO;
    const int wrow = warp * (16 * MT);

    // ---- B + emb A via cp.async (zfill OOB rows) ----
    {
        uint32_t sBu = smem_u32(sB);
        for (int c = tid; c < BW / 4; c += 256)
            cp_async16_s(sBu + c * 16, wt + c * 4);
        const unsigned* inb = in + (size_t)n * NPIX * 20;
        uint32_t sAu = smem_u32(sAe);
        for (int e = tid; e < AWIN * 4; e += 256) {
            int row = e >> 2, c = e & 3;
            int pix = s0 + row;
            cp_async16_z(sAu + (uint32_t)((row * ASTE + c * 4) * 4),
                         inb + (size_t)pix * 20 + c * 4,
                         (pix < NPIX) ? 16u : 0u);
        }
        asm volatile("cp.async.commit_group;" ::: "memory");
    }
    // ---- occ raw staging (registers) ----
    {
        const unsigned* inw = in + (size_t)n * NPIX * 20;
        for (int row = tid; row < AWIN; row += 256) {
            int pix = s0 + row;
            uint32_t v = (pix < NPIX) ? inw[(size_t)pix * 20 + 16] : 0u;
            sOc[row] = *(__half*)&v;                  // low half = ch32
        }
    }
    __syncthreads();
    // ---- build occ im2col ----
    {
        __half* imh = (__half*)sIm;
        for (int e = tid; e < MPIX * 16; e += 256) {
            int rr = e >> 4, w2 = e & 15;
            int k0 = 2 * w2, k1 = 2 * w2 + 1;
            __half h0 = __float2half(0.f), h1 = h0;
            if (k0 < 25) {
                int sh = (k0 / 5 - 2) * Wp + (k0 % 5) - 2;
                h0 = sOc[rr + HALO + sh];
            }
            if (k1 < 25) {
                int sh = (k1 / 5 - 2) * Wp + (k1 % 5) - 2;
                h1 = sOc[rr + HALO + sh];
            }
            imh[(rr * ASTI) * 2 + 2 * w2]     = h0;
            imh[(rr * ASTI) * 2 + 2 * w2 + 1] = h1;
        }
    }
    asm volatile("cp.async.wait_group 0;" ::: "memory");
    __syncthreads();

    float d[MT][NT][4];
#pragma unroll
    for (int mt = 0; mt < MT; ++mt)
#pragma unroll
        for (int nt = 0; nt < NT; ++nt)
#pragma unroll
            for (int q = 0; q < 4; ++q) d[mt][nt][q] = 0.f;

    const uint32_t a_off0 = smem_u32(sAe) +
        (uint32_t)(((HALO + wrow + (lane & 15)) * ASTE + ((lane >> 4) << 2)) * 4);
    const uint32_t i_off0 = smem_u32(sIm) +
        (uint32_t)(((wrow + (lane & 15)) * ASTI + ((lane >> 4) << 2)) * 4);

    for (int tap = 0; tap < 25; ++tap) {
        int shift = (tap / 5 - PAD) * Wp + (tap % 5) - PAD;
        uint32_t abase = a_off0 + (uint32_t)(shift * (ASTE * 4));
        const uint2* btap = (const uint2*)sB + (size_t)tap * (2 * NT * 32) + lane;
#pragma unroll
        for (int c16 = 0; c16 < 2; ++c16) {
            uint2 bf[NT];
#pragma unroll
            for (int nt = 0; nt < NT; ++nt)
                bf[nt] = btap[(c16 * NT + nt) * 32];
#pragma unroll
            for (int mt = 0; mt < MT; ++mt) {
                uint32_t af[4];
                ldsm_x4(af, abase + (uint32_t)((mt * 16 * ASTE + c16 * 8) * 4));
#pragma unroll
                for (int nt = 0; nt < NT; ++nt)
                    mma_f16(d[mt][nt], af, (const uint32_t*)&bf[nt]);
            }
        }
    }
    {
        const uint2* btap = (const uint2*)(sB + 25600) + lane;
#pragma unroll
        for (int g = 0; g < 2; ++g) {
            uint2 bf[NT];
#pragma unroll
            for (int nt = 0; nt < NT; ++nt)
                bf[nt] = btap[(g * NT + nt) * 32];
#pragma unroll
            for (int mt = 0; mt < MT; ++mt) {
                uint32_t af[4];
                ldsm_x4(af, i_off0 + (uint32_t)((mt * 16 * ASTI + g * 8) * 4));
#pragma unroll
                for (int nt = 0; nt < NT; ++nt)
                    mma_f16(d[mt][nt], af, (const uint32_t*)&bf[nt]);
            }
        }
    }

    float2 bv[NT];
#pragma unroll
    for (int nt = 0; nt < NT; ++nt)
        bv[nt] = *(const float2*)(bias + nt * 8 + 2 * ac);
#pragma unroll
    for (int mt = 0; mt < MT; ++mt) {
#pragma unroll
        for (int half = 0; half < 2; ++half) {
            int p = p0 + wrow + mt * 16 + half * 8 + ar;
            int y = p / Wp - PAD, x = p % Wp - PAD;
            if (x >= 0 && x < W && y < W) {
                uint32_t* ob = out + (((size_t)n * W + y) * W + x) * 32 + ac;
#pragma unroll
                for (int nt = 0; nt < NT; ++nt) {
                    float vx = fmaxf(d[mt][nt][half * 2 + 0] + bv[nt].x, 0.f);
                    float vy = fmaxf(d[mt][nt][half * 2 + 1] + bv[nt].y, 0.f);
                    ob[nt * 4] = f2h2(vx, vy);
                }
            }
        }
    }
}

// ---------------- generic fp16 mma conv (conv2/conv3) -----------------------
template<int CINH, int HALVES, int NCO, int MT, int K, int H, int W, int PAD,
         int OUT_HALF, int CO_TOTAL>
__global__ void __launch_bounds__(256, 2)
hmma_conv_kernel(const void* __restrict__ in_, const unsigned* __restrict__ wt,
                 const float* __restrict__ bias, void* __restrict__ out_) {
    constexpr int NT    = NCO / 8;
    constexpr int NC16  = CINH / 16;
    constexpr int KK    = K * K;
    constexpr int TAPS  = KK * HALVES;
    constexpr int MPIX  = 8 * 16 * MT;
    constexpr int Wp    = W + 2 * PAD, Hp = H + 2 * PAD;
    constexpr int NPIX  = Wp * Hp;
    constexpr int HALO  = PAD * Wp + PAD;
    constexpr int AWIN  = MPIX + 2 * HALO;
    constexpr int AST2  = CINH / 2 + 4;
    constexpr int AWORDS = HALVES * AWIN * AST2;
    constexpr int BWORDS = TAPS * NC16 * NT * 64;
    constexpr int CINF   = 64 * HALVES;

    extern __shared__ uint32_t sm[];
    uint32_t* sA = sm;
    uint32_t* sB = sm + AWORDS;

    const int tid  = threadIdx.x;
    const int warp = tid >> 5, lane = tid & 31;
    const int ar   = lane >> 2, ac = lane & 3;
    const int n    = blockIdx.z;
    const int cob  = blockIdx.y;
    const int co0  = cob * NCO;
    const int p0   = HALO + blockIdx.x * MPIX;
    const int s0   = p0 - HALO;
    const int wrow = warp * (16 * MT);

    {
        const unsigned* wsrc = wt + (size_t)cob * BWORDS;
        uint32_t sBu = smem_u32(sB);
        for (int c = tid; c < BWORDS / 4; c += 256)
            cp_async16_s(sBu + c * 16, wsrc + c * 4);
        const uint4* inb = (const uint4*)in_ + (size_t)n * NPIX * (CINF / 8);
        uint32_t sAu = smem_u32(sA);
        for (int e = tid; e < HALVES * AWIN * 8; e += 256) {
            int h = e / (AWIN * 8);
            int r2 = e % (AWIN * 8);
            int row = r2 >> 3, c = r2 & 7;
            int pix = s0 + row;
            cp_async16_z(sAu + (uint32_t)(((h * AWIN + row) * AST2 + c * 4) * 4),
                         inb + (size_t)pix * (CINF / 8) + h * 8 + c,
                         (pix < NPIX) ? 16u : 0u);
        }
        asm volatile("cp.async.commit_group;" ::: "memory");
    }
    asm volatile("cp.async.wait_group 0;" ::: "memory");
    __syncthreads();

    float d[MT][NT][4];
#pragma unroll
    for (int mt = 0; mt < MT; ++mt)
#pragma unroll
        for (int nt = 0; nt < NT; ++nt)
#pragma unroll
            for (int q = 0; q < 4; ++q) d[mt][nt][q] = 0.f;

    const uint32_t a_off0 = smem_u32(sA) +
        (uint32_t)(((HALO + wrow + (lane & 15)) * AST2 + ((lane >> 4) << 2)) * 4);

    for (int tap = 0; tap < TAPS; ++tap) {
        int h  = (HALVES == 2) ? (tap / KK) : 0;
        int kt = (HALVES == 2) ? (tap % KK) : tap;
        int shift = (kt / K - PAD) * Wp + (kt % K) - PAD;
        uint32_t abase = a_off0 + (uint32_t)((h * AWIN + shift) * (AST2 * 4));
        const uint2* btap = (const uint2*)sB + (size_t)tap * (NC16 * NT * 32) + lane;
#pragma unroll
        for (int c16 = 0; c16 < NC16; ++c16) {
            uint2 bf[NT];
#pragma unroll
            for (int nt = 0; nt < NT; ++nt)
                bf[nt] = btap[(c16 * NT + nt) * 32];
#pragma unroll
            for (int mt = 0; mt < MT; ++mt) {
                uint32_t af[4];
                ldsm_x4(af, abase + (uint32_t)((mt * 16 * AST2 + c16 * 8) * 4));
#pragma unroll
                for (int nt = 0; nt < NT; ++nt)
                    mma_f16(d[mt][nt], af, (const uint32_t*)&bf[nt]);
            }
        }
    }

    float2 bv[NT];
#pragma unroll
    for (int nt = 0; nt < NT; ++nt)
        bv[nt] = *(const float2*)(bias + co0 + nt * 8 + 2 * ac);

#pragma unroll
    for (int mt = 0; mt < MT; ++mt) {
#pragma unroll
        for (int half = 0; half < 2; ++half) {
            int p = p0 + wrow + mt * 16 + half * 8 + ar;
            int y = p / Wp - PAD, x = p % Wp - PAD;
            if (x >= 0 && x < W && y < H) {
                size_t pix = ((size_t)n * H + y) * W + x;
                if (OUT_HALF) {
                    uint32_t* ob = (uint32_t*)out_ + pix * (CO_TOTAL / 2) + co0 / 2 + ac;
#pragma unroll
                    for (int nt = 0; nt < NT; ++nt) {
                        float vx = fmaxf(d[mt][nt][half * 2 + 0] + bv[nt].x, 0.f);
                        float vy = fmaxf(d[mt][nt][half * 2 + 1] + bv[nt].y, 0.f);
                        ob[nt * 4] = f2h2(vx, vy);
                    }
                } else {
                    float* ob = (float*)out_ + pix * CO_TOTAL + co0 + 2 * ac;
#pragma unroll
                    for (int nt = 0; nt < NT; ++nt) {
                        float2 v;
                        v.x = fmaxf(d[mt][nt][half * 2 + 0] + bv[nt].x, 0.f);
                        v.y = fmaxf(d[mt][nt][half * 2 + 1] + bv[nt].y, 0.f);
                        *(float2*)(ob + nt * 8) = v;
                    }
                }
            }
        }
    }
}

// ---------------- pools (write own pad frame) / gap / fc ----------------
template<int C, int HI, int HO, int P>
__global__ void pool_half_kernel(const uint2* __restrict__ in, uint2* __restrict__ out) {
    constexpr int C4 = C / 4, HOP = HO + 2 * P;
    int idx = blockIdx.x * blockDim.x + threadIdx.x;
    if (idx >= NB * HOP * HOP * C4) return;
    int c  = idx % C4;
    int ox = (idx / C4) % HOP;
    int oy = (idx / (C4 * HOP)) % HOP;
    int n  = idx / (C4 * HOP * HOP);
    uint2 r;
    if (ox < P || ox >= HO + P || oy < P || oy >= HO + P) {
        r = make_uint2(0u, 0u);
    } else {
        const uint2* p = in + (((size_t)n * HI + 2 * (oy - P)) * HI + 2 * (ox - P)) * C4 + c;
        uint2 m0 = p[0];
        __half2 ma = *(__half2*)&m0.x, mb = *(__half2*)&m0.y;
#pragma unroll
        for (int dy = 0; dy < 3; ++dy)
#pragma unroll
            for (int dx = 0; dx < 3; ++dx) {
                uint2 q = p[((size_t)dy * HI + dx) * C4];
                ma = __hmax2(ma, *(__half2*)&q.x);
                mb = __hmax2(mb, *(__half2*)&q.y);
            }
        r.x = *(uint32_t*)&ma; r.y = *(uint32_t*)&mb;
    }
    out[(((size_t)n * HOP + oy) * HOP + ox) * C4 + c] = r;
}

template<int C, int HI, int HO>
__global__ void pool_f32_kernel(const float4* __restrict__ in, float4* __restrict__ out) {
    constexpr int C4 = C / 4;
    int idx = blockIdx.x * blockDim.x + threadIdx.x;
    if (idx >= NB * HO * HO * C4) return;
    int c  = idx % C4;
    int ox = (idx / C4) % HO;
    int oy = (idx / (C4 * HO)) % HO;
    int n  = idx / (C4 * HO * HO);
    const float4* p = in + (((size_t)n * HI + 2 * oy) * HI + 2 * ox) * C4 + c;
    float4 m = p[0];
#pragma unroll
    for (int dy = 0; dy < 3; ++dy)
#pragma unroll
        for (int dx = 0; dx < 3; ++dx) {
            float4 q = p[((size_t)dy * HI + dx) * C4];
            m.x = fmaxf(m.x, q.x); m.y = fmaxf(m.y, q.y);
            m.z = fmaxf(m.z, q.z); m.w = fmaxf(m.w, q.w);
        }
    out[(((size_t)n * HO + oy) * HO + ox) * C4 + c] = m;
}

__global__ void gap_kernel(const float4* __restrict__ in, float4* __restrict__ out) {
    int idx = blockIdx.x * blockDim.x + threadIdx.x;
    if (idx >= NB * 64) return;
    int n = idx >> 6, c = idx & 63;
    const float4* p = in + (size_t)n * 64 * 64 + c;
    float4 s = make_float4(0.f, 0.f, 0.f, 0.f);
#pragma unroll
    for (int i = 0; i < 64; ++i) {
        float4 q = p[i * 64];
        s.x += q.x; s.y += q.y; s.z += q.z; s.w += q.w;
    }
    s.x *= (1.f/64.f); s.y *= (1.f/64.f); s.z *= (1.f/64.f); s.w *= (1.f/64.f);
    out[idx] = s;
}

__global__ void fc_kernel(const float* __restrict__ in, const float* __restrict__ w,
                          const float* __restrict__ b, float* __restrict__ out,
                          int K_, int O_, int relu) {
    int idx = blockIdx.x * blockDim.x + threadIdx.x;
    if (idx >= NB * O_) return;
    int n = idx / O_, o = idx % O_;
    const float4* ip = (const float4*)(in + (size_t)n * K_);
    const float4* wp = (const float4*)(w + (size_t)o * K_);
    float s = b[o];
    int k4 = K_ >> 2;
#pragma unroll 4
    for (int k = 0; k < k4; ++k) {
        float4 a = ip[k], ww = wp[k];
        s = fmaf(a.x, ww.x, s); s = fmaf(a.y, ww.y, s);
        s = fmaf(a.z, ww.z, s); s = fmaf(a.w, ww.w, s);
    }
    if (relu) s = fmaxf(s, 0.f);
    out[idx] = s;
}

// ---------------- launch ----------------
extern "C" void kernel_launch(void* const* d_in, const int* in_sizes, int n_in,
                              void* d_out, int out_size) {
    const int*   X    = (const int*)  d_in[0];
    const int*   rmap = (const int*)  d_in[1];
    const float* emb  = (const float*)d_in[2];
    const float* cw0  = (const float*)d_in[3];
    const float* cb0  = (const float*)d_in[4];
    const float* cw1  = (const float*)d_in[5];
    const float* cb1  = (const float*)d_in[6];
    const float* cw2  = (const float*)d_in[7];
    const float* cb2  = (const float*)d_in[8];
    const float* fw0  = (const float*)d_in[9];
    const float* fb0  = (const float*)d_in[10];
    const float* fw1  = (const float*)d_in[11];
    const float* fb1  = (const float*)d_in[12];
    const float* fw2  = (const float*)d_in[13];
    const float* fb2  = (const float*)d_in[14];
    float* out = (float*)d_out;

    float *c3, *p3, *gapb, *f1, *f2;
    unsigned *grid, *c1, *p1, *c2, *p2, *wt1, *wt2, *wt3;
    cudaGetSymbolAddress((void**)&grid, g_grid);
    cudaGetSymbolAddress((void**)&c1,  g_c1);
    cudaGetSymbolAddress((void**)&p1,  g_p1);
    cudaGetSymbolAddress((void**)&c2,  g_c2);
    cudaGetSymbolAddress((void**)&p2,  g_p2);
    cudaGetSymbolAddress((void**)&c3,  g_c3);
    cudaGetSymbolAddress((void**)&p3,  g_p3);
    cudaGetSymbolAddress((void**)&gapb, g_gap);
    cudaGetSymbolAddress((void**)&f1,  g_f1);
    cudaGetSymbolAddress((void**)&f2,  g_f2);
    cudaGetSymbolAddress((void**)&wt1, g_wt1);
    cudaGetSymbolAddress((void**)&wt2, g_wt2);
    cudaGetSymbolAddress((void**)&wt3, g_wt3);

    const int SM1 = 43312 * 4;
    const int SM2 = (460 * 36 +  9216) * 4;
    const int SM3 = (2 * 424 * 36 + 18432) * 4;
    cudaFuncSetAttribute((const void*)conv1_kernel,
                         cudaFuncAttributeMaxDynamicSharedMemorySize, SM1);
    cudaFuncSetAttribute((const void*)hmma_conv_kernel<64, 1, 32, 3, 3, 35, 35, 1, 1, 128>,
                         cudaFuncAttributeMaxDynamicSharedMemorySize, SM2);
    cudaFuncSetAttribute((const void*)hmma_conv_kernel<64, 2, 32, 3, 3, 17, 17, 1, 0, 256>,
                         cudaFuncAttributeMaxDynamicSharedMemorySize, SM3);

    // zero grid (scatter accumulates into it)
    {
        int n4 = NB * 76 * 76 * 20 / 4;
        zero_kernel<<<(n4 + 255) / 256, 256>>>((float4*)grid, n4);
    }
    // weight transforms
    {
        wtrans1_kernel<<<(26624 + 255) / 256, 256>>>(cw0, wt1);
        int n2 = 36864;  wtrans_kernel<64, 64, 1, 32, 4, 9><<<(n2 + 255) / 256, 256>>>(cw1, wt2);
        int n3 = 147456; wtrans_kernel<128, 64, 2, 32, 8, 9><<<(n3 + 255) / 256, 256>>>(cw2, wt3);
    }
    // scatter encode (half2 atomics)
    {
        int nt = NB * RNUM * 64;
        scatter_kernel<<<(nt + 255) / 256, 256>>>(X, rmap, emb, (__half2*)grid);
    }
    // conv1 + pool1 (pool writes pad frame)
    conv1_kernel<<<dim3(22, 1, NB), 256, SM1>>>(grid, wt1, cb0, c1);
    {
        int nt = NB * 37 * 37 * 16;
        pool_half_kernel<64, 72, 35, 1><<<(nt + 255) / 256, 256>>>((const uint2*)c1, (uint2*)p1);
    }
    // conv2 + pool2
    hmma_conv_kernel<64, 1, 32, 3, 3, 35, 35, 1, 1, 128>
        <<<dim3(4, 4, NB), 256, SM2>>>(p1, wt2, cb1, c2);
    {
        int nt = NB * 19 * 19 * 32;
        pool_half_kernel<128, 35, 17, 1><<<(nt + 255) / 256, 256>>>((const uint2*)c2, (uint2*)p2);
    }
    // conv3 + pool3
    hmma_conv_kernel<64, 2, 32, 3, 3, 17, 17, 1, 0, 256>
        <<<dim3(1, 8, NB), 256, SM3>>>(p2, wt3, cb2, c3);
    {
        int nt = NB * 8 * 8 * 64;
        pool_f32_kernel<256, 17, 8><<<(nt + 255) / 256, 256>>>((const float4*)c3, (float4*)p3);
    }
    // GAP + FC stack
    gap_kernel<<<(NB * 64 + 255) / 256, 256>>>((const float4*)p3, (float4*)gapb);
    fc_kernel<<<(NB * 512 + 255) / 256, 256>>>(gapb, fw0, fb0, f1, 256, 512, 1);
    fc_kernel<<<(NB * 256 + 255) / 256, 256>>>(f1,   fw1, fb1, f2, 512, 256, 1);
    fc_kernel<<<(NB * 512 + 255) / 256, 256>>>(f2,   fw2, fb2, out, 256, 512, 0);
}

// round 10
// speedup vs baseline: 8.2029x; 1.0192x over previous
#include <cuda_runtime.h>
#include <cuda_fp16.h>
#include <stdint.h>

// ---------------- problem constants ----------------
#define NB   128
#define RNUM 300
#define EMB  32

// ---------------- buffers ----------------
// grid: half NHWC [n][76][76][40]: ch0-31 = emb, ch32 = occupancy, 33-39 pad
__device__ unsigned g_grid[NB * 76 * 76 * 20];   // half2 words
__device__ unsigned g_c1 [NB * 72 * 72 * 32];    // conv1 out half2 (64ch)
__device__ unsigned g_p1 [NB * 37 * 37 * 32];    // pool1 half2 (pad1)
__device__ unsigned g_c2 [NB * 35 * 35 * 64];    // conv2 out half2 (128ch)
__device__ unsigned g_p2 [NB * 19 * 19 * 64];    // pool2 half2 (pad1)
__device__ float    g_c3 [NB * 17 * 17 * 256];   // conv3 out fp32
__device__ float    g_p3 [NB * 8 * 8 * 256];
__device__ float    g_gap[NB * 256];
__device__ float    g_f1 [NB * 512];
__device__ float    g_f2 [NB * 256];
// conv1 B: [cob2]{ emb 25*2*4*64 , occ 2*4*64 } = 2 * 13312 words
__device__ unsigned g_wt1[ 26624];
__device__ unsigned g_wt2[ 36864];               // [cob4][tap9][c16 4][nt4][64]
__device__ unsigned g_wt3[147456];               // [h2][cob8][kk9][c16 4][nt4][64]

// ---------------- helpers ----------------
__device__ __forceinline__ void mma_f16(float* d, const uint32_t* a, const uint32_t* b) {
    asm volatile(
        "mma.sync.aligned.m16n8k16.row.col.f32.f16.f16.f32 "
        "{%0,%1,%2,%3}, {%4,%5,%6,%7}, {%8,%9}, {%0,%1,%2,%3};"
        : "+f"(d[0]), "+f"(d[1]), "+f"(d[2]), "+f"(d[3])
        : "r"(a[0]), "r"(a[1]), "r"(a[2]), "r"(a[3]), "r"(b[0]), "r"(b[1]));
}
__device__ __forceinline__ void ldsm_x4(uint32_t* a, uint32_t addr) {
    asm volatile("ldmatrix.sync.aligned.m8n8.x4.shared.b16 {%0,%1,%2,%3}, [%4];"
        : "=r"(a[0]), "=r"(a[1]), "=r"(a[2]), "=r"(a[3]) : "r"(addr));
}
__device__ __forceinline__ uint32_t smem_u32(const void* p) {
    uint32_t a;
    asm("{ .reg .u64 t; cvta.to.shared.u64 t, %1; cvt.u32.u64 %0, t; }" : "=r"(a) : "l"(p));
    return a;
}
__device__ __forceinline__ void cp_async16_s(uint32_t saddr, const void* g) {
    asm volatile("cp.async.cg.shared.global [%0], [%1], 16;" :: "r"(saddr), "l"(g));
}
__device__ __forceinline__ void cp_async16_z(uint32_t saddr, const void* g, uint32_t srcsz) {
    asm volatile("cp.async.cg.shared.global [%0], [%1], 16, %2;"
                 :: "r"(saddr), "l"(g), "r"(srcsz));
}
__device__ __forceinline__ uint32_t f2h2(float a, float b) {
    __half2 h = __float22half2_rn(make_float2(a, b));
    return *(uint32_t*)&h;
}

// ---------------- zero fill ----------------
__global__ void zero_kernel(float4* __restrict__ p, int n4) {
    int i = blockIdx.x * blockDim.x + threadIdx.x;
    if (i < n4) p[i] = make_float4(0.f, 0.f, 0.f, 0.f);
}

// ---------------- scatter rooms into half grid (half2 atomics) --------------
__global__ void scatter_kernel(const int* __restrict__ X,
                               const int* __restrict__ rm,
                               const float* __restrict__ emb,
                               __half2* __restrict__ grid) {
    int idx = blockIdx.x * blockDim.x + threadIdx.x;
    if (idx >= NB * RNUM * 64) return;
    int cell = idx & 63;
    int r    = (idx >> 6) % RNUM;
    int n    = idx / (RNUM * 64);
    if (!rm[r * 64 + cell]) return;
    int cx = cell >> 3, cy = cell & 7;
    int px = X[(n * RNUM + r) * 2 + 0];
    int py = X[(n * RNUM + r) * 2 + 1];
    int Y = py + cy + 2, Xc = px + cx + 2;
    __half2* base = grid + (((size_t)n * 76 + Y) * 76 + Xc) * 20;
    const float* er = emb + r * EMB;
#pragma unroll
    for (int w = 0; w < 16; ++w)
        atomicAdd(base + w, __float22half2_rn(make_float2(er[2 * w], er[2 * w + 1])));
    atomicAdd(base + 16, __float22half2_rn(make_float2(1.f, 0.f)));   // occupancy ch32
}

// ------- conv1 weight transform: [cob2]{ emb[tap25][c16 2][nt4][64], occ[g2][nt4][64] }
__global__ void wtrans1_kernel(const float* __restrict__ w, unsigned* __restrict__ wt) {
    int i = blockIdx.x * blockDim.x + threadIdx.x;
    if (i >= 26624) return;
    int cob = i / 13312;
    int j   = i % 13312;
    int which = j & 1;
    int lane  = (j >> 1) & 31;
    int ac = lane & 3, ar = lane >> 2;
    if (j < 12800) {
        int r  = j >> 6;
        int nt = r % 4;  r /= 4;
        int c16 = r % 2;
        int tap = r / 2;
        int kl  = c16 * 16 + ac * 2 + which * 8;
        int co  = cob * 32 + nt * 8 + ar;
        float v0 = w[((size_t)co * 33 + 1 + kl) * 25 + tap];
        float v1 = w[((size_t)co * 33 + 2 + kl) * 25 + tap];
        wt[i] = f2h2(v0, v1);
    } else {
        int jj = j - 12800;
        int r2 = jj >> 6;
        int nt = r2 % 4;
        int g  = r2 / 4;
        int kl = g * 16 + ac * 2 + which * 8;
        int co = cob * 32 + nt * 8 + ar;
        float v0 = (kl     < 25) ? w[((size_t)co * 33) * 25 + kl]     : 0.f;
        float v1 = (kl + 1 < 25) ? w[((size_t)co * 33) * 25 + kl + 1] : 0.f;
        wt[i] = f2h2(v0, v1);
    }
}

// ------- conv2 weight transform: [cob4][kk9][c16 4][nt4][64] -----------------
__global__ void wtrans2_kernel(const float* __restrict__ w, unsigned* __restrict__ wt) {
    int i = blockIdx.x * blockDim.x + threadIdx.x;
    if (i >= 36864) return;
    int which = i & 1;
    int lane  = (i >> 1) & 31;
    int r     = i >> 6;
    int nt  = r % 4;  r /= 4;
    int c16 = r % 4;  r /= 4;
    int kk  = r % 9;
    int cob = r / 9;
    int ac = lane & 3, ar = lane >> 2;
    int ci0 = c16 * 16 + ac * 2 + which * 8;
    int co  = cob * 32 + nt * 8 + ar;
    float v0 = w[((size_t)co * 64 + ci0)     * 9 + kk];
    float v1 = w[((size_t)co * 64 + ci0 + 1) * 9 + kk];
    wt[i] = f2h2(v0, v1);
}

// ------- conv3 weight transform: [h2][cob8][kk9][c16 4][nt4][64] -------------
__global__ void wtrans3_kernel(const float* __restrict__ w, unsigned* __restrict__ wt) {
    int i = blockIdx.x * blockDim.x + threadIdx.x;
    if (i >= 147456) return;
    int which = i & 1;
    int lane  = (i >> 1) & 31;
    int r     = i >> 6;
    int nt  = r % 4;  r /= 4;
    int c16 = r % 4;  r /= 4;
    int kk  = r % 9;  r /= 9;
    int cob = r % 8;
    int h   = r / 8;
    int ac = lane & 3, ar = lane >> 2;
    int ci0 = h * 64 + c16 * 16 + ac * 2 + which * 8;
    int co  = cob * 32 + nt * 8 + ar;
    float v0 = w[((size_t)co * 128 + ci0)     * 9 + kk];
    float v1 = w[((size_t)co * 128 + ci0 + 1) * 9 + kk];
    wt[i] = f2h2(v0, v1);
}

// ---------------- conv1: NCO=32, 192thr, 2 blocks/SM -------------------------
__global__ void __launch_bounds__(192, 2)
conv1_kernel(const unsigned* __restrict__ in, const unsigned* __restrict__ wt,
             const float* __restrict__ bias, unsigned* __restrict__ out) {
    constexpr int MT = 2, NT = 4, NTHR = 192;
    constexpr int MPIX = 192;
    constexpr int W = 72, PAD = 2, Wp = 76, NPIX = 76 * 76;
    constexpr int HALO = PAD * Wp + PAD;              // 154
    constexpr int AWIN = MPIX + 2 * HALO;             // 500
    constexpr int ASTE = 20;
    constexpr int ASTI = 20;
    constexpr int AEW  = AWIN * ASTE;                 // 10000
    constexpr int IMW  = MPIX * ASTI;                 // 3840
    constexpr int OCW  = 256;
    constexpr int BW   = 13312;                       // per cob

    extern __shared__ uint32_t sm[];
    uint32_t* sAe = sm;
    uint32_t* sIm = sm + AEW;
    __half*   sOc = (__half*)(sm + AEW + IMW);
    uint32_t* sB  = sm + AEW + IMW + OCW;

    const int tid  = threadIdx.x;
    const int warp = tid >> 5, lane = tid & 31;
    const int ar   = lane >> 2, ac = lane & 3;
    const int n    = blockIdx.z;
    const int cob  = blockIdx.y;
    const int p0   = HALO + blockIdx.x * MPIX;
    const int s0   = p0 - HALO;
    const int wrow = warp * (16 * MT);

    // ---- B + emb A via cp.async (zfill OOB rows) ----
    {
        const unsigned* wsrc = wt + (size_t)cob * BW;
        uint32_t sBu = smem_u32(sB);
        for (int c = tid; c < BW / 4; c += NTHR)
            cp_async16_s(sBu + c * 16, wsrc + c * 4);
        const unsigned* inb = in + (size_t)n * NPIX * 20;
        uint32_t sAu = smem_u32(sAe);
        for (int e = tid; e < AWIN * 4; e += NTHR) {
            int row = e >> 2, c = e & 3;
            int pix = s0 + row;
            cp_async16_z(sAu + (uint32_t)((row * ASTE + c * 4) * 4),
                         inb + (size_t)pix * 20 + c * 4,
                         (pix < NPIX) ? 16u : 0u);
        }
        asm volatile("cp.async.commit_group;" ::: "memory");
    }
    // ---- occ raw staging ----
    {
        const unsigned* inw = in + (size_t)n * NPIX * 20;
        for (int row = tid; row < AWIN; row += NTHR) {
            int pix = s0 + row;
            uint32_t v = (pix < NPIX) ? inw[(size_t)pix * 20 + 16] : 0u;
            sOc[row] = *(__half*)&v;
        }
    }
    __syncthreads();
    // ---- build occ im2col ----
    {
        __half* imh = (__half*)sIm;
        for (int e = tid; e < MPIX * 16; e += NTHR) {
            int rr = e >> 4, w2 = e & 15;
            int k0 = 2 * w2, k1 = 2 * w2 + 1;
            __half h0 = __float2half(0.f), h1 = h0;
            if (k0 < 25) {
                int sh = (k0 / 5 - 2) * Wp + (k0 % 5) - 2;
                h0 = sOc[rr + HALO + sh];
            }
            if (k1 < 25) {
                int sh = (k1 / 5 - 2) * Wp + (k1 % 5) - 2;
                h1 = sOc[rr + HALO + sh];
            }
            imh[(rr * ASTI) * 2 + 2 * w2]     = h0;
            imh[(rr * ASTI) * 2 + 2 * w2 + 1] = h1;
        }
    }
    asm volatile("cp.async.wait_group 0;" ::: "memory");
    __syncthreads();

    float d[MT][NT][4];
#pragma unroll
    for (int mt = 0; mt < MT; ++mt)
#pragma unroll
        for (int nt = 0; nt < NT; ++nt)
#pragma unroll
            for (int q = 0; q < 4; ++q) d[mt][nt][q] = 0.f;

    const uint32_t a_off0 = smem_u32(sAe) +
        (uint32_t)(((HALO + wrow + (lane & 15)) * ASTE + ((lane >> 4) << 2)) * 4);
    const uint32_t i_off0 = smem_u32(sIm) +
        (uint32_t)(((wrow + (lane & 15)) * ASTI + ((lane >> 4) << 2)) * 4);

    for (int tap = 0; tap < 25; ++tap) {
        int shift = (tap / 5 - PAD) * Wp + (tap % 5) - PAD;
        uint32_t abase = a_off0 + (uint32_t)(shift * (ASTE * 4));
        const uint2* btap = (const uint2*)sB + (size_t)tap * 256 + lane;
#pragma unroll
        for (int c16 = 0; c16 < 2; ++c16) {
            uint2 bf[NT];
#pragma unroll
            for (int nt = 0; nt < NT; ++nt)
                bf[nt] = btap[(c16 * NT + nt) * 32];
#pragma unroll
            for (int mt = 0; mt < MT; ++mt) {
                uint32_t af[4];
                ldsm_x4(af, abase + (uint32_t)((mt * 16 * ASTE + c16 * 8) * 4));
#pragma unroll
                for (int nt = 0; nt < NT; ++nt)
                    mma_f16(d[mt][nt], af, (const uint32_t*)&bf[nt]);
            }
        }
    }
    {
        const uint2* btap = (const uint2*)(sB + 12800) + lane;
#pragma unroll
        for (int g = 0; g < 2; ++g) {
            uint2 bf[NT];
#pragma unroll
            for (int nt = 0; nt < NT; ++nt)
                bf[nt] = btap[(g * NT + nt) * 32];
#pragma unroll
            for (int mt = 0; mt < MT; ++mt) {
                uint32_t af[4];
                ldsm_x4(af, i_off0 + (uint32_t)((mt * 16 * ASTI + g * 8) * 4));
#pragma unroll
                for (int nt = 0; nt < NT; ++nt)
                    mma_f16(d[mt][nt], af, (const uint32_t*)&bf[nt]);
            }
        }
    }

    float2 bv[NT];
#pragma unroll
    for (int nt = 0; nt < NT; ++nt)
        bv[nt] = *(const float2*)(bias + cob * 32 + nt * 8 + 2 * ac);
#pragma unroll
    for (int mt = 0; mt < MT; ++mt) {
#pragma unroll
        for (int half = 0; half < 2; ++half) {
            int p = p0 + wrow + mt * 16 + half * 8 + ar;
            int y = p / Wp - PAD, x = p % Wp - PAD;
            if (x >= 0 && x < W && y < W) {
                uint32_t* ob = out + (((size_t)n * W + y) * W + x) * 32 + cob * 16 + ac;
#pragma unroll
                for (int nt = 0; nt < NT; ++nt) {
                    float vx = fmaxf(d[mt][nt][half * 2 + 0] + bv[nt].x, 0.f);
                    float vy = fmaxf(d[mt][nt][half * 2 + 1] + bv[nt].y, 0.f);
                    ob[nt * 4] = f2h2(vx, vy);
                }
            }
        }
    }
}

// ---------------- generic fp16 mma conv (conv2 / conv3 passes) ---------------
// MODE: 0 = half out, bias+relu ; 1 = f32 raw store ; 2 = f32 accum+bias+relu
template<int NCO, int MT, int K, int H, int W, int PAD, int MODE,
         int CO_TOTAL, int CIN_STR8, int CH_OFF8>
__global__ void __launch_bounds__(256, 2)
hmma_conv_kernel(const void* __restrict__ in_, const unsigned* __restrict__ wt,
                 const float* __restrict__ bias, void* __restrict__ out_) {
    constexpr int CINH  = 64;
    constexpr int NT    = NCO / 8;
    constexpr int NC16  = CINH / 16;
    constexpr int TAPS  = K * K;
    constexpr int MPIX  = 8 * 16 * MT;
    constexpr int Wp    = W + 2 * PAD, Hp = H + 2 * PAD;
    constexpr int NPIX  = Wp * Hp;
    constexpr int HALO  = PAD * Wp + PAD;
    constexpr int AWIN  = MPIX + 2 * HALO;
    constexpr int AST2  = CINH / 2 + 4;
    constexpr int AWORDS = AWIN * AST2;
    constexpr int BWORDS = TAPS * NC16 * NT * 64;

    extern __shared__ uint32_t sm[];
    uint32_t* sA = sm;
    uint32_t* sB = sm + AWORDS;

    const int tid  = threadIdx.x;
    const int warp = tid >> 5, lane = tid & 31;
    const int ar   = lane >> 2, ac = lane & 3;
    const int n    = blockIdx.z;
    const int cob  = blockIdx.y;
    const int co0  = cob * NCO;
    const int p0   = HALO + blockIdx.x * MPIX;
    const int s0   = p0 - HALO;
    const int wrow = warp * (16 * MT);

    {
        const unsigned* wsrc = wt + (size_t)cob * BWORDS;
        uint32_t sBu = smem_u32(sB);
        for (int c = tid; c < BWORDS / 4; c += 256)
            cp_async16_s(sBu + c * 16, wsrc + c * 4);
        const uint4* inb = (const uint4*)in_ + (size_t)n * NPIX * CIN_STR8 + CH_OFF8;
        uint32_t sAu = smem_u32(sA);
        for (int e = tid; e < AWIN * 8; e += 256) {
            int row = e >> 3, c = e & 7;
            int pix = s0 + row;
            cp_async16_z(sAu + (uint32_t)((row * AST2 + c * 4) * 4),
                         inb + (size_t)pix * CIN_STR8 + c,
                         (pix < NPIX) ? 16u : 0u);
        }
        asm volatile("cp.async.commit_group;" ::: "memory");
    }
    asm volatile("cp.async.wait_group 0;" ::: "memory");
    __syncthreads();

    float d[MT][NT][4];
#pragma unroll
    for (int mt = 0; mt < MT; ++mt)
#pragma unroll
        for (int nt = 0; nt < NT; ++nt)
#pragma unroll
            for (int q = 0; q < 4; ++q) d[mt][nt][q] = 0.f;

    const uint32_t a_off0 = smem_u32(sA) +
        (uint32_t)(((HALO + wrow + (lane & 15)) * AST2 + ((lane >> 4) << 2)) * 4);

    for (int tap = 0; tap < TAPS; ++tap) {
        int shift = (tap / K - PAD) * Wp + (tap % K) - PAD;
        uint32_t abase = a_off0 + (uint32_t)(shift * (AST2 * 4));
        const uint2* btap = (const uint2*)sB + (size_t)tap * (NC16 * NT * 32) + lane;
#pragma unroll
        for (int c16 = 0; c16 < NC16; ++c16) {
            uint2 bf[NT];
#pragma unroll
            for (int nt = 0; nt < NT; ++nt)
                bf[nt] = btap[(c16 * NT + nt) * 32];
#pragma unroll
            for (int mt = 0; mt < MT; ++mt) {
                uint32_t af[4];
                ldsm_x4(af, abase + (uint32_t)((mt * 16 * AST2 + c16 * 8) * 4));
#pragma unroll
                for (int nt = 0; nt < NT; ++nt)
                    mma_f16(d[mt][nt], af, (const uint32_t*)&bf[nt]);
            }
        }
    }

    float2 bv[NT];
#pragma unroll
    for (int nt = 0; nt < NT; ++nt)
        bv[nt] = *(const float2*)(bias + co0 + nt * 8 + 2 * ac);

#pragma unroll
    for (int mt = 0; mt < MT; ++mt) {
#pragma unroll
        for (int half = 0; half < 2; ++half) {
            int p = p0 + wrow + mt * 16 + half * 8 + ar;
            int y = p / Wp - PAD, x = p % Wp - PAD;
            if (x >= 0 && x < W && y < H) {
                size_t pix = ((size_t)n * H + y) * W + x;
                if (MODE == 0) {
                    uint32_t* ob = (uint32_t*)out_ + pix * (CO_TOTAL / 2) + co0 / 2 + ac;
#pragma unroll
                    for (int nt = 0; nt < NT; ++nt) {
                        float vx = fmaxf(d[mt][nt][half * 2 + 0] + bv[nt].x, 0.f);
                        float vy = fmaxf(d[mt][nt][half * 2 + 1] + bv[nt].y, 0.f);
                        ob[nt * 4] = f2h2(vx, vy);
                    }
                } else if (MODE == 1) {
                    float* ob = (float*)out_ + pix * CO_TOTAL + co0 + 2 * ac;
#pragma unroll
                    for (int nt = 0; nt < NT; ++nt) {
                        float2 v;
                        v.x = d[mt][nt][half * 2 + 0];
                        v.y = d[mt][nt][half * 2 + 1];
                        *(float2*)(ob + nt * 8) = v;
                    }
                } else {
                    float* ob = (float*)out_ + pix * CO_TOTAL + co0 + 2 * ac;
#pragma unroll
                    for (int nt = 0; nt < NT; ++nt) {
                        float2 prev = *(float2*)(ob + nt * 8);
                        float2 v;
                        v.x = fmaxf(prev.x + d[mt][nt][half * 2 + 0] + bv[nt].x, 0.f);
                        v.y = fmaxf(prev.y + d[mt][nt][half * 2 + 1] + bv[nt].y, 0.f);
                        *(float2*)(ob + nt * 8) = v;
                    }
                }
            }
        }
    }
}

// ---------------- pools (write own pad frame) / gap / fc ----------------
template<int C, int HI, int HO, int P>
__global__ void pool_half_kernel(const uint2* __restrict__ in, uint2* __restrict__ out) {
    constexpr int C4 = C / 4, HOP = HO + 2 * P;
    int idx = blockIdx.x * blockDim.x + threadIdx.x;
    if (idx >= NB * HOP * HOP * C4) return;
    int c  = idx % C4;
    int ox = (idx / C4) % HOP;
    int oy = (idx / (C4 * HOP)) % HOP;
    int n  = idx / (C4 * HOP * HOP);
    uint2 r;
    if (ox < P || ox >= HO + P || oy < P || oy >= HO + P) {
        r = make_uint2(0u, 0u);
    } else {
        const uint2* p = in + (((size_t)n * HI + 2 * (oy - P)) * HI + 2 * (ox - P)) * C4 + c;
        uint2 m0 = p[0];
        __half2 ma = *(__half2*)&m0.x, mb = *(__half2*)&m0.y;
#pragma unroll
        for (int dy = 0; dy < 3; ++dy)
#pragma unroll
            for (int dx = 0; dx < 3; ++dx) {
                uint2 q = p[((size_t)dy * HI + dx) * C4];
                ma = __hmax2(ma, *(__half2*)&q.x);
                mb = __hmax2(mb, *(__half2*)&q.y);
            }
        r.x = *(uint32_t*)&ma; r.y = *(uint32_t*)&mb;
    }
    out[(((size_t)n * HOP + oy) * HOP + ox) * C4 + c] = r;
}

template<int C, int HI, int HO>
__global__ void pool_f32_kernel(const float4* __restrict__ in, float4* __restrict__ out) {
    constexpr int C4 = C / 4;
    int idx = blockIdx.x * blockDim.x + threadIdx.x;
    if (idx >= NB * HO * HO * C4) return;
    int c  = idx % C4;
    int ox = (idx / C4) % HO;
    int oy = (idx / (C4 * HO)) % HO;
    int n  = idx / (C4 * HO * HO);
    const float4* p = in + (((size_t)n * HI + 2 * oy) * HI + 2 * ox) * C4 + c;
    float4 m = p[0];
#pragma unroll
    for (int dy = 0; dy < 3; ++dy)
#pragma unroll
        for (int dx = 0; dx < 3; ++dx) {
            float4 q = p[((size_t)dy * HI + dx) * C4];
            m.x = fmaxf(m.x, q.x); m.y = fmaxf(m.y, q.y);
            m.z = fmaxf(m.z, q.z); m.w = fmaxf(m.w, q.w);
        }
    out[(((size_t)n * HO + oy) * HO + ox) * C4 + c] = m;
}

__global__ void gap_kernel(const float4* __restrict__ in, float4* __restrict__ out) {
    int idx = blockIdx.x * blockDim.x + threadIdx.x;
    if (idx >= NB * 64) return;
    int n = idx >> 6, c = idx & 63;
    const float4* p = in + (size_t)n * 64 * 64 + c;
    float4 s = make_float4(0.f, 0.f, 0.f, 0.f);
#pragma unroll
    for (int i = 0; i < 64; ++i) {
        float4 q = p[i * 64];
        s.x += q.x; s.y += q.y; s.z += q.z; s.w += q.w;
    }
    s.x *= (1.f/64.f); s.y *= (1.f/64.f); s.z *= (1.f/64.f); s.w *= (1.f/64.f);
    out[idx] = s;
}

__global__ void fc_kernel(const float* __restrict__ in, const float* __restrict__ w,
                          const float* __restrict__ b, float* __restrict__ out,
                          int K_, int O_, int relu) {
    int idx = blockIdx.x * blockDim.x + threadIdx.x;
    if (idx >= NB * O_) return;
    int n = idx / O_, o = idx % O_;
    const float4* ip = (const float4*)(in + (size_t)n * K_);
    const float4* wp = (const float4*)(w + (size_t)o * K_);
    float s = b[o];
    int k4 = K_ >> 2;
#pragma unroll 4
    for (int k = 0; k < k4; ++k) {
        float4 a = ip[k], ww = wp[k];
        s = fmaf(a.x, ww.x, s); s = fmaf(a.y, ww.y, s);
        s = fmaf(a.z, ww.z, s); s = fmaf(a.w, ww.w, s);
    }
    if (relu) s = fmaxf(s, 0.f);
    out[idx] = s;
}

// ---------------- launch ----------------
extern "C" void kernel_launch(void* const* d_in, const int* in_sizes, int n_in,
                              void* d_out, int out_size) {
    const int*   X    = (const int*)  d_in[0];
    const int*   rmap = (const int*)  d_in[1];
    const float* emb  = (const float*)d_in[2];
    const float* cw0  = (const float*)d_in[3];
    const float* cb0  = (const float*)d_in[4];
    const float* cw1  = (const float*)d_in[5];
    const float* cb1  = (const float*)d_in[6];
    const float* cw2  = (const float*)d_in[7];
    const float* cb2  = (const float*)d_in[8];
    const float* fw0  = (const float*)d_in[9];
    const float* fb0  = (const float*)d_in[10];
    const float* fw1  = (const float*)d_in[11];
    const float* fb1  = (const float*)d_in[12];
    const float* fw2  = (const float*)d_in[13];
    const float* fb2  = (const float*)d_in[14];
    float* out = (float*)d_out;

    float *c3, *p3, *gapb, *f1, *f2;
    unsigned *grid, *c1, *p1, *c2, *p2, *wt1, *wt2, *wt3;
    cudaGetSymbolAddress((void**)&grid, g_grid);
    cudaGetSymbolAddress((void**)&c1,  g_c1);
    cudaGetSymbolAddress((void**)&p1,  g_p1);
    cudaGetSymbolAddress((void**)&c2,  g_c2);
    cudaGetSymbolAddress((void**)&p2,  g_p2);
    cudaGetSymbolAddress((void**)&c3,  g_c3);
    cudaGetSymbolAddress((void**)&p3,  g_p3);
    cudaGetSymbolAddress((void**)&gapb, g_gap);
    cudaGetSymbolAddress((void**)&f1,  g_f1);
    cudaGetSymbolAddress((void**)&f2,  g_f2);
    cudaGetSymbolAddress((void**)&wt1, g_wt1);
    cudaGetSymbolAddress((void**)&wt2, g_wt2);
    cudaGetSymbolAddress((void**)&wt3, g_wt3);

    // smem (bytes):
    // conv1: (10000 + 3840 + 256 + 13312)*4 = 109,632  -> 2 blocks/SM
    // conv2: ((384+76)*36 + 9216)*4         = 103,104  -> 2 blocks/SM
    // conv3 pass: ((384+40)*36 + 9216)*4    =  97,920  -> 2 blocks/SM
    const int SM1 = (10000 + 3840 + 256 + 13312) * 4;
    const int SM2 = (460 * 36 + 9216) * 4;
    const int SM3 = (424 * 36 + 9216) * 4;
    cudaFuncSetAttribute((const void*)conv1_kernel,
                         cudaFuncAttributeMaxDynamicSharedMemorySize, SM1);
    cudaFuncSetAttribute((const void*)hmma_conv_kernel<32, 3, 3, 35, 35, 1, 0, 128, 8, 0>,
                         cudaFuncAttributeMaxDynamicSharedMemorySize, SM2);
    cudaFuncSetAttribute((const void*)hmma_conv_kernel<32, 3, 3, 17, 17, 1, 1, 256, 16, 0>,
                         cudaFuncAttributeMaxDynamicSharedMemorySize, SM3);
    cudaFuncSetAttribute((const void*)hmma_conv_kernel<32, 3, 3, 17, 17, 1, 2, 256, 16, 8>,
                         cudaFuncAttributeMaxDynamicSharedMemorySize, SM3);

    // zero grid (scatter accumulates into it)
    {
        int n4 = NB * 76 * 76 * 20 / 4;
        zero_kernel<<<(n4 + 255) / 256, 256>>>((float4*)grid, n4);
    }
    // weight transforms
    {
        wtrans1_kernel<<<(26624 + 255) / 256, 256>>>(cw0, wt1);
        wtrans2_kernel<<<(36864 + 255) / 256, 256>>>(cw1, wt2);
        wtrans3_kernel<<<(147456 + 255) / 256, 256>>>(cw2, wt3);
    }
    // scatter encode (half2 atomics)
    {
        int nt = NB * RNUM * 64;
        scatter_kernel<<<(nt + 255) / 256, 256>>>(X, rmap, emb, (__half2*)grid);
    }
    // conv1 + pool1
    conv1_kernel<<<dim3(29, 2, NB), 192, SM1>>>(grid, wt1, cb0, c1);
    {
        int nt = NB * 37 * 37 * 16;
        pool_half_kernel<64, 72, 35, 1><<<(nt + 255) / 256, 256>>>((const uint2*)c1, (uint2*)p1);
    }
    // conv2 + pool2
    hmma_conv_kernel<32, 3, 3, 35, 35, 1, 0, 128, 8, 0>
        <<<dim3(4, 4, NB), 256, SM2>>>(p1, wt2, cb1, c2);
    {
        int nt = NB * 19 * 19 * 32;
        pool_half_kernel<128, 35, 17, 1><<<(nt + 255) / 256, 256>>>((const uint2*)c2, (uint2*)p2);
    }
    // conv3: two ci-half passes (raw write, then accumulate+bias+relu)
    hmma_conv_kernel<32, 3, 3, 17, 17, 1, 1, 256, 16, 0>
        <<<dim3(1, 8, NB), 256, SM3>>>(p2, wt3, cb2, c3);
    hmma_conv_kernel<32, 3, 3, 17, 17, 1, 2, 256, 16, 8>
        <<<dim3(1, 8, NB), 256, SM3>>>(p2, wt3 + 73728, cb2, c3);
    {
        int nt = NB * 8 * 8 * 64;
        pool_f32_kernel<256, 17, 8><<<(nt + 255) / 256, 256>>>((const float4*)c3, (float4*)p3);
    }
    // GAP + FC stack
    gap_kernel<<<(NB * 64 + 255) / 256, 256>>>((const float4*)p3, (float4*)gapb);
    fc_kernel<<<(NB * 512 + 255) / 256, 256>>>(gapb, fw0, fb0, f1, 256, 512, 1);
    fc_kernel<<<(NB * 256 + 255) / 256, 256>>>(f1,   fw1, fb1, f2, 512, 256, 1);
    fc_kernel<<<(NB * 512 + 255) / 256, 256>>>(f2,   fw2, fb2, out, 256, 512, 0);
}

// round 11
// speedup vs baseline: 8.4236x; 1.0269x over previous
#include <cuda_runtime.h>
#include <cuda_fp16.h>
#include <stdint.h>

// ---------------- problem constants ----------------
#define NB   128
#define RNUM 300
#define EMB  32

// ---------------- buffers ----------------
// grid: half NHWC [n][76][76][40]: ch0-31 = emb, ch32 = occupancy, 33-39 pad
__device__ unsigned g_grid[NB * 76 * 76 * 20];   // half2 words
__device__ unsigned g_c1 [NB * 72 * 72 * 32];    // conv1 out half2 (64ch)
__device__ unsigned g_p1 [NB * 37 * 37 * 32];    // pool1 half2 (pad1)
__device__ unsigned g_c2 [NB * 35 * 35 * 64];    // conv2 out half2 (128ch)
__device__ unsigned g_p2 [NB * 19 * 19 * 64];    // pool2 half2 (pad1)
__device__ float    g_c3 [NB * 17 * 17 * 256];   // conv3 partial (ci 0..63) fp32
__device__ float    g_gap[NB * 256];
__device__ float    g_f1 [NB * 512];
__device__ float    g_f2 [NB * 256];
// conv1 B: [cob2]{ emb 25*2*4*64 , occ 2*4*64 } = 2 * 13312 words
__device__ unsigned g_wt1[ 26624];
__device__ unsigned g_wt2[ 36864];               // [cob4][tap9][c16 4][nt4][64]
__device__ unsigned g_wt3[147456];               // [h2][cob8][kk9][c16 4][nt4][64]

// ---------------- helpers ----------------
__device__ __forceinline__ void mma_f16(float* d, const uint32_t* a, const uint32_t* b) {
    asm volatile(
        "mma.sync.aligned.m16n8k16.row.col.f32.f16.f16.f32 "
        "{%0,%1,%2,%3}, {%4,%5,%6,%7}, {%8,%9}, {%0,%1,%2,%3};"
        : "+f"(d[0]), "+f"(d[1]), "+f"(d[2]), "+f"(d[3])
        : "r"(a[0]), "r"(a[1]), "r"(a[2]), "r"(a[3]), "r"(b[0]), "r"(b[1]));
}
__device__ __forceinline__ void ldsm_x4(uint32_t* a, uint32_t addr) {
    asm volatile("ldmatrix.sync.aligned.m8n8.x4.shared.b16 {%0,%1,%2,%3}, [%4];"
        : "=r"(a[0]), "=r"(a[1]), "=r"(a[2]), "=r"(a[3]) : "r"(addr));
}
__device__ __forceinline__ uint32_t smem_u32(const void* p) {
    uint32_t a;
    asm("{ .reg .u64 t; cvta.to.shared.u64 t, %1; cvt.u32.u64 %0, t; }" : "=r"(a) : "l"(p));
    return a;
}
__device__ __forceinline__ void cp_async16_s(uint32_t saddr, const void* g) {
    asm volatile("cp.async.cg.shared.global [%0], [%1], 16;" :: "r"(saddr), "l"(g));
}
__device__ __forceinline__ void cp_async16_z(uint32_t saddr, const void* g, uint32_t srcsz) {
    asm volatile("cp.async.cg.shared.global [%0], [%1], 16, %2;"
                 :: "r"(saddr), "l"(g), "r"(srcsz));
}
__device__ __forceinline__ uint32_t f2h2(float a, float b) {
    __half2 h = __float22half2_rn(make_float2(a, b));
    return *(uint32_t*)&h;
}

// ---------------- zero fill ----------------
__global__ void zero_kernel(float4* __restrict__ p, int n4) {
    int i = blockIdx.x * blockDim.x + threadIdx.x;
    if (i < n4) p[i] = make_float4(0.f, 0.f, 0.f, 0.f);
}

// ---------------- scatter rooms into half grid (half2 atomics) --------------
__global__ void scatter_kernel(const int* __restrict__ X,
                               const int* __restrict__ rm,
                               const float* __restrict__ emb,
                               __half2* __restrict__ grid) {
    int idx = blockIdx.x * blockDim.x + threadIdx.x;
    if (idx >= NB * RNUM * 64) return;
    int cell = idx & 63;
    int r    = (idx >> 6) % RNUM;
    int n    = idx / (RNUM * 64);
    if (!rm[r * 64 + cell]) return;
    int cx = cell >> 3, cy = cell & 7;
    int px = X[(n * RNUM + r) * 2 + 0];
    int py = X[(n * RNUM + r) * 2 + 1];
    int Y = py + cy + 2, Xc = px + cx + 2;
    __half2* base = grid + (((size_t)n * 76 + Y) * 76 + Xc) * 20;
    const float* er = emb + r * EMB;
#pragma unroll
    for (int w = 0; w < 16; ++w)
        atomicAdd(base + w, __float22half2_rn(make_float2(er[2 * w], er[2 * w + 1])));
    atomicAdd(base + 16, __float22half2_rn(make_float2(1.f, 0.f)));   // occupancy ch32
}

// ------- fused weight transform (all three convs, one launch) ---------------
__global__ void wtrans_all_kernel(const float* __restrict__ w0,
                                  const float* __restrict__ w1,
                                  const float* __restrict__ w2,
                                  unsigned* __restrict__ wt1,
                                  unsigned* __restrict__ wt2,
                                  unsigned* __restrict__ wt3) {
    int i = blockIdx.x * blockDim.x + threadIdx.x;
    if (i < 26624) {
        // conv1: [cob2]{ emb[tap25][c16 2][nt4][64], occ[g2][nt4][64] }
        int cob = i / 13312;
        int j   = i % 13312;
        int which = j & 1;
        int lane  = (j >> 1) & 31;
        int ac = lane & 3, ar = lane >> 2;
        if (j < 12800) {
            int r  = j >> 6;
            int nt = r % 4;  r /= 4;
            int c16 = r % 2;
            int tap = r / 2;
            int kl  = c16 * 16 + ac * 2 + which * 8;
            int co  = cob * 32 + nt * 8 + ar;
            float v0 = w0[((size_t)co * 33 + 1 + kl) * 25 + tap];
            float v1 = w0[((size_t)co * 33 + 2 + kl) * 25 + tap];
            wt1[i] = f2h2(v0, v1);
        } else {
            int jj = j - 12800;
            int r2 = jj >> 6;
            int nt = r2 % 4;
            int g  = r2 / 4;
            int kl = g * 16 + ac * 2 + which * 8;
            int co = cob * 32 + nt * 8 + ar;
            float v0 = (kl     < 25) ? w0[((size_t)co * 33) * 25 + kl]     : 0.f;
            float v1 = (kl + 1 < 25) ? w0[((size_t)co * 33) * 25 + kl + 1] : 0.f;
            wt1[i] = f2h2(v0, v1);
        }
    } else if (i < 26624 + 36864) {
        // conv2: [cob4][kk9][c16 4][nt4][64]
        int j = i - 26624;
        int which = j & 1;
        int lane  = (j >> 1) & 31;
        int r     = j >> 6;
        int nt  = r % 4;  r /= 4;
        int c16 = r % 4;  r /= 4;
        int kk  = r % 9;
        int cob = r / 9;
        int ac = lane & 3, ar = lane >> 2;
        int ci0 = c16 * 16 + ac * 2 + which * 8;
        int co  = cob * 32 + nt * 8 + ar;
        float v0 = w1[((size_t)co * 64 + ci0)     * 9 + kk];
        float v1 = w1[((size_t)co * 64 + ci0 + 1) * 9 + kk];
        wt2[j] = f2h2(v0, v1);
    } else if (i < 26624 + 36864 + 147456) {
        // conv3: [h2][cob8][kk9][c16 4][nt4][64]
        int j = i - 26624 - 36864;
        int which = j & 1;
        int lane  = (j >> 1) & 31;
        int r     = j >> 6;
        int nt  = r % 4;  r /= 4;
        int c16 = r % 4;  r /= 4;
        int kk  = r % 9;  r /= 9;
        int cob = r % 8;
        int h   = r / 8;
        int ac = lane & 3, ar = lane >> 2;
        int ci0 = h * 64 + c16 * 16 + ac * 2 + which * 8;
        int co  = cob * 32 + nt * 8 + ar;
        float v0 = w2[((size_t)co * 128 + ci0)     * 9 + kk];
        float v1 = w2[((size_t)co * 128 + ci0 + 1) * 9 + kk];
        wt3[j] = f2h2(v0, v1);
    }
}

// ---------------- conv1: NCO=32, 192thr, 2 blocks/SM -------------------------
__global__ void __launch_bounds__(192, 2)
conv1_kernel(const unsigned* __restrict__ in, const unsigned* __restrict__ wt,
             const float* __restrict__ bias, unsigned* __restrict__ out) {
    constexpr int MT = 2, NT = 4, NTHR = 192;
    constexpr int MPIX = 192;
    constexpr int W = 72, PAD = 2, Wp = 76, NPIX = 76 * 76;
    constexpr int HALO = PAD * Wp + PAD;              // 154
    constexpr int AWIN = MPIX + 2 * HALO;             // 500
    constexpr int ASTE = 20;
    constexpr int ASTI = 20;
    constexpr int AEW  = AWIN * ASTE;                 // 10000
    constexpr int IMW  = MPIX * ASTI;                 // 3840
    constexpr int OCW  = 256;
    constexpr int BW   = 13312;

    extern __shared__ uint32_t sm[];
    uint32_t* sAe = sm;
    uint32_t* sIm = sm + AEW;
    __half*   sOc = (__half*)(sm + AEW + IMW);
    uint32_t* sB  = sm + AEW + IMW + OCW;

    const int tid  = threadIdx.x;
    const int warp = tid >> 5, lane = tid & 31;
    const int ar   = lane >> 2, ac = lane & 3;
    const int n    = blockIdx.z;
    const int cob  = blockIdx.y;
    const int p0   = HALO + blockIdx.x * MPIX;
    const int s0   = p0 - HALO;
    const int wrow = warp * (16 * MT);

    {
        const unsigned* wsrc = wt + (size_t)cob * BW;
        uint32_t sBu = smem_u32(sB);
        for (int c = tid; c < BW / 4; c += NTHR)
            cp_async16_s(sBu + c * 16, wsrc + c * 4);
        const unsigned* inb = in + (size_t)n * NPIX * 20;
        uint32_t sAu = smem_u32(sAe);
        for (int e = tid; e < AWIN * 4; e += NTHR) {
            int row = e >> 2, c = e & 3;
            int pix = s0 + row;
            cp_async16_z(sAu + (uint32_t)((row * ASTE + c * 4) * 4),
                         inb + (size_t)pix * 20 + c * 4,
                         (pix < NPIX) ? 16u : 0u);
        }
        asm volatile("cp.async.commit_group;" ::: "memory");
    }
    {
        const unsigned* inw = in + (size_t)n * NPIX * 20;
        for (int row = tid; row < AWIN; row += NTHR) {
            int pix = s0 + row;
            uint32_t v = (pix < NPIX) ? inw[(size_t)pix * 20 + 16] : 0u;
            sOc[row] = *(__half*)&v;
        }
    }
    __syncthreads();
    {
        __half* imh = (__half*)sIm;
        for (int e = tid; e < MPIX * 16; e += NTHR) {
            int rr = e >> 4, w2 = e & 15;
            int k0 = 2 * w2, k1 = 2 * w2 + 1;
            __half h0 = __float2half(0.f), h1 = h0;
            if (k0 < 25) {
                int sh = (k0 / 5 - 2) * Wp + (k0 % 5) - 2;
                h0 = sOc[rr + HALO + sh];
            }
            if (k1 < 25) {
                int sh = (k1 / 5 - 2) * Wp + (k1 % 5) - 2;
                h1 = sOc[rr + HALO + sh];
            }
            imh[(rr * ASTI) * 2 + 2 * w2]     = h0;
            imh[(rr * ASTI) * 2 + 2 * w2 + 1] = h1;
        }
    }
    asm volatile("cp.async.wait_group 0;" ::: "memory");
    __syncthreads();

    float d[MT][NT][4];
#pragma unroll
    for (int mt = 0; mt < MT; ++mt)
#pragma unroll
        for (int nt = 0; nt < NT; ++nt)
#pragma unroll
            for (int q = 0; q < 4; ++q) d[mt][nt][q] = 0.f;

    const uint32_t a_off0 = smem_u32(sAe) +
        (uint32_t)(((HALO + wrow + (lane & 15)) * ASTE + ((lane >> 4) << 2)) * 4);
    const uint32_t i_off0 = smem_u32(sIm) +
        (uint32_t)(((wrow + (lane & 15)) * ASTI + ((lane >> 4) << 2)) * 4);

    for (int tap = 0; tap < 25; ++tap) {
        int shift = (tap / 5 - PAD) * Wp + (tap % 5) - PAD;
        uint32_t abase = a_off0 + (uint32_t)(shift * (ASTE * 4));
        const uint2* btap = (const uint2*)sB + (size_t)tap * 256 + lane;
#pragma unroll
        for (int c16 = 0; c16 < 2; ++c16) {
            uint2 bf[NT];
#pragma unroll
            for (int nt = 0; nt < NT; ++nt)
                bf[nt] = btap[(c16 * NT + nt) * 32];
#pragma unroll
            for (int mt = 0; mt < MT; ++mt) {
                uint32_t af[4];
                ldsm_x4(af, abase + (uint32_t)((mt * 16 * ASTE + c16 * 8) * 4));
#pragma unroll
                for (int nt = 0; nt < NT; ++nt)
                    mma_f16(d[mt][nt], af, (const uint32_t*)&bf[nt]);
            }
        }
    }
    {
        const uint2* btap = (const uint2*)(sB + 12800) + lane;
#pragma unroll
        for (int g = 0; g < 2; ++g) {
            uint2 bf[NT];
#pragma unroll
            for (int nt = 0; nt < NT; ++nt)
                bf[nt] = btap[(g * NT + nt) * 32];
#pragma unroll
            for (int mt = 0; mt < MT; ++mt) {
                uint32_t af[4];
                ldsm_x4(af, i_off0 + (uint32_t)((mt * 16 * ASTI + g * 8) * 4));
#pragma unroll
                for (int nt = 0; nt < NT; ++nt)
                    mma_f16(d[mt][nt], af, (const uint32_t*)&bf[nt]);
            }
        }
    }

    float2 bv[NT];
#pragma unroll
    for (int nt = 0; nt < NT; ++nt)
        bv[nt] = *(const float2*)(bias + cob * 32 + nt * 8 + 2 * ac);
#pragma unroll
    for (int mt = 0; mt < MT; ++mt) {
#pragma unroll
        for (int half = 0; half < 2; ++half) {
            int p = p0 + wrow + mt * 16 + half * 8 + ar;
            int y = p / Wp - PAD, x = p % Wp - PAD;
            if (x >= 0 && x < W && y < W) {
                uint32_t* ob = out + (((size_t)n * W + y) * W + x) * 32 + cob * 16 + ac;
#pragma unroll
                for (int nt = 0; nt < NT; ++nt) {
                    float vx = fmaxf(d[mt][nt][half * 2 + 0] + bv[nt].x, 0.f);
                    float vy = fmaxf(d[mt][nt][half * 2 + 1] + bv[nt].y, 0.f);
                    ob[nt * 4] = f2h2(vx, vy);
                }
            }
        }
    }
}

// ---------------- generic fp16 mma conv (conv2 / conv3 pass1) ----------------
// MODE: 0 = half out, bias+relu ; 1 = f32 raw store
template<int NCO, int MT, int K, int H, int W, int PAD, int MODE,
         int CO_TOTAL, int CIN_STR8, int CH_OFF8>
__global__ void __launch_bounds__(256, 2)
hmma_conv_kernel(const void* __restrict__ in_, const unsigned* __restrict__ wt,
                 const float* __restrict__ bias, void* __restrict__ out_) {
    constexpr int CINH  = 64;
    constexpr int NT    = NCO / 8;
    constexpr int NC16  = CINH / 16;
    constexpr int TAPS  = K * K;
    constexpr int MPIX  = 8 * 16 * MT;
    constexpr int Wp    = W + 2 * PAD, Hp = H + 2 * PAD;
    constexpr int NPIX  = Wp * Hp;
    constexpr int HALO  = PAD * Wp + PAD;
    constexpr int AWIN  = MPIX + 2 * HALO;
    constexpr int AST2  = CINH / 2 + 4;
    constexpr int AWORDS = AWIN * AST2;
    constexpr int BWORDS = TAPS * NC16 * NT * 64;

    extern __shared__ uint32_t sm[];
    uint32_t* sA = sm;
    uint32_t* sB = sm + AWORDS;

    const int tid  = threadIdx.x;
    const int warp = tid >> 5, lane = tid & 31;
    const int ar   = lane >> 2, ac = lane & 3;
    const int n    = blockIdx.z;
    const int cob  = blockIdx.y;
    const int co0  = cob * NCO;
    const int p0   = HALO + blockIdx.x * MPIX;
    const int s0   = p0 - HALO;
    const int wrow = warp * (16 * MT);

    {
        const unsigned* wsrc = wt + (size_t)cob * BWORDS;
        uint32_t sBu = smem_u32(sB);
        for (int c = tid; c < BWORDS / 4; c += 256)
            cp_async16_s(sBu + c * 16, wsrc + c * 4);
        const uint4* inb = (const uint4*)in_ + (size_t)n * NPIX * CIN_STR8 + CH_OFF8;
        uint32_t sAu = smem_u32(sA);
        for (int e = tid; e < AWIN * 8; e += 256) {
            int row = e >> 3, c = e & 7;
            int pix = s0 + row;
            cp_async16_z(sAu + (uint32_t)((row * AST2 + c * 4) * 4),
                         inb + (size_t)pix * CIN_STR8 + c,
                         (pix < NPIX) ? 16u : 0u);
        }
        asm volatile("cp.async.commit_group;" ::: "memory");
    }
    asm volatile("cp.async.wait_group 0;" ::: "memory");
    __syncthreads();

    float d[MT][NT][4];
#pragma unroll
    for (int mt = 0; mt < MT; ++mt)
#pragma unroll
        for (int nt = 0; nt < NT; ++nt)
#pragma unroll
            for (int q = 0; q < 4; ++q) d[mt][nt][q] = 0.f;

    const uint32_t a_off0 = smem_u32(sA) +
        (uint32_t)(((HALO + wrow + (lane & 15)) * AST2 + ((lane >> 4) << 2)) * 4);

    for (int tap = 0; tap < TAPS; ++tap) {
        int shift = (tap / K - PAD) * Wp + (tap % K) - PAD;
        uint32_t abase = a_off0 + (uint32_t)(shift * (AST2 * 4));
        const uint2* btap = (const uint2*)sB + (size_t)tap * (NC16 * NT * 32) + lane;
#pragma unroll
        for (int c16 = 0; c16 < NC16; ++c16) {
            uint2 bf[NT];
#pragma unroll
            for (int nt = 0; nt < NT; ++nt)
                bf[nt] = btap[(c16 * NT + nt) * 32];
#pragma unroll
            for (int mt = 0; mt < MT; ++mt) {
                uint32_t af[4];
                ldsm_x4(af, abase + (uint32_t)((mt * 16 * AST2 + c16 * 8) * 4));
#pragma unroll
                for (int nt = 0; nt < NT; ++nt)
                    mma_f16(d[mt][nt], af, (const uint32_t*)&bf[nt]);
            }
        }
    }

    float2 bv[NT];
#pragma unroll
    for (int nt = 0; nt < NT; ++nt)
        bv[nt] = *(const float2*)(bias + co0 + nt * 8 + 2 * ac);

#pragma unroll
    for (int mt = 0; mt < MT; ++mt) {
#pragma unroll
        for (int half = 0; half < 2; ++half) {
            int p = p0 + wrow + mt * 16 + half * 8 + ar;
            int y = p / Wp - PAD, x = p % Wp - PAD;
            if (x >= 0 && x < W && y < H) {
                size_t pix = ((size_t)n * H + y) * W + x;
                if (MODE == 0) {
                    uint32_t* ob = (uint32_t*)out_ + pix * (CO_TOTAL / 2) + co0 / 2 + ac;
#pragma unroll
                    for (int nt = 0; nt < NT; ++nt) {
                        float vx = fmaxf(d[mt][nt][half * 2 + 0] + bv[nt].x, 0.f);
                        float vy = fmaxf(d[mt][nt][half * 2 + 1] + bv[nt].y, 0.f);
                        ob[nt * 4] = f2h2(vx, vy);
                    }
                } else {
                    float* ob = (float*)out_ + pix * CO_TOTAL + co0 + 2 * ac;
#pragma unroll
                    for (int nt = 0; nt < NT; ++nt) {
                        float2 v;
                        v.x = d[mt][nt][half * 2 + 0];
                        v.y = d[mt][nt][half * 2 + 1];
                        *(float2*)(ob + nt * 8) = v;
                    }
                }
            }
        }
    }
}

// ---------------- conv3 pass2 fused: accum + bias + relu + pool3 + GAP -------
// One block covers the whole 17x17 image for 32 channels of one batch element.
__global__ void __launch_bounds__(256, 2)
conv3b_kernel(const void* __restrict__ in_, const unsigned* __restrict__ wt,
              const float* __restrict__ bias, const float* __restrict__ prev,
              float* __restrict__ gap) {
    constexpr int NCO = 32, MT = 3, K = 3, H = 17, W = 17, PAD = 1;
    constexpr int CO_TOTAL = 256, CIN_STR8 = 16, CH_OFF8 = 8;
    constexpr int CINH  = 64;
    constexpr int NT    = NCO / 8;
    constexpr int NC16  = CINH / 16;
    constexpr int TAPS  = K * K;
    constexpr int MPIX  = 8 * 16 * MT;               // 384
    constexpr int Wp    = W + 2 * PAD, Hp = H + 2 * PAD;
    constexpr int NPIX  = Wp * Hp;                   // 361
    constexpr int HALO  = PAD * Wp + PAD;            // 20
    constexpr int AWIN  = MPIX + 2 * HALO;           // 424
    constexpr int AST2  = CINH / 2 + 4;              // 36
    constexpr int AWORDS = AWIN * AST2;              // 15264
    constexpr int BWORDS = TAPS * NC16 * NT * 64;    // 9216
    constexpr int OST   = 33;                        // output tile stride

    extern __shared__ uint32_t sm[];
    uint32_t* sA = sm;
    uint32_t* sB = sm + AWORDS;
    float*    sOut  = (float*)sm;                    // overlay after mainloop: [289][33]
    float*    sPart = (float*)(sm + AWORDS);         // overlay on sB: [32][8]

    const int tid  = threadIdx.x;
    const int warp = tid >> 5, lane = tid & 31;
    const int ar   = lane >> 2, ac = lane & 3;
    const int n    = blockIdx.z;
    const int cob  = blockIdx.y;
    const int co0  = cob * NCO;
    const int p0   = HALO;
    const int s0   = 0;
    const int wrow = warp * (16 * MT);

    {
        const unsigned* wsrc = wt + (size_t)cob * BWORDS;
        uint32_t sBu = smem_u32(sB);
        for (int c = tid; c < BWORDS / 4; c += 256)
            cp_async16_s(sBu + c * 16, wsrc + c * 4);
        const uint4* inb = (const uint4*)in_ + (size_t)n * NPIX * CIN_STR8 + CH_OFF8;
        uint32_t sAu = smem_u32(sA);
        for (int e = tid; e < AWIN * 8; e += 256) {
            int row = e >> 3, c = e & 7;
            int pix = s0 + row;
            cp_async16_z(sAu + (uint32_t)((row * AST2 + c * 4) * 4),
                         inb + (size_t)pix * CIN_STR8 + c,
                         (pix < NPIX) ? 16u : 0u);
        }
        asm volatile("cp.async.commit_group;" ::: "memory");
    }
    asm volatile("cp.async.wait_group 0;" ::: "memory");
    __syncthreads();

    float d[MT][NT][4];
#pragma unroll
    for (int mt = 0; mt < MT; ++mt)
#pragma unroll
        for (int nt = 0; nt < NT; ++nt)
#pragma unroll
            for (int q = 0; q < 4; ++q) d[mt][nt][q] = 0.f;

    const uint32_t a_off0 = smem_u32(sA) +
        (uint32_t)(((HALO + wrow + (lane & 15)) * AST2 + ((lane >> 4) << 2)) * 4);

    for (int tap = 0; tap < TAPS; ++tap) {
        int shift = (tap / K - PAD) * Wp + (tap % K) - PAD;
        uint32_t abase = a_off0 + (uint32_t)(shift * (AST2 * 4));
        const uint2* btap = (const uint2*)sB + (size_t)tap * (NC16 * NT * 32) + lane;
#pragma unroll
        for (int c16 = 0; c16 < NC16; ++c16) {
            uint2 bf[NT];
#pragma unroll
            for (int nt = 0; nt < NT; ++nt)
                bf[nt] = btap[(c16 * NT + nt) * 32];
#pragma unroll
            for (int mt = 0; mt < MT; ++mt) {
                uint32_t af[4];
                ldsm_x4(af, abase + (uint32_t)((mt * 16 * AST2 + c16 * 8) * 4));
#pragma unroll
                for (int nt = 0; nt < NT; ++nt)
                    mma_f16(d[mt][nt], af, (const uint32_t*)&bf[nt]);
            }
        }
    }

    float2 bv[NT];
#pragma unroll
    for (int nt = 0; nt < NT; ++nt)
        bv[nt] = *(const float2*)(bias + co0 + nt * 8 + 2 * ac);

    __syncthreads();   // sA/sB reads done; safe to overlay output tile

    // accumulate prev + bias + relu -> smem tile [y*17+x][OST]
#pragma unroll
    for (int mt = 0; mt < MT; ++mt) {
#pragma unroll
        for (int half = 0; half < 2; ++half) {
            int p = p0 + wrow + mt * 16 + half * 8 + ar;
            int y = p / Wp - PAD, x = p % Wp - PAD;
            if (x >= 0 && x < W && y < H) {
                size_t pix = ((size_t)n * H + y) * W + x;
                const float* pb = prev + pix * CO_TOTAL + co0 + 2 * ac;
                float* so = sOut + (y * W + x) * OST + 2 * ac;
#pragma unroll
                for (int nt = 0; nt < NT; ++nt) {
                    float2 pv = *(const float2*)(pb + nt * 8);
                    so[nt * 8 + 0] = fmaxf(pv.x + d[mt][nt][half * 2 + 0] + bv[nt].x, 0.f);
                    so[nt * 8 + 1] = fmaxf(pv.y + d[mt][nt][half * 2 + 1] + bv[nt].y, 0.f);
                }
            }
        }
    }
    __syncthreads();

    // pool 3x3 s2 -> 8x8, partial GAP sums: thread t: c = t/8, seg = t%8
    {
        int c = tid >> 3, seg = tid & 7;
        float s = 0.f;
#pragma unroll
        for (int j = 0; j < 8; ++j) {
            int pp = seg * 8 + j;
            int oy = pp >> 3, ox = pp & 7;
            const float* b0 = sOut + ((2 * oy) * W + 2 * ox) * OST + c;
            float m = b0[0];
#pragma unroll
            for (int dy = 0; dy < 3; ++dy)
#pragma unroll
                for (int dx = 0; dx < 3; ++dx)
                    m = fmaxf(m, b0[(dy * W + dx) * OST]);
            s += m;
        }
        sPart[c * 8 + seg] = s;
    }
    __syncthreads();
    if (tid < 32) {
        float s = 0.f;
#pragma unroll
        for (int j = 0; j < 8; ++j) s += sPart[tid * 8 + j];
        gap[(size_t)n * 256 + co0 + tid] = s * (1.0f / 64.0f);
    }
}

// ---------------- pools (write own pad frame) / fc ----------------
template<int C, int HI, int HO, int P>
__global__ void pool_half_kernel(const uint2* __restrict__ in, uint2* __restrict__ out) {
    constexpr int C4 = C / 4, HOP = HO + 2 * P;
    int idx = blockIdx.x * blockDim.x + threadIdx.x;
    if (idx >= NB * HOP * HOP * C4) return;
    int c  = idx % C4;
    int ox = (idx / C4) % HOP;
    int oy = (idx / (C4 * HOP)) % HOP;
    int n  = idx / (C4 * HOP * HOP);
    uint2 r;
    if (ox < P || ox >= HO + P || oy < P || oy >= HO + P) {
        r = make_uint2(0u, 0u);
    } else {
        const uint2* p = in + (((size_t)n * HI + 2 * (oy - P)) * HI + 2 * (ox - P)) * C4 + c;
        uint2 m0 = p[0];
        __half2 ma = *(__half2*)&m0.x, mb = *(__half2*)&m0.y;
#pragma unroll
        for (int dy = 0; dy < 3; ++dy)
#pragma unroll
            for (int dx = 0; dx < 3; ++dx) {
                uint2 q = p[((size_t)dy * HI + dx) * C4];
                ma = __hmax2(ma, *(__half2*)&q.x);
                mb = __hmax2(mb, *(__half2*)&q.y);
            }
        r.x = *(uint32_t*)&ma; r.y = *(uint32_t*)&mb;
    }
    out[(((size_t)n * HOP + oy) * HOP + ox) * C4 + c] = r;
}

__global__ void fc_kernel(const float* __restrict__ in, const float* __restrict__ w,
                          const float* __restrict__ b, float* __restrict__ out,
                          int K_, int O_, int relu) {
    int idx = blockIdx.x * blockDim.x + threadIdx.x;
    if (idx >= NB * O_) return;
    int n = idx / O_, o = idx % O_;
    const float4* ip = (const float4*)(in + (size_t)n * K_);
    const float4* wp = (const float4*)(w + (size_t)o * K_);
    float s = b[o];
    int k4 = K_ >> 2;
#pragma unroll 4
    for (int k = 0; k < k4; ++k) {
        float4 a = ip[k], ww = wp[k];
        s = fmaf(a.x, ww.x, s); s = fmaf(a.y, ww.y, s);
        s = fmaf(a.z, ww.z, s); s = fmaf(a.w, ww.w, s);
    }
    if (relu) s = fmaxf(s, 0.f);
    out[idx] = s;
}

// ---------------- launch ----------------
extern "C" void kernel_launch(void* const* d_in, const int* in_sizes, int n_in,
                              void* d_out, int out_size) {
    const int*   X    = (const int*)  d_in[0];
    const int*   rmap = (const int*)  d_in[1];
    const float* emb  = (const float*)d_in[2];
    const float* cw0  = (const float*)d_in[3];
    const float* cb0  = (const float*)d_in[4];
    const float* cw1  = (const float*)d_in[5];
    const float* cb1  = (const float*)d_in[6];
    const float* cw2  = (const float*)d_in[7];
    const float* cb2  = (const float*)d_in[8];
    const float* fw0  = (const float*)d_in[9];
    const float* fb0  = (const float*)d_in[10];
    const float* fw1  = (const float*)d_in[11];
    const float* fb1  = (const float*)d_in[12];
    const float* fw2  = (const float*)d_in[13];
    const float* fb2  = (const float*)d_in[14];
    float* out = (float*)d_out;

    float *c3, *gapb, *f1, *f2;
    unsigned *grid, *c1, *p1, *c2, *p2, *wt1, *wt2, *wt3;
    cudaGetSymbolAddress((void**)&grid, g_grid);
    cudaGetSymbolAddress((void**)&c1,  g_c1);
    cudaGetSymbolAddress((void**)&p1,  g_p1);
    cudaGetSymbolAddress((void**)&c2,  g_c2);
    cudaGetSymbolAddress((void**)&p2,  g_p2);
    cudaGetSymbolAddress((void**)&c3,  g_c3);
    cudaGetSymbolAddress((void**)&gapb, g_gap);
    cudaGetSymbolAddress((void**)&f1,  g_f1);
    cudaGetSymbolAddress((void**)&f2,  g_f2);
    cudaGetSymbolAddress((void**)&wt1, g_wt1);
    cudaGetSymbolAddress((void**)&wt2, g_wt2);
    cudaGetSymbolAddress((void**)&wt3, g_wt3);

    const int SM1 = (10000 + 3840 + 256 + 13312) * 4;   // 109,632
    const int SM2 = (460 * 36 + 9216) * 4;              // 103,104
    const int SM3 = (424 * 36 + 9216) * 4;              //  97,920
    cudaFuncSetAttribute((const void*)conv1_kernel,
                         cudaFuncAttributeMaxDynamicSharedMemorySize, SM1);
    cudaFuncSetAttribute((const void*)hmma_conv_kernel<32, 3, 3, 35, 35, 1, 0, 128, 8, 0>,
                         cudaFuncAttributeMaxDynamicSharedMemorySize, SM2);
    cudaFuncSetAttribute((const void*)hmma_conv_kernel<32, 3, 3, 17, 17, 1, 1, 256, 16, 0>,
                         cudaFuncAttributeMaxDynamicSharedMemorySize, SM3);
    cudaFuncSetAttribute((const void*)conv3b_kernel,
                         cudaFuncAttributeMaxDynamicSharedMemorySize, SM3);

    // zero grid (scatter accumulates into it)
    {
        int n4 = NB * 76 * 76 * 20 / 4;
        zero_kernel<<<(n4 + 255) / 256, 256>>>((float4*)grid, n4);
    }
    // fused weight transform (one launch)
    wtrans_all_kernel<<<(210944 + 255) / 256, 256>>>(cw0, cw1, cw2, wt1, wt2, wt3);
    // scatter encode (half2 atomics)
    {
        int nt = NB * RNUM * 64;
        scatter_kernel<<<(nt + 255) / 256, 256>>>(X, rmap, emb, (__half2*)grid);
    }
    // conv1 + pool1
    conv1_kernel<<<dim3(29, 2, NB), 192, SM1>>>(grid, wt1, cb0, c1);
    {
        int nt = NB * 37 * 37 * 16;
        pool_half_kernel<64, 72, 35, 1><<<(nt + 255) / 256, 256>>>((const uint2*)c1, (uint2*)p1);
    }
    // conv2 + pool2
    hmma_conv_kernel<32, 3, 3, 35, 35, 1, 0, 128, 8, 0>
        <<<dim3(4, 4, NB), 256, SM2>>>(p1, wt2, cb1, c2);
    {
        int nt = NB * 19 * 19 * 32;
        pool_half_kernel<128, 35, 17, 1><<<(nt + 255) / 256, 256>>>((const uint2*)c2, (uint2*)p2);
    }
    // conv3: pass1 raw write (ci 0..63), pass2 fused accum+bias+relu+pool+GAP
    hmma_conv_kernel<32, 3, 3, 17, 17, 1, 1, 256, 16, 0>
        <<<dim3(1, 8, NB), 256, SM3>>>(p2, wt3, cb2, c3);
    conv3b_kernel<<<dim3(1, 8, NB), 256, SM3>>>(p2, wt3 + 73728, cb2, c3, gapb);
    // FC stack
    fc_kernel<<<(NB * 512 + 255) / 256, 256>>>(gapb, fw0, fb0, f1, 256, 512, 1);
    fc_kernel<<<(NB * 256 + 255) / 256, 256>>>(f1,   fw1, fb1, f2, 512, 256, 1);
    fc_kernel<<<(NB * 512 + 255) / 256, 256>>>(f2,   fw2, fb2, out, 256, 512, 0);
}